// round 6
// baseline (speedup 1.0000x reference)
#include <cuda_runtime.h>
#include <cuda_bf16.h>
#include <math.h>
#include <stdint.h>

#define NT    4096
#define D     512
#define NHD   16
#define DH    32
#define DEPTH 3
#define DMLP  2048
#define GENES 250
#define GH    64
#define GW    64

// ---------------- PTX helpers ----------------
__device__ __forceinline__ uint32_t smem_u32(const void* p) {
    uint32_t a;
    asm("{ .reg .u64 t; cvta.to.shared.u64 t, %1; cvt.u32.u64 %0, t; }" : "=r"(a) : "l"(p));
    return a;
}
#define CP_ASYNC16(sa, ga) \
    asm volatile("cp.async.cg.shared.global [%0], [%1], 16;" :: "r"(sa), "l"(ga))
#define CP_COMMIT() asm volatile("cp.async.commit_group;")
#define CP_WAIT(n)  asm volatile("cp.async.wait_group %0;" :: "n"(n))

#define LDSM4(r0, r1, r2, r3, addr) \
    asm volatile("ldmatrix.sync.aligned.m8n8.x4.shared.b16 {%0,%1,%2,%3}, [%4];" \
        : "=r"(r0), "=r"(r1), "=r"(r2), "=r"(r3) : "r"(addr))
#define LDSM4T(r0, r1, r2, r3, addr) \
    asm volatile("ldmatrix.sync.aligned.m8n8.x4.trans.shared.b16 {%0,%1,%2,%3}, [%4];" \
        : "=r"(r0), "=r"(r1), "=r"(r2), "=r"(r3) : "r"(addr))

__device__ __forceinline__ void mma_bf16(float* d, const uint32_t* a, const uint32_t* b) {
    asm volatile("mma.sync.aligned.m16n8k16.row.col.f32.bf16.bf16.f32 "
        "{%0,%1,%2,%3}, {%4,%5,%6,%7}, {%8,%9}, {%0,%1,%2,%3};"
        : "+f"(d[0]), "+f"(d[1]), "+f"(d[2]), "+f"(d[3])
        : "r"(a[0]), "r"(a[1]), "r"(a[2]), "r"(a[3]), "r"(b[0]), "r"(b[1]));
}

#define PACKBF(d, lo, hi) \
    asm("cvt.rn.bf16x2.f32 %0, %1, %2;" : "=r"(d) : "f"(hi), "f"(lo))

__device__ __forceinline__ float ex2f(float x) {
    float y; asm("ex2.approx.f32 %0, %1;" : "=f"(y) : "f"(x)); return y;
}

__device__ __forceinline__ void hilo(float v, __nv_bfloat16& h, __nv_bfloat16& l) {
    h = __float2bfloat16(v);
    l = __float2bfloat16(v - __bfloat162float(h));
}

// ---------------- device scratch ----------------
__device__ float g_x[NT * D];
__device__ float g_grid[GH * GW * D];
__device__ __nv_bfloat16 g_qkv_h[NT * 3 * D], g_qkv_l[NT * 3 * D];
__device__ __nv_bfloat16 g_xn_h[NT * D],  g_xn_l[NT * D];
__device__ __nv_bfloat16 g_ao_h[NT * D],  g_ao_l[NT * D];
__device__ __nv_bfloat16 g_hh[NT * DMLP], g_hl[NT * DMLP];
__device__ __nv_bfloat16 g_xf_h[NT * D],  g_xf_l[NT * D];
__device__ __nv_bfloat16 g_wqkv_h[DEPTH * 3 * D * D], g_wqkv_l[DEPTH * 3 * D * D];
__device__ __nv_bfloat16 g_wo_h[DEPTH * D * D],       g_wo_l[DEPTH * D * D];
__device__ __nv_bfloat16 g_w1_h[DEPTH * DMLP * D],    g_w1_l[DEPTH * DMLP * D];
__device__ __nv_bfloat16 g_w2_h[DEPTH * D * DMLP],    g_w2_l[DEPTH * D * DMLP];
__device__ __nv_bfloat16 g_wp_h[GENES * D],           g_wp_l[GENES * D];

__global__ void cvt_kernel(const float* __restrict__ s, __nv_bfloat16* __restrict__ h,
                           __nv_bfloat16* __restrict__ l, int n) {
    int i = blockIdx.x * blockDim.x + threadIdx.x;
    if (i < n) { __nv_bfloat16 a, b; hilo(s[i], a, b); h[i] = a; l[i] = b; }
}
__global__ void cvt2_kernel(const float* __restrict__ s1, __nv_bfloat16* __restrict__ h1,
                            __nv_bfloat16* __restrict__ l1, int n1,
                            const float* __restrict__ s2, __nv_bfloat16* __restrict__ h2,
                            __nv_bfloat16* __restrict__ l2, int n2) {
    int i = blockIdx.x * blockDim.x + threadIdx.x;
    if (i < n1) {
        __nv_bfloat16 a, b; hilo(s1[i], a, b); h1[i] = a; l1[i] = b;
    } else if (i < n1 + n2) {
        int j = i - n1;
        __nv_bfloat16 a, b; hilo(s2[j], a, b); h2[j] = a; l2[j] = b;
    }
}

// ---------------- LayerNorm -> bf16 hi/lo (optionally fp32 copy) -----------
template <int WF32>
__global__ void ln_kernel(const float* __restrict__ in, float* __restrict__ out32,
                          __nv_bfloat16* __restrict__ oh, __nv_bfloat16* __restrict__ ol,
                          const float* __restrict__ gam, const float* __restrict__ bet) {
    int row = blockIdx.x, t = threadIdx.x;
    float4 v = ((const float4*)(in + (size_t)row * D))[t];
    float s = v.x + v.y + v.z + v.w;
    float ss = v.x * v.x + v.y * v.y + v.z * v.z + v.w * v.w;
#pragma unroll
    for (int off = 16; off; off >>= 1) {
        s  += __shfl_xor_sync(0xffffffffu, s, off);
        ss += __shfl_xor_sync(0xffffffffu, ss, off);
    }
    __shared__ float sb[4], ssb[4];
    int w = t >> 5, lane = t & 31;
    if (lane == 0) { sb[w] = s; ssb[w] = ss; }
    __syncthreads();
    s = sb[0] + sb[1] + sb[2] + sb[3];
    ss = ssb[0] + ssb[1] + ssb[2] + ssb[3];
    float mean = s * (1.0f / D);
    float inv = rsqrtf(ss * (1.0f / D) - mean * mean + 1e-5f);
    float4 g4 = ((const float4*)gam)[t];
    float4 b4 = ((const float4*)bet)[t];
    float o0 = (v.x - mean) * inv * g4.x + b4.x;
    float o1 = (v.y - mean) * inv * g4.y + b4.y;
    float o2 = (v.z - mean) * inv * g4.z + b4.z;
    float o3 = (v.w - mean) * inv * g4.w + b4.w;
    size_t base = (size_t)row * D + t * 4;
    __nv_bfloat16 h0, l0, h1, l1, h2, l2, h3, l3;
    hilo(o0, h0, l0); hilo(o1, h1, l1); hilo(o2, h2, l2); hilo(o3, h3, l3);
    __nv_bfloat162 p;
    p.x = h0; p.y = h1; *(__nv_bfloat162*)(oh + base) = p;
    p.x = h2; p.y = h3; *(__nv_bfloat162*)(oh + base + 2) = p;
    p.x = l0; p.y = l1; *(__nv_bfloat162*)(ol + base) = p;
    p.x = l2; p.y = l3; *(__nv_bfloat162*)(ol + base + 2) = p;
    if (WF32) {
        float4 o; o.x = o0; o.y = o1; o.z = o2; o.w = o3;
        ((float4*)(out32 + (size_t)row * D))[t] = o;
    }
}

// ---------------- bf16 hi/lo 3-term GEMM via mma.sync (HMMA) ----------------
#define TPITCH 80
#define TILE_B (128 * TPITCH)
#define STAGE_B (4 * TILE_B)
#define GEMM_DYN (2 * STAGE_B)

__device__ __forceinline__ void stage_load(
    uint32_t sbase, const __nv_bfloat16* Ah, const __nv_bfloat16* Al,
    const __nv_bfloat16* Wh, const __nv_bfloat16* Wl,
    int mrow, int ncol, int OUT, int K, int kt, int tid) {
#pragma unroll
    for (int i = 0; i < 2; i++) {
        int chunk = tid + i * 256;
        int r = chunk >> 2, c16 = chunk & 3;
        uint32_t so = (uint32_t)(r * TPITCH + c16 * 16);
        size_t aoff = (size_t)(mrow + r) * K + kt + c16 * 8;
        int wr = ncol + r; if (wr >= OUT) wr = OUT - 1;
        size_t woff = (size_t)wr * K + kt + c16 * 8;
        CP_ASYNC16(sbase + so,              (const char*)(Ah + aoff));
        CP_ASYNC16(sbase + TILE_B + so,     (const char*)(Al + aoff));
        CP_ASYNC16(sbase + 2 * TILE_B + so, (const char*)(Wh + woff));
        CP_ASYNC16(sbase + 3 * TILE_B + so, (const char*)(Wl + woff));
    }
}

// MODE 0: out32=v+bias ; 1: outh/l=hilo(gelu(v+bias)) ; 2: out32+=v+bias ; 3: outh/l=hilo(v+bias)
template <int MODE>
__global__ void __launch_bounds__(256) gemm_mma(
    const __nv_bfloat16* __restrict__ Ah, const __nv_bfloat16* __restrict__ Al,
    const __nv_bfloat16* __restrict__ Wh, const __nv_bfloat16* __restrict__ Wl,
    const float* __restrict__ bias, float* __restrict__ out32,
    __nv_bfloat16* __restrict__ outh, __nv_bfloat16* __restrict__ outl,
    int OUT, int K) {
    extern __shared__ char dyn_raw[];
    const int tid = threadIdx.x, wid = tid >> 5, lane = tid & 31;
    const int mrow = blockIdx.y * 128, ncol = blockIdx.x * 128;
    const int warp_m = wid & 1, warp_n = wid >> 1;
    const int m_off = warp_m * 64, n_off = warp_n * 32;
    const int NIT = K >> 5;
    uint32_t smem0 = smem_u32(dyn_raw);

    float acc[4][4][4];
#pragma unroll
    for (int a = 0; a < 4; a++)
#pragma unroll
        for (int b = 0; b < 4; b++)
#pragma unroll
            for (int c = 0; c < 4; c++) acc[a][b][c] = 0.f;

    const uint32_t a_lm = (uint32_t)((m_off + (lane & 15)) * TPITCH + (lane & 16));
    const int bl = lane & 7, bg = (lane >> 3) & 3;
    const uint32_t b_lm = (uint32_t)((n_off + ((bg >> 1) << 3) + bl) * TPITCH + ((bg & 1) << 4));

    stage_load(smem0, Ah, Al, Wh, Wl, mrow, ncol, OUT, K, 0, tid);
    CP_COMMIT();

    for (int it = 0; it < NIT; it++) {
        if (it + 1 < NIT) {
            stage_load(smem0 + ((it + 1) & 1) * STAGE_B, Ah, Al, Wh, Wl,
                       mrow, ncol, OUT, K, (it + 1) * 32, tid);
            CP_COMMIT();
            CP_WAIT(1);
        } else {
            CP_WAIT(0);
        }
        __syncthreads();
        uint32_t sb = smem0 + (it & 1) * STAGE_B;
#pragma unroll
        for (int ks = 0; ks < 2; ks++) {
            uint32_t kb = (uint32_t)(ks * 32);
            uint32_t ah[4][4], al[4][4], bh[4][2], bl2[4][2];
#pragma unroll
            for (int mt = 0; mt < 4; mt++) {
                uint32_t ad = sb + a_lm + mt * (16 * TPITCH) + kb;
                LDSM4(ah[mt][0], ah[mt][1], ah[mt][2], ah[mt][3], ad);
                LDSM4(al[mt][0], al[mt][1], al[mt][2], al[mt][3], ad + TILE_B);
            }
#pragma unroll
            for (int np = 0; np < 2; np++) {
                uint32_t bd = sb + 2 * TILE_B + b_lm + np * (16 * TPITCH) + kb;
                LDSM4(bh[2 * np][0], bh[2 * np][1], bh[2 * np + 1][0], bh[2 * np + 1][1], bd);
                LDSM4(bl2[2 * np][0], bl2[2 * np][1], bl2[2 * np + 1][0], bl2[2 * np + 1][1], bd + TILE_B);
            }
#pragma unroll
            for (int mt = 0; mt < 4; mt++)
#pragma unroll
                for (int nt = 0; nt < 4; nt++) {
                    mma_bf16(acc[mt][nt], ah[mt], bh[nt]);
                    mma_bf16(acc[mt][nt], ah[mt], bl2[nt]);
                    mma_bf16(acc[mt][nt], al[mt], bh[nt]);
                }
        }
        __syncthreads();
    }

    const int r0 = lane >> 2, cp = (lane & 3) * 2;
#pragma unroll
    for (int mt = 0; mt < 4; mt++)
#pragma unroll
        for (int nt = 0; nt < 4; nt++) {
            int col = ncol + n_off + nt * 8 + cp;
            if (col >= OUT) continue;
            float bx = bias[col], by = bias[col + 1];
#pragma unroll
            for (int half = 0; half < 2; half++) {
                int row = mrow + m_off + mt * 16 + r0 + half * 8;
                float vx = acc[mt][nt][2 * half] + bx;
                float vy = acc[mt][nt][2 * half + 1] + by;
                size_t idx = (size_t)row * OUT + col;
                if (MODE == 0) {
                    *(float2*)(out32 + idx) = make_float2(vx, vy);
                } else if (MODE == 1 || MODE == 3) {
                    if (MODE == 1) {
                        vx = 0.5f * vx * (1.0f + erff(vx * 0.70710678118654752f));
                        vy = 0.5f * vy * (1.0f + erff(vy * 0.70710678118654752f));
                    }
                    __nv_bfloat16 hx, lx, hy, ly;
                    hilo(vx, hx, lx); hilo(vy, hy, ly);
                    __nv_bfloat162 p;
                    p.x = hx; p.y = hy; *(__nv_bfloat162*)(outh + idx) = p;
                    p.x = lx; p.y = ly; *(__nv_bfloat162*)(outl + idx) = p;
                } else {
                    float2 o = *(float2*)(out32 + idx);
                    o.x += vx; o.y += vy;
                    *(float2*)(out32 + idx) = o;
                }
            }
        }
}

// ---------------- flash attention on HMMA, bf16 hi/lo 3-term -----------------
// CTA = (head, 128-query block), 256 threads / 8 warps x 16 rows.
// K/V tiles of 64 keys double-buffered; K/V smem shared by 8 warps (halves L2 traffic).
#define AP 80
#define KVT (64 * AP)
#define ASTG (4 * KVT)
#define QT (128 * AP)

__global__ void __launch_bounds__(256) attn_tc() {
    __shared__ __align__(16) char smem[2 * ASTG];
    const int tid = threadIdx.x, wid = tid >> 5, lane = tid & 31;
    const int h = blockIdx.x, qb = blockIdx.y * 128;
    const uint32_t s0 = smem_u32(smem);

    // ---- stage Q (128x32 hi/lo) and load fragments
#pragma unroll
    for (int i = 0; i < 4; i++) {
        int idx = tid + i * 256;
        int tile = idx >> 9, rem = idx & 511, r = rem >> 2, c = rem & 3;
        const __nv_bfloat16* src = (tile ? g_qkv_l : g_qkv_h) + (size_t)(qb + r) * 1536 + h * 32 + c * 8;
        CP_ASYNC16(s0 + tile * QT + r * AP + c * 16, src);
    }
    CP_COMMIT(); CP_WAIT(0); __syncthreads();
    uint32_t qh[2][4], ql[2][4];
    {
        uint32_t alm = s0 + (wid * 16 + (lane & 15)) * AP + (lane & 16);
        LDSM4(qh[0][0], qh[0][1], qh[0][2], qh[0][3], alm);
        LDSM4(qh[1][0], qh[1][1], qh[1][2], qh[1][3], alm + 32);
        LDSM4(ql[0][0], ql[0][1], ql[0][2], ql[0][3], alm + QT);
        LDSM4(ql[1][0], ql[1][1], ql[1][2], ql[1][3], alm + QT + 32);
    }
    __syncthreads();

    const int bl = lane & 7, bg = (lane >> 3) & 3;
    const uint32_t koff = (uint32_t)((((bg >> 1) * 8) + bl) * AP + ((bg & 1) * 16));
    const uint32_t voff = (uint32_t)(((((lane >> 3) & 1) * 8) + (lane & 7)) * AP + (((lane >> 4) & 1) * 16));

    float O[4][4];
#pragma unroll
    for (int a = 0; a < 4; a++)
#pragma unroll
        for (int b = 0; b < 4; b++) O[a][b] = 0.f;
    float m0 = -1e30f, m1 = -1e30f, lsum0 = 0.f, lsum1 = 0.f;
    const float sc2 = 0.25501649f;   // (1/sqrt(32)) * log2(e)

    // prologue: K/V tile 0 (tiles: 0=Kh 1=Kl 2=Vh 3=Vl; 256 chunks each)
    {
#pragma unroll
        for (int i = 0; i < 4; i++) {
            int idx = tid + i * 256;
            int tile = idx >> 8, rem = idx & 255, r = rem >> 2, c = rem & 3;
            const __nv_bfloat16* base = (tile & 1) ? g_qkv_l : g_qkv_h;
            int col = ((tile >> 1) ? 1024 : 512) + h * 32;
            CP_ASYNC16(s0 + tile * KVT + r * AP + c * 16,
                       base + (size_t)r * 1536 + col + c * 8);
        }
        CP_COMMIT();
    }

    for (int t = 0; t < NT / 64; t++) {
        if (t + 1 < NT / 64) {
            int kb = (t + 1) * 64;
            uint32_t st = s0 + ((t + 1) & 1) * ASTG;
#pragma unroll
            for (int i = 0; i < 4; i++) {
                int idx = tid + i * 256;
                int tile = idx >> 8, rem = idx & 255, r = rem >> 2, c = rem & 3;
                const __nv_bfloat16* base = (tile & 1) ? g_qkv_l : g_qkv_h;
                int col = ((tile >> 1) ? 1024 : 512) + h * 32;
                CP_ASYNC16(st + tile * KVT + r * AP + c * 16,
                           base + (size_t)(kb + r) * 1536 + col + c * 8);
            }
            CP_COMMIT(); CP_WAIT(1);
        } else {
            CP_WAIT(0);
        }
        __syncthreads();
        uint32_t sb = s0 + (t & 1) * ASTG;

        // ---- S = Q K^T (3-term)
        float S[8][4];
#pragma unroll
        for (int a = 0; a < 8; a++)
#pragma unroll
            for (int b = 0; b < 4; b++) S[a][b] = 0.f;
#pragma unroll
        for (int ks = 0; ks < 2; ks++) {
            uint32_t kh[8][2], kl[8][2];
#pragma unroll
            for (int np = 0; np < 4; np++) {
                uint32_t ad = sb + np * (16 * AP) + koff + ks * 32;
                LDSM4(kh[2 * np][0], kh[2 * np][1], kh[2 * np + 1][0], kh[2 * np + 1][1], ad);
                LDSM4(kl[2 * np][0], kl[2 * np][1], kl[2 * np + 1][0], kl[2 * np + 1][1], ad + KVT);
            }
#pragma unroll
            for (int nt = 0; nt < 8; nt++) {
                mma_bf16(S[nt], qh[ks], kh[nt]);
                mma_bf16(S[nt], qh[ks], kl[nt]);
                mma_bf16(S[nt], ql[ks], kh[nt]);
            }
        }

        // ---- online softmax
        float t0 = -1e30f, t1 = -1e30f;
#pragma unroll
        for (int nt = 0; nt < 8; nt++) {
            t0 = fmaxf(t0, fmaxf(S[nt][0], S[nt][1]));
            t1 = fmaxf(t1, fmaxf(S[nt][2], S[nt][3]));
        }
        t0 *= sc2; t1 *= sc2;
        t0 = fmaxf(t0, __shfl_xor_sync(0xffffffffu, t0, 1));
        t0 = fmaxf(t0, __shfl_xor_sync(0xffffffffu, t0, 2));
        t1 = fmaxf(t1, __shfl_xor_sync(0xffffffffu, t1, 1));
        t1 = fmaxf(t1, __shfl_xor_sync(0xffffffffu, t1, 2));
        float mn0 = fmaxf(m0, t0), mn1 = fmaxf(m1, t1);
        float c0 = ex2f(m0 - mn0), c1 = ex2f(m1 - mn1);
        m0 = mn0; m1 = mn1;
        lsum0 *= c0; lsum1 *= c1;
#pragma unroll
        for (int nt = 0; nt < 4; nt++) {
            O[nt][0] *= c0; O[nt][1] *= c0; O[nt][2] *= c1; O[nt][3] *= c1;
        }
        uint32_t ph01[8], ph23[8], pl01[8], pl23[8];
#pragma unroll
        for (int nt = 0; nt < 8; nt++) {
            float p0 = ex2f(fmaf(S[nt][0], sc2, -m0));
            float p1 = ex2f(fmaf(S[nt][1], sc2, -m0));
            float p2 = ex2f(fmaf(S[nt][2], sc2, -m1));
            float p3 = ex2f(fmaf(S[nt][3], sc2, -m1));
            lsum0 += p0 + p1; lsum1 += p2 + p3;
            uint32_t hp, lp;
            PACKBF(hp, p0, p1); ph01[nt] = hp;
            float h0f = __uint_as_float(hp << 16);
            float h1f = __uint_as_float(hp & 0xffff0000u);
            PACKBF(lp, p0 - h0f, p1 - h1f); pl01[nt] = lp;
            PACKBF(hp, p2, p3); ph23[nt] = hp;
            h0f = __uint_as_float(hp << 16);
            h1f = __uint_as_float(hp & 0xffff0000u);
            PACKBF(lp, p2 - h0f, p3 - h1f); pl23[nt] = lp;
        }

        // ---- O += P V (3-term)
#pragma unroll
        for (int s = 0; s < 4; s++) {
            uint32_t aH[4] = { ph01[2 * s], ph23[2 * s], ph01[2 * s + 1], ph23[2 * s + 1] };
            uint32_t aL[4] = { pl01[2 * s], pl23[2 * s], pl01[2 * s + 1], pl23[2 * s + 1] };
            uint32_t vh[4][2], vl[4][2];
#pragma unroll
            for (int d2 = 0; d2 < 2; d2++) {
                uint32_t ad = sb + 2 * KVT + s * (16 * AP) + voff + d2 * 32;
                LDSM4T(vh[2 * d2][0], vh[2 * d2][1], vh[2 * d2 + 1][0], vh[2 * d2 + 1][1], ad);
                LDSM4T(vl[2 * d2][0], vl[2 * d2][1], vl[2 * d2 + 1][0], vl[2 * d2 + 1][1], ad + KVT);
            }
#pragma unroll
            for (int nt = 0; nt < 4; nt++) {
                mma_bf16(O[nt], aH, vh[nt]);
                mma_bf16(O[nt], aH, vl[nt]);
                mma_bf16(O[nt], aL, vh[nt]);
            }
        }
        __syncthreads();
    }

    // ---- epilogue
    lsum0 += __shfl_xor_sync(0xffffffffu, lsum0, 1);
    lsum0 += __shfl_xor_sync(0xffffffffu, lsum0, 2);
    lsum1 += __shfl_xor_sync(0xffffffffu, lsum1, 1);
    lsum1 += __shfl_xor_sync(0xffffffffu, lsum1, 2);
    float i0 = 1.f / lsum0, i1 = 1.f / lsum1;
    int r0 = qb + wid * 16 + (lane >> 2), r1 = r0 + 8;
    int colb = h * 32 + (lane & 3) * 2;
#pragma unroll
    for (int nt = 0; nt < 4; nt++) {
        int col = colb + nt * 8;
        float v0 = O[nt][0] * i0, v1 = O[nt][1] * i0;
        float v2 = O[nt][2] * i1, v3 = O[nt][3] * i1;
        uint32_t hp, lp;
        PACKBF(hp, v0, v1);
        float h0f = __uint_as_float(hp << 16), h1f = __uint_as_float(hp & 0xffff0000u);
        PACKBF(lp, v0 - h0f, v1 - h1f);
        *(uint32_t*)(g_ao_h + (size_t)r0 * D + col) = hp;
        *(uint32_t*)(g_ao_l + (size_t)r0 * D + col) = lp;
        PACKBF(hp, v2, v3);
        h0f = __uint_as_float(hp << 16); h1f = __uint_as_float(hp & 0xffff0000u);
        PACKBF(lp, v2 - h0f, v3 - h1f);
        *(uint32_t*)(g_ao_h + (size_t)r1 * D + col) = hp;
        *(uint32_t*)(g_ao_l + (size_t)r1 * D + col) = lp;
    }
}

// ---------------- conv path (scatter, then fused conv+gather) --------------
__global__ void scatter_kernel(const int* __restrict__ coords) {
    int idx = blockIdx.x * blockDim.x + threadIdx.x;
    int n = idx >> 7, d4 = idx & 127;
    int rr = coords[2 * n], cc = coords[2 * n + 1];
    ((float4*)g_grid)[(size_t)(rr * GW + cc) * 128 + d4] =
        ((const float4*)g_x)[(size_t)n * 128 + d4];
}
__global__ void convgather_kernel(const int* __restrict__ coords,
                                  const float* __restrict__ ck,
                                  const float* __restrict__ cb) {
    int idx = blockIdx.x * blockDim.x + threadIdx.x;   // NT*D
    int n = idx >> 9, d = idx & (D - 1);
    int r = coords[2 * n], c = coords[2 * n + 1];
    float acc = cb[d];
#pragma unroll
    for (int kh = 0; kh < 3; kh++) {
        int rr = r + kh - 1;
        if ((unsigned)rr >= GH) continue;
#pragma unroll
        for (int kw = 0; kw < 3; kw++) {
            int cc = c + kw - 1;
            if ((unsigned)cc >= GW) continue;
            acc += ck[d * 9 + kh * 3 + kw] * g_grid[(size_t)(rr * GW + cc) * D + d];
        }
    }
    g_x[idx] += acc;
}

// ---------------- host ----------------
extern "C" void kernel_launch(void* const* d_in, const int* in_sizes, int n_in,
                              void* d_out, int out_size) {
    const float* gf     = (const float*)d_in[0];
    const int*   coords = (const int*)d_in[1];
    int wi = (n_in >= 22) ? 4 : 2;
    const float* ln1_g = (const float*)d_in[wi + 0];
    const float* ln1_b = (const float*)d_in[wi + 1];
    const float* wqkv  = (const float*)d_in[wi + 2];
    const float* bqkv  = (const float*)d_in[wi + 3];
    const float* wo    = (const float*)d_in[wi + 4];
    const float* bo    = (const float*)d_in[wi + 5];
    const float* ln2_g = (const float*)d_in[wi + 6];
    const float* ln2_b = (const float*)d_in[wi + 7];
    const float* w1    = (const float*)d_in[wi + 8];
    const float* b1    = (const float*)d_in[wi + 9];
    const float* w2    = (const float*)d_in[wi + 10];
    const float* b2    = (const float*)d_in[wi + 11];
    const float* ck    = (const float*)d_in[wi + 12];
    const float* cb    = (const float*)d_in[wi + 13];
    const float* lnf_g = (const float*)d_in[wi + 14];
    const float* lnf_b = (const float*)d_in[wi + 15];
    const float* wp    = (const float*)d_in[wi + 16];
    const float* bp    = (const float*)d_in[wi + 17];

    float* out_x    = (float*)d_out;
    float* out_pred = out_x + (size_t)NT * D;

    static float* px = nullptr;
    static __nv_bfloat16 *pqh, *pql, *pxnh, *pxnl, *paoh, *paol, *phh, *phl, *pxfh, *pxfl;
    static __nv_bfloat16 *pWqh, *pWql, *pWoh, *pWol, *pW1h, *pW1l, *pW2h, *pW2l, *pWph, *pWpl;
    if (!px) {
        cudaGetSymbolAddress((void**)&px, g_x);
        cudaGetSymbolAddress((void**)&pqh, g_qkv_h);  cudaGetSymbolAddress((void**)&pql, g_qkv_l);
        cudaGetSymbolAddress((void**)&pxnh, g_xn_h);  cudaGetSymbolAddress((void**)&pxnl, g_xn_l);
        cudaGetSymbolAddress((void**)&paoh, g_ao_h);  cudaGetSymbolAddress((void**)&paol, g_ao_l);
        cudaGetSymbolAddress((void**)&phh, g_hh);     cudaGetSymbolAddress((void**)&phl, g_hl);
        cudaGetSymbolAddress((void**)&pxfh, g_xf_h);  cudaGetSymbolAddress((void**)&pxfl, g_xf_l);
        cudaGetSymbolAddress((void**)&pWqh, g_wqkv_h); cudaGetSymbolAddress((void**)&pWql, g_wqkv_l);
        cudaGetSymbolAddress((void**)&pWoh, g_wo_h);   cudaGetSymbolAddress((void**)&pWol, g_wo_l);
        cudaGetSymbolAddress((void**)&pW1h, g_w1_h);   cudaGetSymbolAddress((void**)&pW1l, g_w1_l);
        cudaGetSymbolAddress((void**)&pW2h, g_w2_h);   cudaGetSymbolAddress((void**)&pW2l, g_w2_l);
        cudaGetSymbolAddress((void**)&pWph, g_wp_h);   cudaGetSymbolAddress((void**)&pWpl, g_wp_l);
        cudaFuncSetAttribute(gemm_mma<0>, cudaFuncAttributeMaxDynamicSharedMemorySize, GEMM_DYN);
        cudaFuncSetAttribute(gemm_mma<1>, cudaFuncAttributeMaxDynamicSharedMemorySize, GEMM_DYN);
        cudaFuncSetAttribute(gemm_mma<2>, cudaFuncAttributeMaxDynamicSharedMemorySize, GEMM_DYN);
        cudaFuncSetAttribute(gemm_mma<3>, cudaFuncAttributeMaxDynamicSharedMemorySize, GEMM_DYN);
    }

    cudaMemcpyAsync(px, gf, (size_t)NT * D * sizeof(float), cudaMemcpyDeviceToDevice);

    // kernels #0..#3 (cvt), so #4 = ln, #5 = QKV GEMM (profiled by ncu -s 5 -c 1)
    cvt_kernel<<<(DEPTH * 3 * D * D + 255) / 256, 256>>>(wqkv, pWqh, pWql, DEPTH * 3 * D * D);
    cvt_kernel<<<(DEPTH * DMLP * D + 255) / 256, 256>>>(w1, pW1h, pW1l, DEPTH * DMLP * D);
    cvt_kernel<<<(DEPTH * D * DMLP + 255) / 256, 256>>>(w2, pW2h, pW2l, DEPTH * D * DMLP);
    cvt2_kernel<<<(DEPTH * D * D + GENES * D + 255) / 256, 256>>>(
        wo, pWoh, pWol, DEPTH * D * D, wp, pWph, pWpl, GENES * D);

    for (int i = 0; i < DEPTH; i++) {
        ln_kernel<0><<<NT, 128>>>(px, nullptr, pxnh, pxnl, ln1_g + i * D, ln1_b + i * D);
        gemm_mma<3><<<dim3(12, 32), 256, GEMM_DYN>>>(
            pxnh, pxnl, pWqh + (size_t)i * 3 * D * D, pWql + (size_t)i * 3 * D * D,
            bqkv + i * 3 * D, nullptr, pqh, pql, 3 * D, D);
        attn_tc<<<dim3(NHD, NT / 128), 256>>>();
        gemm_mma<2><<<dim3(4, 32), 256, GEMM_DYN>>>(
            paoh, paol, pWoh + (size_t)i * D * D, pWol + (size_t)i * D * D,
            bo + i * D, px, nullptr, nullptr, D, D);
        ln_kernel<0><<<NT, 128>>>(px, nullptr, pxnh, pxnl, ln2_g + i * D, ln2_b + i * D);
        gemm_mma<1><<<dim3(16, 32), 256, GEMM_DYN>>>(
            pxnh, pxnl, pW1h + (size_t)i * DMLP * D, pW1l + (size_t)i * DMLP * D,
            b1 + i * DMLP, nullptr, phh, phl, DMLP, D);
        gemm_mma<2><<<dim3(4, 32), 256, GEMM_DYN>>>(
            phh, phl, pW2h + (size_t)i * D * DMLP, pW2l + (size_t)i * D * DMLP,
            b2 + i * D, px, nullptr, nullptr, D, DMLP);
        scatter_kernel<<<NT * (D / 4) / 256, 256>>>(coords);
        convgather_kernel<<<NT * D / 256, 256>>>(coords, ck + (size_t)i * D * 9, cb + i * D);
    }
    ln_kernel<1><<<NT, 128>>>(px, out_x, pxfh, pxfl, lnf_g, lnf_b);
    gemm_mma<0><<<dim3(2, 32), 256, GEMM_DYN>>>(
        pxfh, pxfl, pWph, pWpl, bp, out_pred, nullptr, nullptr, GENES, D);
}

// round 7
// speedup vs baseline: 1.0284x; 1.0284x over previous
#include <cuda_runtime.h>
#include <cuda_bf16.h>
#include <math.h>
#include <stdint.h>

#define NT    4096
#define D     512
#define NHD   16
#define DH    32
#define DEPTH 3
#define DMLP  2048
#define GENES 250
#define GH    64
#define GW    64

// ---------------- PTX helpers ----------------
__device__ __forceinline__ uint32_t smem_u32(const void* p) {
    uint32_t a;
    asm("{ .reg .u64 t; cvta.to.shared.u64 t, %1; cvt.u32.u64 %0, t; }" : "=r"(a) : "l"(p));
    return a;
}
#define CP_ASYNC16(sa, ga) \
    asm volatile("cp.async.cg.shared.global [%0], [%1], 16;" :: "r"(sa), "l"(ga))
#define CP_COMMIT() asm volatile("cp.async.commit_group;")
#define CP_WAIT(n)  asm volatile("cp.async.wait_group %0;" :: "n"(n))

#define LDSM4(r0, r1, r2, r3, addr) \
    asm volatile("ldmatrix.sync.aligned.m8n8.x4.shared.b16 {%0,%1,%2,%3}, [%4];" \
        : "=r"(r0), "=r"(r1), "=r"(r2), "=r"(r3) : "r"(addr))
#define LDSM4T(r0, r1, r2, r3, addr) \
    asm volatile("ldmatrix.sync.aligned.m8n8.x4.trans.shared.b16 {%0,%1,%2,%3}, [%4];" \
        : "=r"(r0), "=r"(r1), "=r"(r2), "=r"(r3) : "r"(addr))

__device__ __forceinline__ void mma_bf16(float* d, const uint32_t* a, const uint32_t* b) {
    asm volatile("mma.sync.aligned.m16n8k16.row.col.f32.bf16.bf16.f32 "
        "{%0,%1,%2,%3}, {%4,%5,%6,%7}, {%8,%9}, {%0,%1,%2,%3};"
        : "+f"(d[0]), "+f"(d[1]), "+f"(d[2]), "+f"(d[3])
        : "r"(a[0]), "r"(a[1]), "r"(a[2]), "r"(a[3]), "r"(b[0]), "r"(b[1]));
}

#define PACKBF(d, lo, hi) \
    asm("cvt.rn.bf16x2.f32 %0, %1, %2;" : "=r"(d) : "f"(hi), "f"(lo))

__device__ __forceinline__ float ex2f(float x) {
    float y; asm("ex2.approx.f32 %0, %1;" : "=f"(y) : "f"(x)); return y;
}

__device__ __forceinline__ void hilo(float v, __nv_bfloat16& h, __nv_bfloat16& l) {
    h = __float2bfloat16(v);
    l = __float2bfloat16(v - __bfloat162float(h));
}

// ---------------- device scratch ----------------
__device__ float g_x[NT * D];
__device__ float g_grid[GH * GW * D];
__device__ __nv_bfloat16 g_qkv_h[NT * 3 * D], g_qkv_l[NT * 3 * D];
__device__ __nv_bfloat16 g_xn_h[NT * D],  g_xn_l[NT * D];
__device__ __nv_bfloat16 g_ao_h[NT * D],  g_ao_l[NT * D];
__device__ __nv_bfloat16 g_hh[NT * DMLP], g_hl[NT * DMLP];
__device__ __nv_bfloat16 g_xf_h[NT * D],  g_xf_l[NT * D];
__device__ __nv_bfloat16 g_wqkv_h[DEPTH * 3 * D * D], g_wqkv_l[DEPTH * 3 * D * D];
__device__ __nv_bfloat16 g_wo_h[DEPTH * D * D],       g_wo_l[DEPTH * D * D];
__device__ __nv_bfloat16 g_w1_h[DEPTH * DMLP * D],    g_w1_l[DEPTH * DMLP * D];
__device__ __nv_bfloat16 g_w2_h[DEPTH * D * DMLP],    g_w2_l[DEPTH * D * DMLP];
__device__ __nv_bfloat16 g_wp_h[GENES * D],           g_wp_l[GENES * D];

// ---- one merged weight-conversion kernel (segments: wqkv, w1, w2, wo, wp) --
#define N_WQKV (DEPTH * 3 * D * D)
#define N_W1   (DEPTH * DMLP * D)
#define N_W2   (DEPTH * D * DMLP)
#define N_WO   (DEPTH * D * D)
#define N_WP   (GENES * D)
#define N_CVT  (N_WQKV + N_W1 + N_W2 + N_WO + N_WP)

__global__ void cvt_all(const float* __restrict__ wqkv, const float* __restrict__ w1,
                        const float* __restrict__ w2, const float* __restrict__ wo,
                        const float* __restrict__ wp) {
    int i = blockIdx.x * blockDim.x + threadIdx.x;
    const float* s; __nv_bfloat16 *h, *l; int j = i;
    if (j < N_WQKV)              { s = wqkv; h = g_wqkv_h; l = g_wqkv_l; }
    else if ((j -= N_WQKV) < N_W1) { s = w1; h = g_w1_h; l = g_w1_l; }
    else if ((j -= N_W1) < N_W2)   { s = w2; h = g_w2_h; l = g_w2_l; }
    else if ((j -= N_W2) < N_WO)   { s = wo; h = g_wo_h; l = g_wo_l; }
    else if ((j -= N_WO) < N_WP)   { s = wp; h = g_wp_h; l = g_wp_l; }
    else return;
    __nv_bfloat16 a, b; hilo(s[j], a, b); h[j] = a; l[j] = b;
}

// ---------------- LayerNorm -> bf16 hi/lo (optionally fp32 copy) -----------
template <int WF32>
__global__ void ln_kernel(const float* __restrict__ in, float* __restrict__ out32,
                          __nv_bfloat16* __restrict__ oh, __nv_bfloat16* __restrict__ ol,
                          const float* __restrict__ gam, const float* __restrict__ bet) {
    int row = blockIdx.x, t = threadIdx.x;
    float4 v = ((const float4*)(in + (size_t)row * D))[t];
    float s = v.x + v.y + v.z + v.w;
    float ss = v.x * v.x + v.y * v.y + v.z * v.z + v.w * v.w;
#pragma unroll
    for (int off = 16; off; off >>= 1) {
        s  += __shfl_xor_sync(0xffffffffu, s, off);
        ss += __shfl_xor_sync(0xffffffffu, ss, off);
    }
    __shared__ float sb[4], ssb[4];
    int w = t >> 5, lane = t & 31;
    if (lane == 0) { sb[w] = s; ssb[w] = ss; }
    __syncthreads();
    s = sb[0] + sb[1] + sb[2] + sb[3];
    ss = ssb[0] + ssb[1] + ssb[2] + ssb[3];
    float mean = s * (1.0f / D);
    float inv = rsqrtf(ss * (1.0f / D) - mean * mean + 1e-5f);
    float4 g4 = ((const float4*)gam)[t];
    float4 b4 = ((const float4*)bet)[t];
    float o0 = (v.x - mean) * inv * g4.x + b4.x;
    float o1 = (v.y - mean) * inv * g4.y + b4.y;
    float o2 = (v.z - mean) * inv * g4.z + b4.z;
    float o3 = (v.w - mean) * inv * g4.w + b4.w;
    size_t base = (size_t)row * D + t * 4;
    __nv_bfloat16 h0, l0, h1, l1, h2, l2, h3, l3;
    hilo(o0, h0, l0); hilo(o1, h1, l1); hilo(o2, h2, l2); hilo(o3, h3, l3);
    __nv_bfloat162 p;
    p.x = h0; p.y = h1; *(__nv_bfloat162*)(oh + base) = p;
    p.x = h2; p.y = h3; *(__nv_bfloat162*)(oh + base + 2) = p;
    p.x = l0; p.y = l1; *(__nv_bfloat162*)(ol + base) = p;
    p.x = l2; p.y = l3; *(__nv_bfloat162*)(ol + base + 2) = p;
    if (WF32) {
        float4 o; o.x = o0; o.y = o1; o.z = o2; o.w = o3;
        ((float4*)(out32 + (size_t)row * D))[t] = o;
    }
}

// ---------------- bf16 hi/lo 3-term GEMM via mma.sync (HMMA) ----------------
#define TPITCH 80
#define TILE_B (128 * TPITCH)
#define STAGE_B (4 * TILE_B)
#define GEMM_DYN (2 * STAGE_B)

__device__ __forceinline__ void stage_load(
    uint32_t sbase, const __nv_bfloat16* Ah, const __nv_bfloat16* Al,
    const __nv_bfloat16* Wh, const __nv_bfloat16* Wl,
    int mrow, int ncol, int OUT, int K, int kt, int tid) {
#pragma unroll
    for (int i = 0; i < 2; i++) {
        int chunk = tid + i * 256;
        int r = chunk >> 2, c16 = chunk & 3;
        uint32_t so = (uint32_t)(r * TPITCH + c16 * 16);
        size_t aoff = (size_t)(mrow + r) * K + kt + c16 * 8;
        int wr = ncol + r; if (wr >= OUT) wr = OUT - 1;
        size_t woff = (size_t)wr * K + kt + c16 * 8;
        CP_ASYNC16(sbase + so,              (const char*)(Ah + aoff));
        CP_ASYNC16(sbase + TILE_B + so,     (const char*)(Al + aoff));
        CP_ASYNC16(sbase + 2 * TILE_B + so, (const char*)(Wh + woff));
        CP_ASYNC16(sbase + 3 * TILE_B + so, (const char*)(Wl + woff));
    }
}

// MODE 0: out32=v+bias ; 1: outh/l=hilo(gelu(v+bias)) ; 2: out32+=v+bias ; 3: outh/l=hilo(v+bias)
template <int MODE>
__global__ void __launch_bounds__(256) gemm_mma(
    const __nv_bfloat16* __restrict__ Ah, const __nv_bfloat16* __restrict__ Al,
    const __nv_bfloat16* __restrict__ Wh, const __nv_bfloat16* __restrict__ Wl,
    const float* __restrict__ bias, float* __restrict__ out32,
    __nv_bfloat16* __restrict__ outh, __nv_bfloat16* __restrict__ outl,
    int OUT, int K) {
    extern __shared__ char dyn_raw[];
    const int tid = threadIdx.x, wid = tid >> 5, lane = tid & 31;
    const int mrow = blockIdx.y * 128, ncol = blockIdx.x * 128;
    const int warp_m = wid & 1, warp_n = wid >> 1;
    const int m_off = warp_m * 64, n_off = warp_n * 32;
    const int NIT = K >> 5;
    uint32_t smem0 = smem_u32(dyn_raw);

    float acc[4][4][4];
#pragma unroll
    for (int a = 0; a < 4; a++)
#pragma unroll
        for (int b = 0; b < 4; b++)
#pragma unroll
            for (int c = 0; c < 4; c++) acc[a][b][c] = 0.f;

    const uint32_t a_lm = (uint32_t)((m_off + (lane & 15)) * TPITCH + (lane & 16));
    const int bl = lane & 7, bg = (lane >> 3) & 3;
    const uint32_t b_lm = (uint32_t)((n_off + ((bg >> 1) << 3) + bl) * TPITCH + ((bg & 1) << 4));

    stage_load(smem0, Ah, Al, Wh, Wl, mrow, ncol, OUT, K, 0, tid);
    CP_COMMIT();

    for (int it = 0; it < NIT; it++) {
        if (it + 1 < NIT) {
            stage_load(smem0 + ((it + 1) & 1) * STAGE_B, Ah, Al, Wh, Wl,
                       mrow, ncol, OUT, K, (it + 1) * 32, tid);
            CP_COMMIT();
            CP_WAIT(1);
        } else {
            CP_WAIT(0);
        }
        __syncthreads();
        uint32_t sb = smem0 + (it & 1) * STAGE_B;
#pragma unroll
        for (int ks = 0; ks < 2; ks++) {
            uint32_t kb = (uint32_t)(ks * 32);
            uint32_t ah[4][4], al[4][4], bh[4][2], bl2[4][2];
#pragma unroll
            for (int mt = 0; mt < 4; mt++) {
                uint32_t ad = sb + a_lm + mt * (16 * TPITCH) + kb;
                LDSM4(ah[mt][0], ah[mt][1], ah[mt][2], ah[mt][3], ad);
                LDSM4(al[mt][0], al[mt][1], al[mt][2], al[mt][3], ad + TILE_B);
            }
#pragma unroll
            for (int np = 0; np < 2; np++) {
                uint32_t bd = sb + 2 * TILE_B + b_lm + np * (16 * TPITCH) + kb;
                LDSM4(bh[2 * np][0], bh[2 * np][1], bh[2 * np + 1][0], bh[2 * np + 1][1], bd);
                LDSM4(bl2[2 * np][0], bl2[2 * np][1], bl2[2 * np + 1][0], bl2[2 * np + 1][1], bd + TILE_B);
            }
#pragma unroll
            for (int mt = 0; mt < 4; mt++)
#pragma unroll
                for (int nt = 0; nt < 4; nt++) {
                    mma_bf16(acc[mt][nt], ah[mt], bh[nt]);
                    mma_bf16(acc[mt][nt], ah[mt], bl2[nt]);
                    mma_bf16(acc[mt][nt], al[mt], bh[nt]);
                }
        }
        __syncthreads();
    }

    const int r0 = lane >> 2, cp = (lane & 3) * 2;
#pragma unroll
    for (int mt = 0; mt < 4; mt++)
#pragma unroll
        for (int nt = 0; nt < 4; nt++) {
            int col = ncol + n_off + nt * 8 + cp;
            if (col >= OUT) continue;
            float bx = bias[col], by = bias[col + 1];
#pragma unroll
            for (int half = 0; half < 2; half++) {
                int row = mrow + m_off + mt * 16 + r0 + half * 8;
                float vx = acc[mt][nt][2 * half] + bx;
                float vy = acc[mt][nt][2 * half + 1] + by;
                size_t idx = (size_t)row * OUT + col;
                if (MODE == 0) {
                    *(float2*)(out32 + idx) = make_float2(vx, vy);
                } else if (MODE == 1 || MODE == 3) {
                    if (MODE == 1) {
                        vx = 0.5f * vx * (1.0f + erff(vx * 0.70710678118654752f));
                        vy = 0.5f * vy * (1.0f + erff(vy * 0.70710678118654752f));
                    }
                    __nv_bfloat16 hx, lx, hy, ly;
                    hilo(vx, hx, lx); hilo(vy, hy, ly);
                    __nv_bfloat162 p;
                    p.x = hx; p.y = hy; *(__nv_bfloat162*)(outh + idx) = p;
                    p.x = lx; p.y = ly; *(__nv_bfloat162*)(outl + idx) = p;
                } else {
                    float2 o = *(float2*)(out32 + idx);
                    o.x += vx; o.y += vy;
                    *(float2*)(out32 + idx) = o;
                }
            }
        }
}

// ---------------- flash attention on HMMA, bf16 hi/lo 3-term -----------------
// CTA = (head, 64-query block), 128 threads (round-5 config: 2-3 CTAs/SM).
#define AP 80
#define KVT (64 * AP)
#define ASTG (4 * KVT)

__global__ void __launch_bounds__(128) attn_tc() {
    __shared__ __align__(16) char smem[2 * ASTG];
    const int tid = threadIdx.x, wid = tid >> 5, lane = tid & 31;
    const int h = blockIdx.x, qb = blockIdx.y * 64;
    const uint32_t s0 = smem_u32(smem);

    // ---- stage Q (64x32 hi/lo) and load fragments
#pragma unroll
    for (int i = 0; i < 4; i++) {
        int idx = tid + i * 128;
        int tile = idx >> 8, rem = idx & 255, r = rem >> 2, c = rem & 3;
        const __nv_bfloat16* src = (tile ? g_qkv_l : g_qkv_h) + (size_t)(qb + r) * 1536 + h * 32 + c * 8;
        CP_ASYNC16(s0 + tile * KVT + r * AP + c * 16, src);
    }
    CP_COMMIT(); CP_WAIT(0); __syncthreads();
    uint32_t qh[2][4], ql[2][4];
    {
        uint32_t alm = s0 + (wid * 16 + (lane & 15)) * AP + (lane & 16);
        LDSM4(qh[0][0], qh[0][1], qh[0][2], qh[0][3], alm);
        LDSM4(qh[1][0], qh[1][1], qh[1][2], qh[1][3], alm + 32);
        LDSM4(ql[0][0], ql[0][1], ql[0][2], ql[0][3], alm + KVT);
        LDSM4(ql[1][0], ql[1][1], ql[1][2], ql[1][3], alm + KVT + 32);
    }
    __syncthreads();

    const int bl = lane & 7, bg = (lane >> 3) & 3;
    const uint32_t koff = (uint32_t)((((bg >> 1) * 8) + bl) * AP + ((bg & 1) * 16));
    const uint32_t voff = (uint32_t)(((((lane >> 3) & 1) * 8) + (lane & 7)) * AP + (((lane >> 4) & 1) * 16));

    float O[4][4];
#pragma unroll
    for (int a = 0; a < 4; a++)
#pragma unroll
        for (int b = 0; b < 4; b++) O[a][b] = 0.f;
    float m0 = -1e30f, m1 = -1e30f, lsum0 = 0.f, lsum1 = 0.f;
    const float sc2 = 0.25501649f;   // (1/sqrt(32)) * log2(e)

    // prologue: K/V tile 0
    {
#pragma unroll
        for (int i = 0; i < 8; i++) {
            int idx = tid + i * 128;
            int tile = idx >> 8, rem = idx & 255, r = rem >> 2, c = rem & 3;
            const __nv_bfloat16* base = (tile & 1) ? g_qkv_l : g_qkv_h;
            int col = ((tile >> 1) ? 1024 : 512) + h * 32;
            CP_ASYNC16(s0 + tile * KVT + r * AP + c * 16,
                       base + (size_t)r * 1536 + col + c * 8);
        }
        CP_COMMIT();
    }

    for (int t = 0; t < NT / 64; t++) {
        if (t + 1 < NT / 64) {
            int kb = (t + 1) * 64;
            uint32_t st = s0 + ((t + 1) & 1) * ASTG;
#pragma unroll
            for (int i = 0; i < 8; i++) {
                int idx = tid + i * 128;
                int tile = idx >> 8, rem = idx & 255, r = rem >> 2, c = rem & 3;
                const __nv_bfloat16* base = (tile & 1) ? g_qkv_l : g_qkv_h;
                int col = ((tile >> 1) ? 1024 : 512) + h * 32;
                CP_ASYNC16(st + tile * KVT + r * AP + c * 16,
                           base + (size_t)(kb + r) * 1536 + col + c * 8);
            }
            CP_COMMIT(); CP_WAIT(1);
        } else {
            CP_WAIT(0);
        }
        __syncthreads();
        uint32_t sb = s0 + (t & 1) * ASTG;

        // ---- S = Q K^T (3-term)
        float S[8][4];
#pragma unroll
        for (int a = 0; a < 8; a++)
#pragma unroll
            for (int b = 0; b < 4; b++) S[a][b] = 0.f;
#pragma unroll
        for (int ks = 0; ks < 2; ks++) {
            uint32_t kh[8][2], kl[8][2];
#pragma unroll
            for (int np = 0; np < 4; np++) {
                uint32_t ad = sb + np * (16 * AP) + koff + ks * 32;
                LDSM4(kh[2 * np][0], kh[2 * np][1], kh[2 * np + 1][0], kh[2 * np + 1][1], ad);
                LDSM4(kl[2 * np][0], kl[2 * np][1], kl[2 * np + 1][0], kl[2 * np + 1][1], ad + KVT);
            }
#pragma unroll
            for (int nt = 0; nt < 8; nt++) {
                mma_bf16(S[nt], qh[ks], kh[nt]);
                mma_bf16(S[nt], qh[ks], kl[nt]);
                mma_bf16(S[nt], ql[ks], kh[nt]);
            }
        }

        // ---- online softmax
        float t0 = -1e30f, t1 = -1e30f;
#pragma unroll
        for (int nt = 0; nt < 8; nt++) {
            t0 = fmaxf(t0, fmaxf(S[nt][0], S[nt][1]));
            t1 = fmaxf(t1, fmaxf(S[nt][2], S[nt][3]));
        }
        t0 *= sc2; t1 *= sc2;
        t0 = fmaxf(t0, __shfl_xor_sync(0xffffffffu, t0, 1));
        t0 = fmaxf(t0, __shfl_xor_sync(0xffffffffu, t0, 2));
        t1 = fmaxf(t1, __shfl_xor_sync(0xffffffffu, t1, 1));
        t1 = fmaxf(t1, __shfl_xor_sync(0xffffffffu, t1, 2));
        float mn0 = fmaxf(m0, t0), mn1 = fmaxf(m1, t1);
        float c0 = ex2f(m0 - mn0), c1 = ex2f(m1 - mn1);
        m0 = mn0; m1 = mn1;
        lsum0 *= c0; lsum1 *= c1;
#pragma unroll
        for (int nt = 0; nt < 4; nt++) {
            O[nt][0] *= c0; O[nt][1] *= c0; O[nt][2] *= c1; O[nt][3] *= c1;
        }
        uint32_t ph01[8], ph23[8], pl01[8], pl23[8];
#pragma unroll
        for (int nt = 0; nt < 8; nt++) {
            float p0 = ex2f(fmaf(S[nt][0], sc2, -m0));
            float p1 = ex2f(fmaf(S[nt][1], sc2, -m0));
            float p2 = ex2f(fmaf(S[nt][2], sc2, -m1));
            float p3 = ex2f(fmaf(S[nt][3], sc2, -m1));
            lsum0 += p0 + p1; lsum1 += p2 + p3;
            uint32_t hp, lp;
            PACKBF(hp, p0, p1); ph01[nt] = hp;
            float h0f = __uint_as_float(hp << 16);
            float h1f = __uint_as_float(hp & 0xffff0000u);
            PACKBF(lp, p0 - h0f, p1 - h1f); pl01[nt] = lp;
            PACKBF(hp, p2, p3); ph23[nt] = hp;
            h0f = __uint_as_float(hp << 16);
            h1f = __uint_as_float(hp & 0xffff0000u);
            PACKBF(lp, p2 - h0f, p3 - h1f); pl23[nt] = lp;
        }

        // ---- O += P V (3-term)
#pragma unroll
        for (int s = 0; s < 4; s++) {
            uint32_t aH[4] = { ph01[2 * s], ph23[2 * s], ph01[2 * s + 1], ph23[2 * s + 1] };
            uint32_t aL[4] = { pl01[2 * s], pl23[2 * s], pl01[2 * s + 1], pl23[2 * s + 1] };
            uint32_t vh[4][2], vl[4][2];
#pragma unroll
            for (int d2 = 0; d2 < 2; d2++) {
                uint32_t ad = sb + 2 * KVT + s * (16 * AP) + voff + d2 * 32;
                LDSM4T(vh[2 * d2][0], vh[2 * d2][1], vh[2 * d2 + 1][0], vh[2 * d2 + 1][1], ad);
                LDSM4T(vl[2 * d2][0], vl[2 * d2][1], vl[2 * d2 + 1][0], vl[2 * d2 + 1][1], ad + KVT);
            }
#pragma unroll
            for (int nt = 0; nt < 4; nt++) {
                mma_bf16(O[nt], aH, vh[nt]);
                mma_bf16(O[nt], aH, vl[nt]);
                mma_bf16(O[nt], aL, vh[nt]);
            }
        }
        __syncthreads();
    }

    // ---- epilogue
    lsum0 += __shfl_xor_sync(0xffffffffu, lsum0, 1);
    lsum0 += __shfl_xor_sync(0xffffffffu, lsum0, 2);
    lsum1 += __shfl_xor_sync(0xffffffffu, lsum1, 1);
    lsum1 += __shfl_xor_sync(0xffffffffu, lsum1, 2);
    float i0 = 1.f / lsum0, i1 = 1.f / lsum1;
    int r0 = qb + wid * 16 + (lane >> 2), r1 = r0 + 8;
    int colb = h * 32 + (lane & 3) * 2;
#pragma unroll
    for (int nt = 0; nt < 4; nt++) {
        int col = colb + nt * 8;
        float v0 = O[nt][0] * i0, v1 = O[nt][1] * i0;
        float v2 = O[nt][2] * i1, v3 = O[nt][3] * i1;
        uint32_t hp, lp;
        PACKBF(hp, v0, v1);
        float h0f = __uint_as_float(hp << 16), h1f = __uint_as_float(hp & 0xffff0000u);
        PACKBF(lp, v0 - h0f, v1 - h1f);
        *(uint32_t*)(g_ao_h + (size_t)r0 * D + col) = hp;
        *(uint32_t*)(g_ao_l + (size_t)r0 * D + col) = lp;
        PACKBF(hp, v2, v3);
        h0f = __uint_as_float(hp << 16); h1f = __uint_as_float(hp & 0xffff0000u);
        PACKBF(lp, v2 - h0f, v3 - h1f);
        *(uint32_t*)(g_ao_h + (size_t)r1 * D + col) = hp;
        *(uint32_t*)(g_ao_l + (size_t)r1 * D + col) = lp;
    }
}

// ---------------- conv path (scatter, then fused conv+gather) --------------
__global__ void scatter_kernel(const int* __restrict__ coords) {
    int idx = blockIdx.x * blockDim.x + threadIdx.x;
    int n = idx >> 7, d4 = idx & 127;
    int rr = coords[2 * n], cc = coords[2 * n + 1];
    ((float4*)g_grid)[(size_t)(rr * GW + cc) * 128 + d4] =
        ((const float4*)g_x)[(size_t)n * 128 + d4];
}
__global__ void convgather_kernel(const int* __restrict__ coords,
                                  const float* __restrict__ ck,
                                  const float* __restrict__ cb) {
    int idx = blockIdx.x * blockDim.x + threadIdx.x;
    int n = idx >> 9, d = idx & (D - 1);
    int r = coords[2 * n], c = coords[2 * n + 1];
    float acc = cb[d];
#pragma unroll
    for (int kh = 0; kh < 3; kh++) {
        int rr = r + kh - 1;
        if ((unsigned)rr >= GH) continue;
#pragma unroll
        for (int kw = 0; kw < 3; kw++) {
            int cc = c + kw - 1;
            if ((unsigned)cc >= GW) continue;
            acc += ck[d * 9 + kh * 3 + kw] * g_grid[(size_t)(rr * GW + cc) * D + d];
        }
    }
    g_x[idx] += acc;
}

// ---------------- host ----------------
extern "C" void kernel_launch(void* const* d_in, const int* in_sizes, int n_in,
                              void* d_out, int out_size) {
    const float* gf     = (const float*)d_in[0];
    const int*   coords = (const int*)d_in[1];
    int wi = (n_in >= 22) ? 4 : 2;
    const float* ln1_g = (const float*)d_in[wi + 0];
    const float* ln1_b = (const float*)d_in[wi + 1];
    const float* wqkv  = (const float*)d_in[wi + 2];
    const float* bqkv  = (const float*)d_in[wi + 3];
    const float* wo    = (const float*)d_in[wi + 4];
    const float* bo    = (const float*)d_in[wi + 5];
    const float* ln2_g = (const float*)d_in[wi + 6];
    const float* ln2_b = (const float*)d_in[wi + 7];
    const float* w1    = (const float*)d_in[wi + 8];
    const float* b1    = (const float*)d_in[wi + 9];
    const float* w2    = (const float*)d_in[wi + 10];
    const float* b2    = (const float*)d_in[wi + 11];
    const float* ck    = (const float*)d_in[wi + 12];
    const float* cb    = (const float*)d_in[wi + 13];
    const float* lnf_g = (const float*)d_in[wi + 14];
    const float* lnf_b = (const float*)d_in[wi + 15];
    const float* wp    = (const float*)d_in[wi + 16];
    const float* bp    = (const float*)d_in[wi + 17];

    float* out_x    = (float*)d_out;
    float* out_pred = out_x + (size_t)NT * D;

    static float* px = nullptr;
    static __nv_bfloat16 *pqh, *pql, *pxnh, *pxnl, *paoh, *paol, *phh, *phl, *pxfh, *pxfl;
    static __nv_bfloat16 *pWqh, *pWql, *pWoh, *pWol, *pW1h, *pW1l, *pW2h, *pW2l, *pWph, *pWpl;
    if (!px) {
        cudaGetSymbolAddress((void**)&px, g_x);
        cudaGetSymbolAddress((void**)&pqh, g_qkv_h);  cudaGetSymbolAddress((void**)&pql, g_qkv_l);
        cudaGetSymbolAddress((void**)&pxnh, g_xn_h);  cudaGetSymbolAddress((void**)&pxnl, g_xn_l);
        cudaGetSymbolAddress((void**)&paoh, g_ao_h);  cudaGetSymbolAddress((void**)&paol, g_ao_l);
        cudaGetSymbolAddress((void**)&phh, g_hh);     cudaGetSymbolAddress((void**)&phl, g_hl);
        cudaGetSymbolAddress((void**)&pxfh, g_xf_h);  cudaGetSymbolAddress((void**)&pxfl, g_xf_l);
        cudaGetSymbolAddress((void**)&pWqh, g_wqkv_h); cudaGetSymbolAddress((void**)&pWql, g_wqkv_l);
        cudaGetSymbolAddress((void**)&pWoh, g_wo_h);   cudaGetSymbolAddress((void**)&pWol, g_wo_l);
        cudaGetSymbolAddress((void**)&pW1h, g_w1_h);   cudaGetSymbolAddress((void**)&pW1l, g_w1_l);
        cudaGetSymbolAddress((void**)&pW2h, g_w2_h);   cudaGetSymbolAddress((void**)&pW2l, g_w2_l);
        cudaGetSymbolAddress((void**)&pWph, g_wp_h);   cudaGetSymbolAddress((void**)&pWpl, g_wp_l);
        cudaFuncSetAttribute(gemm_mma<0>, cudaFuncAttributeMaxDynamicSharedMemorySize, GEMM_DYN);
        cudaFuncSetAttribute(gemm_mma<1>, cudaFuncAttributeMaxDynamicSharedMemorySize, GEMM_DYN);
        cudaFuncSetAttribute(gemm_mma<2>, cudaFuncAttributeMaxDynamicSharedMemorySize, GEMM_DYN);
        cudaFuncSetAttribute(gemm_mma<3>, cudaFuncAttributeMaxDynamicSharedMemorySize, GEMM_DYN);
    }

    cudaMemcpyAsync(px, gf, (size_t)NT * D * sizeof(float), cudaMemcpyDeviceToDevice);

    // single merged weight conversion (launch #1); ncu -s 5 then lands inside
    // the first layer (QKV gemm / attn / wo gemm region)
    cvt_all<<<(N_CVT + 255) / 256, 256>>>(wqkv, w1, w2, wo, wp);

    for (int i = 0; i < DEPTH; i++) {
        ln_kernel<0><<<NT, 128>>>(px, nullptr, pxnh, pxnl, ln1_g + i * D, ln1_b + i * D);
        gemm_mma<3><<<dim3(12, 32), 256, GEMM_DYN>>>(
            pxnh, pxnl, pWqh + (size_t)i * 3 * D * D, pWql + (size_t)i * 3 * D * D,
            bqkv + i * 3 * D, nullptr, pqh, pql, 3 * D, D);
        attn_tc<<<dim3(NHD, NT / 64), 128>>>();
        gemm_mma<2><<<dim3(4, 32), 256, GEMM_DYN>>>(
            paoh, paol, pWoh + (size_t)i * D * D, pWol + (size_t)i * D * D,
            bo + i * D, px, nullptr, nullptr, D, D);
        ln_kernel<0><<<NT, 128>>>(px, nullptr, pxnh, pxnl, ln2_g + i * D, ln2_b + i * D);
        gemm_mma<1><<<dim3(16, 32), 256, GEMM_DYN>>>(
            pxnh, pxnl, pW1h + (size_t)i * DMLP * D, pW1l + (size_t)i * DMLP * D,
            b1 + i * DMLP, nullptr, phh, phl, DMLP, D);
        gemm_mma<2><<<dim3(4, 32), 256, GEMM_DYN>>>(
            phh, phl, pW2h + (size_t)i * D * DMLP, pW2l + (size_t)i * D * DMLP,
            b2 + i * D, px, nullptr, nullptr, D, DMLP);
        scatter_kernel<<<NT * (D / 4) / 256, 256>>>(coords);
        convgather_kernel<<<NT * D / 256, 256>>>(coords, ck + (size_t)i * D * 9, cb + i * D);
    }
    ln_kernel<1><<<NT, 128>>>(px, out_x, pxfh, pxfl, lnf_g, lnf_b);
    gemm_mma<0><<<dim3(2, 32), 256, GEMM_DYN>>>(
        pxfh, pxfl, pWph, pWpl, bp, out_pred, nullptr, nullptr, GENES, D);
}

// round 8
// speedup vs baseline: 1.1970x; 1.1639x over previous
#include <cuda_runtime.h>
#include <cuda_bf16.h>
#include <math.h>
#include <stdint.h>

#define NT    4096
#define D     512
#define NHD   16
#define DH    32
#define DEPTH 3
#define DMLP  2048
#define GENES 250
#define GH    64
#define GW    64

// ---------------- PTX helpers ----------------
__device__ __forceinline__ uint32_t smem_u32(const void* p) {
    uint32_t a;
    asm("{ .reg .u64 t; cvta.to.shared.u64 t, %1; cvt.u32.u64 %0, t; }" : "=r"(a) : "l"(p));
    return a;
}
#define CP_ASYNC16(sa, ga) \
    asm volatile("cp.async.cg.shared.global [%0], [%1], 16;" :: "r"(sa), "l"(ga))
#define CP_COMMIT() asm volatile("cp.async.commit_group;")
#define CP_WAIT(n)  asm volatile("cp.async.wait_group %0;" :: "n"(n))

#define LDSM4(r0, r1, r2, r3, addr) \
    asm volatile("ldmatrix.sync.aligned.m8n8.x4.shared.b16 {%0,%1,%2,%3}, [%4];" \
        : "=r"(r0), "=r"(r1), "=r"(r2), "=r"(r3) : "r"(addr))
#define LDSM4T(r0, r1, r2, r3, addr) \
    asm volatile("ldmatrix.sync.aligned.m8n8.x4.trans.shared.b16 {%0,%1,%2,%3}, [%4];" \
        : "=r"(r0), "=r"(r1), "=r"(r2), "=r"(r3) : "r"(addr))

__device__ __forceinline__ void mma_bf16(float* d, const uint32_t* a, const uint32_t* b) {
    asm volatile("mma.sync.aligned.m16n8k16.row.col.f32.bf16.bf16.f32 "
        "{%0,%1,%2,%3}, {%4,%5,%6,%7}, {%8,%9}, {%0,%1,%2,%3};"
        : "+f"(d[0]), "+f"(d[1]), "+f"(d[2]), "+f"(d[3])
        : "r"(a[0]), "r"(a[1]), "r"(a[2]), "r"(a[3]), "r"(b[0]), "r"(b[1]));
}

#define PACKBF(d, lo, hi) \
    asm("cvt.rn.bf16x2.f32 %0, %1, %2;" : "=r"(d) : "f"(hi), "f"(lo))

__device__ __forceinline__ float ex2f(float x) {
    float y; asm("ex2.approx.f32 %0, %1;" : "=f"(y) : "f"(x)); return y;
}

__device__ __forceinline__ void hilo(float v, __nv_bfloat16& h, __nv_bfloat16& l) {
    h = __float2bfloat16(v);
    l = __float2bfloat16(v - __bfloat162float(h));
}

// ---------------- device scratch ----------------
__device__ float g_x[NT * D];
__device__ float g_grid[GH * GW * D];
__device__ __nv_bfloat16 g_qkv_h[NT * 3 * D], g_qkv_l[NT * 3 * D];
__device__ __nv_bfloat16 g_xn_h[NT * D],  g_xn_l[NT * D];
__device__ __nv_bfloat16 g_ao_h[NT * D],  g_ao_l[NT * D];
__device__ __nv_bfloat16 g_hh[NT * DMLP], g_hl[NT * DMLP];
__device__ __nv_bfloat16 g_xf_h[NT * D],  g_xf_l[NT * D];
__device__ __nv_bfloat16 g_wqkv_h[DEPTH * 3 * D * D], g_wqkv_l[DEPTH * 3 * D * D];
__device__ __nv_bfloat16 g_wo_h[DEPTH * D * D],       g_wo_l[DEPTH * D * D];
__device__ __nv_bfloat16 g_w1_h[DEPTH * DMLP * D],    g_w1_l[DEPTH * DMLP * D];
__device__ __nv_bfloat16 g_w2_h[DEPTH * D * DMLP],    g_w2_l[DEPTH * D * DMLP];
__device__ __nv_bfloat16 g_wp_h[GENES * D],           g_wp_l[GENES * D];

// ---- one merged weight-conversion kernel ----
#define N_WQKV (DEPTH * 3 * D * D)
#define N_W1   (DEPTH * DMLP * D)
#define N_W2   (DEPTH * D * DMLP)
#define N_WO   (DEPTH * D * D)
#define N_WP   (GENES * D)
#define N_CVT  (N_WQKV + N_W1 + N_W2 + N_WO + N_WP)

__global__ void cvt_all(const float* __restrict__ wqkv, const float* __restrict__ w1,
                        const float* __restrict__ w2, const float* __restrict__ wo,
                        const float* __restrict__ wp) {
    int i = blockIdx.x * blockDim.x + threadIdx.x;
    const float* s; __nv_bfloat16 *h, *l; int j = i;
    if (j < N_WQKV)              { s = wqkv; h = g_wqkv_h; l = g_wqkv_l; }
    else if ((j -= N_WQKV) < N_W1) { s = w1; h = g_w1_h; l = g_w1_l; }
    else if ((j -= N_W1) < N_W2)   { s = w2; h = g_w2_h; l = g_w2_l; }
    else if ((j -= N_W2) < N_WO)   { s = wo; h = g_wo_h; l = g_wo_l; }
    else if ((j -= N_WO) < N_WP)   { s = wp; h = g_wp_h; l = g_wp_l; }
    else return;
    __nv_bfloat16 a, b; hilo(s[j], a, b); h[j] = a; l[j] = b;
}

// ---------------- LayerNorm -> bf16 hi/lo (optionally fp32 copy) -----------
template <int WF32>
__global__ void ln_kernel(const float* __restrict__ in, float* __restrict__ out32,
                          __nv_bfloat16* __restrict__ oh, __nv_bfloat16* __restrict__ ol,
                          const float* __restrict__ gam, const float* __restrict__ bet) {
    int row = blockIdx.x, t = threadIdx.x;
    float4 v = ((const float4*)(in + (size_t)row * D))[t];
    float s = v.x + v.y + v.z + v.w;
    float ss = v.x * v.x + v.y * v.y + v.z * v.z + v.w * v.w;
#pragma unroll
    for (int off = 16; off; off >>= 1) {
        s  += __shfl_xor_sync(0xffffffffu, s, off);
        ss += __shfl_xor_sync(0xffffffffu, ss, off);
    }
    __shared__ float sb[4], ssb[4];
    int w = t >> 5, lane = t & 31;
    if (lane == 0) { sb[w] = s; ssb[w] = ss; }
    __syncthreads();
    s = sb[0] + sb[1] + sb[2] + sb[3];
    ss = ssb[0] + ssb[1] + ssb[2] + ssb[3];
    float mean = s * (1.0f / D);
    float inv = rsqrtf(ss * (1.0f / D) - mean * mean + 1e-5f);
    float4 g4 = ((const float4*)gam)[t];
    float4 b4 = ((const float4*)bet)[t];
    float o0 = (v.x - mean) * inv * g4.x + b4.x;
    float o1 = (v.y - mean) * inv * g4.y + b4.y;
    float o2 = (v.z - mean) * inv * g4.z + b4.z;
    float o3 = (v.w - mean) * inv * g4.w + b4.w;
    size_t base = (size_t)row * D + t * 4;
    __nv_bfloat16 h0, l0, h1, l1, h2, l2, h3, l3;
    hilo(o0, h0, l0); hilo(o1, h1, l1); hilo(o2, h2, l2); hilo(o3, h3, l3);
    __nv_bfloat162 p;
    p.x = h0; p.y = h1; *(__nv_bfloat162*)(oh + base) = p;
    p.x = h2; p.y = h3; *(__nv_bfloat162*)(oh + base + 2) = p;
    p.x = l0; p.y = l1; *(__nv_bfloat162*)(ol + base) = p;
    p.x = l2; p.y = l3; *(__nv_bfloat162*)(ol + base + 2) = p;
    if (WF32) {
        float4 o; o.x = o0; o.y = o1; o.z = o2; o.w = o3;
        ((float4*)(out32 + (size_t)row * D))[t] = o;
    }
}

// ---------------- bf16 hi/lo 3-term GEMM via mma.sync (HMMA) ----------------
#define TPITCH 80
#define TILE_B (128 * TPITCH)
#define STAGE_B (4 * TILE_B)
#define GEMM_DYN (2 * STAGE_B)

__device__ __forceinline__ void stage_load(
    uint32_t sbase, const __nv_bfloat16* Ah, const __nv_bfloat16* Al,
    const __nv_bfloat16* Wh, const __nv_bfloat16* Wl,
    int mrow, int ncol, int OUT, int K, int kt, int tid) {
#pragma unroll
    for (int i = 0; i < 2; i++) {
        int chunk = tid + i * 256;
        int r = chunk >> 2, c16 = chunk & 3;
        uint32_t so = (uint32_t)(r * TPITCH + c16 * 16);
        size_t aoff = (size_t)(mrow + r) * K + kt + c16 * 8;
        int wr = ncol + r; if (wr >= OUT) wr = OUT - 1;
        size_t woff = (size_t)wr * K + kt + c16 * 8;
        CP_ASYNC16(sbase + so,              (const char*)(Ah + aoff));
        CP_ASYNC16(sbase + TILE_B + so,     (const char*)(Al + aoff));
        CP_ASYNC16(sbase + 2 * TILE_B + so, (const char*)(Wh + woff));
        CP_ASYNC16(sbase + 3 * TILE_B + so, (const char*)(Wl + woff));
    }
}

// MODE 0: out32=v+bias ; 1: outh/l=hilo(gelu(v+bias)) ; 2: out32+=v+bias ; 3: outh/l=hilo(v+bias)
template <int MODE>
__global__ void __launch_bounds__(256) gemm_mma(
    const __nv_bfloat16* __restrict__ Ah, const __nv_bfloat16* __restrict__ Al,
    const __nv_bfloat16* __restrict__ Wh, const __nv_bfloat16* __restrict__ Wl,
    const float* __restrict__ bias, float* __restrict__ out32,
    __nv_bfloat16* __restrict__ outh, __nv_bfloat16* __restrict__ outl,
    int OUT, int K) {
    extern __shared__ char dyn_raw[];
    const int tid = threadIdx.x, wid = tid >> 5, lane = tid & 31;
    const int mrow = blockIdx.y * 128, ncol = blockIdx.x * 128;
    const int warp_m = wid & 1, warp_n = wid >> 1;
    const int m_off = warp_m * 64, n_off = warp_n * 32;
    const int NIT = K >> 5;
    uint32_t smem0 = smem_u32(dyn_raw);

    float acc[4][4][4];
#pragma unroll
    for (int a = 0; a < 4; a++)
#pragma unroll
        for (int b = 0; b < 4; b++)
#pragma unroll
            for (int c = 0; c < 4; c++) acc[a][b][c] = 0.f;

    const uint32_t a_lm = (uint32_t)((m_off + (lane & 15)) * TPITCH + (lane & 16));
    const int bl = lane & 7, bg = (lane >> 3) & 3;
    const uint32_t b_lm = (uint32_t)((n_off + ((bg >> 1) << 3) + bl) * TPITCH + ((bg & 1) << 4));

    stage_load(smem0, Ah, Al, Wh, Wl, mrow, ncol, OUT, K, 0, tid);
    CP_COMMIT();

    for (int it = 0; it < NIT; it++) {
        if (it + 1 < NIT) {
            stage_load(smem0 + ((it + 1) & 1) * STAGE_B, Ah, Al, Wh, Wl,
                       mrow, ncol, OUT, K, (it + 1) * 32, tid);
            CP_COMMIT();
            CP_WAIT(1);
        } else {
            CP_WAIT(0);
        }
        __syncthreads();
        uint32_t sb = smem0 + (it & 1) * STAGE_B;
#pragma unroll
        for (int ks = 0; ks < 2; ks++) {
            uint32_t kb = (uint32_t)(ks * 32);
            uint32_t ah[4][4], al[4][4], bh[4][2], bl2[4][2];
#pragma unroll
            for (int mt = 0; mt < 4; mt++) {
                uint32_t ad = sb + a_lm + mt * (16 * TPITCH) + kb;
                LDSM4(ah[mt][0], ah[mt][1], ah[mt][2], ah[mt][3], ad);
                LDSM4(al[mt][0], al[mt][1], al[mt][2], al[mt][3], ad + TILE_B);
            }
#pragma unroll
            for (int np = 0; np < 2; np++) {
                uint32_t bd = sb + 2 * TILE_B + b_lm + np * (16 * TPITCH) + kb;
                LDSM4(bh[2 * np][0], bh[2 * np][1], bh[2 * np + 1][0], bh[2 * np + 1][1], bd);
                LDSM4(bl2[2 * np][0], bl2[2 * np][1], bl2[2 * np + 1][0], bl2[2 * np + 1][1], bd + TILE_B);
            }
#pragma unroll
            for (int mt = 0; mt < 4; mt++)
#pragma unroll
                for (int nt = 0; nt < 4; nt++) {
                    mma_bf16(acc[mt][nt], ah[mt], bh[nt]);
                    mma_bf16(acc[mt][nt], ah[mt], bl2[nt]);
                    mma_bf16(acc[mt][nt], al[mt], bh[nt]);
                }
        }
        __syncthreads();
    }

    const int r0 = lane >> 2, cp = (lane & 3) * 2;
#pragma unroll
    for (int mt = 0; mt < 4; mt++)
#pragma unroll
        for (int nt = 0; nt < 4; nt++) {
            int col = ncol + n_off + nt * 8 + cp;
            if (col >= OUT) continue;
            float bx = bias[col], by = bias[col + 1];
#pragma unroll
            for (int half = 0; half < 2; half++) {
                int row = mrow + m_off + mt * 16 + r0 + half * 8;
                float vx = acc[mt][nt][2 * half] + bx;
                float vy = acc[mt][nt][2 * half + 1] + by;
                size_t idx = (size_t)row * OUT + col;
                if (MODE == 0) {
                    *(float2*)(out32 + idx) = make_float2(vx, vy);
                } else if (MODE == 1 || MODE == 3) {
                    if (MODE == 1) {
                        vx = 0.5f * vx * (1.0f + erff(vx * 0.70710678118654752f));
                        vy = 0.5f * vy * (1.0f + erff(vy * 0.70710678118654752f));
                    }
                    __nv_bfloat16 hx, lx, hy, ly;
                    hilo(vx, hx, lx); hilo(vy, hy, ly);
                    __nv_bfloat162 p;
                    p.x = hx; p.y = hy; *(__nv_bfloat162*)(outh + idx) = p;
                    p.x = lx; p.y = ly; *(__nv_bfloat162*)(outl + idx) = p;
                } else {
                    float2 o = *(float2*)(out32 + idx);
                    o.x += vx; o.y += vy;
                    *(float2*)(out32 + idx) = o;
                }
            }
        }
}

// ---------------- flash attention on HMMA, 2-term hi/lo ---------------------
// CTA = (head, 64-query block), 128 threads. K and V truncated to bf16-hi;
// Q and P keep hi+lo (errors enter only via K_lo/V_lo, ~1e-4 downstream).
// Stage = Kh + Vh = 10 KB, double-buffered (20 KB total smem).
#define AP 80
#define KVT (64 * AP)
#define ASTG (2 * KVT)

__global__ void __launch_bounds__(128) attn_tc() {
    __shared__ __align__(16) char smem[2 * ASTG];
    const int tid = threadIdx.x, wid = tid >> 5, lane = tid & 31;
    const int h = blockIdx.x, qb = blockIdx.y * 64;
    const uint32_t s0 = smem_u32(smem);

    // ---- stage Q (64x32 hi/lo) and load fragments (uses first 10 KB)
#pragma unroll
    for (int i = 0; i < 4; i++) {
        int idx = tid + i * 128;
        int tile = idx >> 8, rem = idx & 255, r = rem >> 2, c = rem & 3;
        const __nv_bfloat16* src = (tile ? g_qkv_l : g_qkv_h) + (size_t)(qb + r) * 1536 + h * 32 + c * 8;
        CP_ASYNC16(s0 + tile * KVT + r * AP + c * 16, src);
    }
    CP_COMMIT(); CP_WAIT(0); __syncthreads();
    uint32_t qh[2][4], ql[2][4];
    {
        uint32_t alm = s0 + (wid * 16 + (lane & 15)) * AP + (lane & 16);
        LDSM4(qh[0][0], qh[0][1], qh[0][2], qh[0][3], alm);
        LDSM4(qh[1][0], qh[1][1], qh[1][2], qh[1][3], alm + 32);
        LDSM4(ql[0][0], ql[0][1], ql[0][2], ql[0][3], alm + KVT);
        LDSM4(ql[1][0], ql[1][1], ql[1][2], ql[1][3], alm + KVT + 32);
    }
    __syncthreads();

    const int bl = lane & 7, bg = (lane >> 3) & 3;
    const uint32_t koff = (uint32_t)((((bg >> 1) * 8) + bl) * AP + ((bg & 1) * 16));
    const uint32_t voff = (uint32_t)(((((lane >> 3) & 1) * 8) + (lane & 7)) * AP + (((lane >> 4) & 1) * 16));

    float O[4][4];
#pragma unroll
    for (int a = 0; a < 4; a++)
#pragma unroll
        for (int b = 0; b < 4; b++) O[a][b] = 0.f;
    float m0 = -1e30f, m1 = -1e30f, lsum0 = 0.f, lsum1 = 0.f;
    const float sc2 = 0.25501649f;   // (1/sqrt(32)) * log2(e)

    // prologue: K/V tile 0 (tiles: 0=Kh, 1=Vh; hi parts only)
    {
#pragma unroll
        for (int i = 0; i < 4; i++) {
            int idx = tid + i * 128;
            int tile = idx >> 8, rem = idx & 255, r = rem >> 2, c = rem & 3;
            int col = (tile ? 1024 : 512) + h * 32;
            CP_ASYNC16(s0 + tile * KVT + r * AP + c * 16,
                       g_qkv_h + (size_t)r * 1536 + col + c * 8);
        }
        CP_COMMIT();
    }

    for (int t = 0; t < NT / 64; t++) {
        if (t + 1 < NT / 64) {
            int kb = (t + 1) * 64;
            uint32_t st = s0 + ((t + 1) & 1) * ASTG;
#pragma unroll
            for (int i = 0; i < 4; i++) {
                int idx = tid + i * 128;
                int tile = idx >> 8, rem = idx & 255, r = rem >> 2, c = rem & 3;
                int col = (tile ? 1024 : 512) + h * 32;
                CP_ASYNC16(st + tile * KVT + r * AP + c * 16,
                           g_qkv_h + (size_t)(kb + r) * 1536 + col + c * 8);
            }
            CP_COMMIT(); CP_WAIT(1);
        } else {
            CP_WAIT(0);
        }
        __syncthreads();
        uint32_t sb = s0 + (t & 1) * ASTG;

        // ---- S = (Qh + Ql) Kh^T (2-term)
        float S[8][4];
#pragma unroll
        for (int a = 0; a < 8; a++)
#pragma unroll
            for (int b = 0; b < 4; b++) S[a][b] = 0.f;
#pragma unroll
        for (int ks = 0; ks < 2; ks++) {
            uint32_t kh[8][2];
#pragma unroll
            for (int np = 0; np < 4; np++) {
                uint32_t ad = sb + np * (16 * AP) + koff + ks * 32;
                LDSM4(kh[2 * np][0], kh[2 * np][1], kh[2 * np + 1][0], kh[2 * np + 1][1], ad);
            }
#pragma unroll
            for (int nt = 0; nt < 8; nt++) {
                mma_bf16(S[nt], qh[ks], kh[nt]);
                mma_bf16(S[nt], ql[ks], kh[nt]);
            }
        }

        // ---- online softmax
        float t0 = -1e30f, t1 = -1e30f;
#pragma unroll
        for (int nt = 0; nt < 8; nt++) {
            t0 = fmaxf(t0, fmaxf(S[nt][0], S[nt][1]));
            t1 = fmaxf(t1, fmaxf(S[nt][2], S[nt][3]));
        }
        t0 *= sc2; t1 *= sc2;
        t0 = fmaxf(t0, __shfl_xor_sync(0xffffffffu, t0, 1));
        t0 = fmaxf(t0, __shfl_xor_sync(0xffffffffu, t0, 2));
        t1 = fmaxf(t1, __shfl_xor_sync(0xffffffffu, t1, 1));
        t1 = fmaxf(t1, __shfl_xor_sync(0xffffffffu, t1, 2));
        float mn0 = fmaxf(m0, t0), mn1 = fmaxf(m1, t1);
        float c0 = ex2f(m0 - mn0), c1 = ex2f(m1 - mn1);
        m0 = mn0; m1 = mn1;
        lsum0 *= c0; lsum1 *= c1;
#pragma unroll
        for (int nt = 0; nt < 4; nt++) {
            O[nt][0] *= c0; O[nt][1] *= c0; O[nt][2] *= c1; O[nt][3] *= c1;
        }
        uint32_t ph01[8], ph23[8], pl01[8], pl23[8];
#pragma unroll
        for (int nt = 0; nt < 8; nt++) {
            float p0 = ex2f(fmaf(S[nt][0], sc2, -m0));
            float p1 = ex2f(fmaf(S[nt][1], sc2, -m0));
            float p2 = ex2f(fmaf(S[nt][2], sc2, -m1));
            float p3 = ex2f(fmaf(S[nt][3], sc2, -m1));
            lsum0 += p0 + p1; lsum1 += p2 + p3;
            uint32_t hp, lp;
            PACKBF(hp, p0, p1); ph01[nt] = hp;
            float h0f = __uint_as_float(hp << 16);
            float h1f = __uint_as_float(hp & 0xffff0000u);
            PACKBF(lp, p0 - h0f, p1 - h1f); pl01[nt] = lp;
            PACKBF(hp, p2, p3); ph23[nt] = hp;
            h0f = __uint_as_float(hp << 16);
            h1f = __uint_as_float(hp & 0xffff0000u);
            PACKBF(lp, p2 - h0f, p3 - h1f); pl23[nt] = lp;
        }

        // ---- O += (Ph + Pl) Vh (2-term)
#pragma unroll
        for (int s = 0; s < 4; s++) {
            uint32_t aH[4] = { ph01[2 * s], ph23[2 * s], ph01[2 * s + 1], ph23[2 * s + 1] };
            uint32_t aL[4] = { pl01[2 * s], pl23[2 * s], pl01[2 * s + 1], pl23[2 * s + 1] };
            uint32_t vh[4][2];
#pragma unroll
            for (int d2 = 0; d2 < 2; d2++) {
                uint32_t ad = sb + KVT + s * (16 * AP) + voff + d2 * 32;
                LDSM4T(vh[2 * d2][0], vh[2 * d2][1], vh[2 * d2 + 1][0], vh[2 * d2 + 1][1], ad);
            }
#pragma unroll
            for (int nt = 0; nt < 4; nt++) {
                mma_bf16(O[nt], aH, vh[nt]);
                mma_bf16(O[nt], aL, vh[nt]);
            }
        }
        __syncthreads();
    }

    // ---- epilogue
    lsum0 += __shfl_xor_sync(0xffffffffu, lsum0, 1);
    lsum0 += __shfl_xor_sync(0xffffffffu, lsum0, 2);
    lsum1 += __shfl_xor_sync(0xffffffffu, lsum1, 1);
    lsum1 += __shfl_xor_sync(0xffffffffu, lsum1, 2);
    float i0 = 1.f / lsum0, i1 = 1.f / lsum1;
    int r0 = qb + wid * 16 + (lane >> 2), r1 = r0 + 8;
    int colb = h * 32 + (lane & 3) * 2;
#pragma unroll
    for (int nt = 0; nt < 4; nt++) {
        int col = colb + nt * 8;
        float v0 = O[nt][0] * i0, v1 = O[nt][1] * i0;
        float v2 = O[nt][2] * i1, v3 = O[nt][3] * i1;
        uint32_t hp, lp;
        PACKBF(hp, v0, v1);
        float h0f = __uint_as_float(hp << 16), h1f = __uint_as_float(hp & 0xffff0000u);
        PACKBF(lp, v0 - h0f, v1 - h1f);
        *(uint32_t*)(g_ao_h + (size_t)r0 * D + col) = hp;
        *(uint32_t*)(g_ao_l + (size_t)r0 * D + col) = lp;
        PACKBF(hp, v2, v3);
        h0f = __uint_as_float(hp << 16); h1f = __uint_as_float(hp & 0xffff0000u);
        PACKBF(lp, v2 - h0f, v3 - h1f);
        *(uint32_t*)(g_ao_h + (size_t)r1 * D + col) = hp;
        *(uint32_t*)(g_ao_l + (size_t)r1 * D + col) = lp;
    }
}

// ---------------- conv path (scatter, then fused conv+gather) --------------
__global__ void scatter_kernel(const int* __restrict__ coords) {
    int idx = blockIdx.x * blockDim.x + threadIdx.x;
    int n = idx >> 7, d4 = idx & 127;
    int rr = coords[2 * n], cc = coords[2 * n + 1];
    ((float4*)g_grid)[(size_t)(rr * GW + cc) * 128 + d4] =
        ((const float4*)g_x)[(size_t)n * 128 + d4];
}
__global__ void convgather_kernel(const int* __restrict__ coords,
                                  const float* __restrict__ ck,
                                  const float* __restrict__ cb) {
    int idx = blockIdx.x * blockDim.x + threadIdx.x;
    int n = idx >> 9, d = idx & (D - 1);
    int r = coords[2 * n], c = coords[2 * n + 1];
    float acc = cb[d];
#pragma unroll
    for (int kh = 0; kh < 3; kh++) {
        int rr = r + kh - 1;
        if ((unsigned)rr >= GH) continue;
#pragma unroll
        for (int kw = 0; kw < 3; kw++) {
            int cc = c + kw - 1;
            if ((unsigned)cc >= GW) continue;
            acc += ck[d * 9 + kh * 3 + kw] * g_grid[(size_t)(rr * GW + cc) * D + d];
        }
    }
    g_x[idx] += acc;
}

// ---------------- host ----------------
extern "C" void kernel_launch(void* const* d_in, const int* in_sizes, int n_in,
                              void* d_out, int out_size) {
    const float* gf     = (const float*)d_in[0];
    const int*   coords = (const int*)d_in[1];
    int wi = (n_in >= 22) ? 4 : 2;
    const float* ln1_g = (const float*)d_in[wi + 0];
    const float* ln1_b = (const float*)d_in[wi + 1];
    const float* wqkv  = (const float*)d_in[wi + 2];
    const float* bqkv  = (const float*)d_in[wi + 3];
    const float* wo    = (const float*)d_in[wi + 4];
    const float* bo    = (const float*)d_in[wi + 5];
    const float* ln2_g = (const float*)d_in[wi + 6];
    const float* ln2_b = (const float*)d_in[wi + 7];
    const float* w1    = (const float*)d_in[wi + 8];
    const float* b1    = (const float*)d_in[wi + 9];
    const float* w2    = (const float*)d_in[wi + 10];
    const float* b2    = (const float*)d_in[wi + 11];
    const float* ck    = (const float*)d_in[wi + 12];
    const float* cb    = (const float*)d_in[wi + 13];
    const float* lnf_g = (const float*)d_in[wi + 14];
    const float* lnf_b = (const float*)d_in[wi + 15];
    const float* wp    = (const float*)d_in[wi + 16];
    const float* bp    = (const float*)d_in[wi + 17];

    float* out_x    = (float*)d_out;
    float* out_pred = out_x + (size_t)NT * D;

    static float* px = nullptr;
    static __nv_bfloat16 *pqh, *pql, *pxnh, *pxnl, *paoh, *paol, *phh, *phl, *pxfh, *pxfl;
    static __nv_bfloat16 *pWqh, *pWql, *pWoh, *pWol, *pW1h, *pW1l, *pW2h, *pW2l, *pWph, *pWpl;
    if (!px) {
        cudaGetSymbolAddress((void**)&px, g_x);
        cudaGetSymbolAddress((void**)&pqh, g_qkv_h);  cudaGetSymbolAddress((void**)&pql, g_qkv_l);
        cudaGetSymbolAddress((void**)&pxnh, g_xn_h);  cudaGetSymbolAddress((void**)&pxnl, g_xn_l);
        cudaGetSymbolAddress((void**)&paoh, g_ao_h);  cudaGetSymbolAddress((void**)&paol, g_ao_l);
        cudaGetSymbolAddress((void**)&phh, g_hh);     cudaGetSymbolAddress((void**)&phl, g_hl);
        cudaGetSymbolAddress((void**)&pxfh, g_xf_h);  cudaGetSymbolAddress((void**)&pxfl, g_xf_l);
        cudaGetSymbolAddress((void**)&pWqh, g_wqkv_h); cudaGetSymbolAddress((void**)&pWql, g_wqkv_l);
        cudaGetSymbolAddress((void**)&pWoh, g_wo_h);   cudaGetSymbolAddress((void**)&pWol, g_wo_l);
        cudaGetSymbolAddress((void**)&pW1h, g_w1_h);   cudaGetSymbolAddress((void**)&pW1l, g_w1_l);
        cudaGetSymbolAddress((void**)&pW2h, g_w2_h);   cudaGetSymbolAddress((void**)&pW2l, g_w2_l);
        cudaGetSymbolAddress((void**)&pWph, g_wp_h);   cudaGetSymbolAddress((void**)&pWpl, g_wp_l);
        cudaFuncSetAttribute(gemm_mma<0>, cudaFuncAttributeMaxDynamicSharedMemorySize, GEMM_DYN);
        cudaFuncSetAttribute(gemm_mma<1>, cudaFuncAttributeMaxDynamicSharedMemorySize, GEMM_DYN);
        cudaFuncSetAttribute(gemm_mma<2>, cudaFuncAttributeMaxDynamicSharedMemorySize, GEMM_DYN);
        cudaFuncSetAttribute(gemm_mma<3>, cudaFuncAttributeMaxDynamicSharedMemorySize, GEMM_DYN);
    }

    cudaMemcpyAsync(px, gf, (size_t)NT * D * sizeof(float), cudaMemcpyDeviceToDevice);

    cvt_all<<<(N_CVT + 255) / 256, 256>>>(wqkv, w1, w2, wo, wp);

    for (int i = 0; i < DEPTH; i++) {
        ln_kernel<0><<<NT, 128>>>(px, nullptr, pxnh, pxnl, ln1_g + i * D, ln1_b + i * D);
        gemm_mma<3><<<dim3(12, 32), 256, GEMM_DYN>>>(
            pxnh, pxnl, pWqh + (size_t)i * 3 * D * D, pWql + (size_t)i * 3 * D * D,
            bqkv + i * 3 * D, nullptr, pqh, pql, 3 * D, D);
        attn_tc<<<dim3(NHD, NT / 64), 128>>>();
        gemm_mma<2><<<dim3(4, 32), 256, GEMM_DYN>>>(
            paoh, paol, pWoh + (size_t)i * D * D, pWol + (size_t)i * D * D,
            bo + i * D, px, nullptr, nullptr, D, D);
        ln_kernel<0><<<NT, 128>>>(px, nullptr, pxnh, pxnl, ln2_g + i * D, ln2_b + i * D);
        gemm_mma<1><<<dim3(16, 32), 256, GEMM_DYN>>>(
            pxnh, pxnl, pW1h + (size_t)i * DMLP * D, pW1l + (size_t)i * DMLP * D,
            b1 + i * DMLP, nullptr, phh, phl, DMLP, D);
        gemm_mma<2><<<dim3(4, 32), 256, GEMM_DYN>>>(
            phh, phl, pW2h + (size_t)i * D * DMLP, pW2l + (size_t)i * D * DMLP,
            b2 + i * D, px, nullptr, nullptr, D, DMLP);
        scatter_kernel<<<NT * (D / 4) / 256, 256>>>(coords);
        convgather_kernel<<<NT * D / 256, 256>>>(coords, ck + (size_t)i * D * 9, cb + i * D);
    }
    ln_kernel<1><<<NT, 128>>>(px, out_x, pxfh, pxfl, lnf_g, lnf_b);
    gemm_mma<0><<<dim3(2, 32), 256, GEMM_DYN>>>(
        pxfh, pxfl, pWph, pWpl, bp, out_pred, nullptr, nullptr, GENES, D);
}

// round 9
// speedup vs baseline: 1.3918x; 1.1627x over previous
#include <cuda_runtime.h>
#include <cuda_bf16.h>
#include <math.h>
#include <stdint.h>

#define NT    4096
#define D     512
#define NHD   16
#define DH    32
#define DEPTH 3
#define DMLP  2048
#define GENES 250
#define GH    64
#define GW    64

// ---------------- PTX helpers ----------------
__device__ __forceinline__ uint32_t smem_u32(const void* p) {
    uint32_t a;
    asm("{ .reg .u64 t; cvta.to.shared.u64 t, %1; cvt.u32.u64 %0, t; }" : "=r"(a) : "l"(p));
    return a;
}
#define CP_ASYNC16(sa, ga) \
    asm volatile("cp.async.cg.shared.global [%0], [%1], 16;" :: "r"(sa), "l"(ga))
#define CP_COMMIT() asm volatile("cp.async.commit_group;")
#define CP_WAIT(n)  asm volatile("cp.async.wait_group %0;" :: "n"(n))

#define LDSM4(r0, r1, r2, r3, addr) \
    asm volatile("ldmatrix.sync.aligned.m8n8.x4.shared.b16 {%0,%1,%2,%3}, [%4];" \
        : "=r"(r0), "=r"(r1), "=r"(r2), "=r"(r3) : "r"(addr))
#define LDSM4T(r0, r1, r2, r3, addr) \
    asm volatile("ldmatrix.sync.aligned.m8n8.x4.trans.shared.b16 {%0,%1,%2,%3}, [%4];" \
        : "=r"(r0), "=r"(r1), "=r"(r2), "=r"(r3) : "r"(addr))

__device__ __forceinline__ void mma_bf16(float* d, const uint32_t* a, const uint32_t* b) {
    asm volatile("mma.sync.aligned.m16n8k16.row.col.f32.bf16.bf16.f32 "
        "{%0,%1,%2,%3}, {%4,%5,%6,%7}, {%8,%9}, {%0,%1,%2,%3};"
        : "+f"(d[0]), "+f"(d[1]), "+f"(d[2]), "+f"(d[3])
        : "r"(a[0]), "r"(a[1]), "r"(a[2]), "r"(a[3]), "r"(b[0]), "r"(b[1]));
}

#define PACKBF(d, lo, hi) \
    asm("cvt.rn.bf16x2.f32 %0, %1, %2;" : "=r"(d) : "f"(hi), "f"(lo))

__device__ __forceinline__ float ex2f(float x) {
    float y; asm("ex2.approx.f32 %0, %1;" : "=f"(y) : "f"(x)); return y;
}

__device__ __forceinline__ void hilo(float v, __nv_bfloat16& h, __nv_bfloat16& l) {
    h = __float2bfloat16(v);
    l = __float2bfloat16(v - __bfloat162float(h));
}

// ---------------- device scratch ----------------
__device__ float g_x[NT * D];
__device__ float g_grid[GH * GW * D];
__device__ __nv_bfloat16 g_qkv_h[NT * 3 * D];
__device__ __nv_bfloat16 g_xn_h[NT * D],  g_xn_l[NT * D];
__device__ __nv_bfloat16 g_ao_h[NT * D],  g_ao_l[NT * D];
__device__ __nv_bfloat16 g_hh[NT * DMLP], g_hl[NT * DMLP];
__device__ __nv_bfloat16 g_xf_h[NT * D],  g_xf_l[NT * D];
__device__ __nv_bfloat16 g_wqkv_h[DEPTH * 3 * D * D], g_wqkv_l[DEPTH * 3 * D * D];
__device__ __nv_bfloat16 g_wo_h[DEPTH * D * D],       g_wo_l[DEPTH * D * D];
__device__ __nv_bfloat16 g_w1_h[DEPTH * DMLP * D],    g_w1_l[DEPTH * DMLP * D];
__device__ __nv_bfloat16 g_w2_h[DEPTH * D * DMLP],    g_w2_l[DEPTH * D * DMLP];
__device__ __nv_bfloat16 g_wp_h[GENES * D],           g_wp_l[GENES * D];

// ---- one merged weight-conversion kernel ----
#define N_WQKV (DEPTH * 3 * D * D)
#define N_W1   (DEPTH * DMLP * D)
#define N_W2   (DEPTH * D * DMLP)
#define N_WO   (DEPTH * D * D)
#define N_WP   (GENES * D)
#define N_CVT  (N_WQKV + N_W1 + N_W2 + N_WO + N_WP)

__global__ void cvt_all(const float* __restrict__ wqkv, const float* __restrict__ w1,
                        const float* __restrict__ w2, const float* __restrict__ wo,
                        const float* __restrict__ wp) {
    int i = blockIdx.x * blockDim.x + threadIdx.x;
    const float* s; __nv_bfloat16 *h, *l; int j = i;
    if (j < N_WQKV)              { s = wqkv; h = g_wqkv_h; l = g_wqkv_l; }
    else if ((j -= N_WQKV) < N_W1) { s = w1; h = g_w1_h; l = g_w1_l; }
    else if ((j -= N_W1) < N_W2)   { s = w2; h = g_w2_h; l = g_w2_l; }
    else if ((j -= N_W2) < N_WO)   { s = wo; h = g_wo_h; l = g_wo_l; }
    else if ((j -= N_WO) < N_WP)   { s = wp; h = g_wp_h; l = g_wp_l; }
    else return;
    __nv_bfloat16 a, b; hilo(s[j], a, b); h[j] = a; l[j] = b;
}

// ---------------- LayerNorm -> bf16 hi/lo (optionally fp32 copy) -----------
template <int WF32>
__global__ void ln_kernel(const float* __restrict__ in, float* __restrict__ out32,
                          __nv_bfloat16* __restrict__ oh, __nv_bfloat16* __restrict__ ol,
                          const float* __restrict__ gam, const float* __restrict__ bet) {
    int row = blockIdx.x, t = threadIdx.x;
    float4 v = ((const float4*)(in + (size_t)row * D))[t];
    float s = v.x + v.y + v.z + v.w;
    float ss = v.x * v.x + v.y * v.y + v.z * v.z + v.w * v.w;
#pragma unroll
    for (int off = 16; off; off >>= 1) {
        s  += __shfl_xor_sync(0xffffffffu, s, off);
        ss += __shfl_xor_sync(0xffffffffu, ss, off);
    }
    __shared__ float sb[4], ssb[4];
    int w = t >> 5, lane = t & 31;
    if (lane == 0) { sb[w] = s; ssb[w] = ss; }
    __syncthreads();
    s = sb[0] + sb[1] + sb[2] + sb[3];
    ss = ssb[0] + ssb[1] + ssb[2] + ssb[3];
    float mean = s * (1.0f / D);
    float inv = rsqrtf(ss * (1.0f / D) - mean * mean + 1e-5f);
    float4 g4 = ((const float4*)gam)[t];
    float4 b4 = ((const float4*)bet)[t];
    float o0 = (v.x - mean) * inv * g4.x + b4.x;
    float o1 = (v.y - mean) * inv * g4.y + b4.y;
    float o2 = (v.z - mean) * inv * g4.z + b4.z;
    float o3 = (v.w - mean) * inv * g4.w + b4.w;
    size_t base = (size_t)row * D + t * 4;
    __nv_bfloat16 h0, l0, h1, l1, h2, l2, h3, l3;
    hilo(o0, h0, l0); hilo(o1, h1, l1); hilo(o2, h2, l2); hilo(o3, h3, l3);
    __nv_bfloat162 p;
    p.x = h0; p.y = h1; *(__nv_bfloat162*)(oh + base) = p;
    p.x = h2; p.y = h3; *(__nv_bfloat162*)(oh + base + 2) = p;
    p.x = l0; p.y = l1; *(__nv_bfloat162*)(ol + base) = p;
    p.x = l2; p.y = l3; *(__nv_bfloat162*)(ol + base + 2) = p;
    if (WF32) {
        float4 o; o.x = o0; o.y = o1; o.z = o2; o.w = o3;
        ((float4*)(out32 + (size_t)row * D))[t] = o;
    }
}

// ---------------- bf16 hi/lo 3-term GEMM via mma.sync (HMMA) ----------------
#define TPITCH 80
#define TILE_B (128 * TPITCH)
#define STAGE_B (4 * TILE_B)
#define GEMM_DYN (2 * STAGE_B)

__device__ __forceinline__ void stage_load(
    uint32_t sbase, const __nv_bfloat16* Ah, const __nv_bfloat16* Al,
    const __nv_bfloat16* Wh, const __nv_bfloat16* Wl,
    int mrow, int ncol, int OUT, int K, int kt, int tid) {
#pragma unroll
    for (int i = 0; i < 2; i++) {
        int chunk = tid + i * 256;
        int r = chunk >> 2, c16 = chunk & 3;
        uint32_t so = (uint32_t)(r * TPITCH + c16 * 16);
        size_t aoff = (size_t)(mrow + r) * K + kt + c16 * 8;
        int wr = ncol + r; if (wr >= OUT) wr = OUT - 1;
        size_t woff = (size_t)wr * K + kt + c16 * 8;
        CP_ASYNC16(sbase + so,              (const char*)(Ah + aoff));
        CP_ASYNC16(sbase + TILE_B + so,     (const char*)(Al + aoff));
        CP_ASYNC16(sbase + 2 * TILE_B + so, (const char*)(Wh + woff));
        CP_ASYNC16(sbase + 3 * TILE_B + so, (const char*)(Wl + woff));
    }
}

// MODE 0: out32=v+bias ; 1: outh/l=hilo(gelu(v+bias)) ; 2: out32+=v+bias ;
// 3: outh/l=hilo(v+bias) ; 4: outh=bf16(v+bias)  (hi only)
template <int MODE>
__global__ void __launch_bounds__(256) gemm_mma(
    const __nv_bfloat16* __restrict__ Ah, const __nv_bfloat16* __restrict__ Al,
    const __nv_bfloat16* __restrict__ Wh, const __nv_bfloat16* __restrict__ Wl,
    const float* __restrict__ bias, float* __restrict__ out32,
    __nv_bfloat16* __restrict__ outh, __nv_bfloat16* __restrict__ outl,
    int OUT, int K) {
    extern __shared__ char dyn_raw[];
    const int tid = threadIdx.x, wid = tid >> 5, lane = tid & 31;
    const int mrow = blockIdx.y * 128, ncol = blockIdx.x * 128;
    const int warp_m = wid & 1, warp_n = wid >> 1;
    const int m_off = warp_m * 64, n_off = warp_n * 32;
    const int NIT = K >> 5;
    uint32_t smem0 = smem_u32(dyn_raw);

    float acc[4][4][4];
#pragma unroll
    for (int a = 0; a < 4; a++)
#pragma unroll
        for (int b = 0; b < 4; b++)
#pragma unroll
            for (int c = 0; c < 4; c++) acc[a][b][c] = 0.f;

    const uint32_t a_lm = (uint32_t)((m_off + (lane & 15)) * TPITCH + (lane & 16));
    const int bl = lane & 7, bg = (lane >> 3) & 3;
    const uint32_t b_lm = (uint32_t)((n_off + ((bg >> 1) << 3) + bl) * TPITCH + ((bg & 1) << 4));

    stage_load(smem0, Ah, Al, Wh, Wl, mrow, ncol, OUT, K, 0, tid);
    CP_COMMIT();

    for (int it = 0; it < NIT; it++) {
        if (it + 1 < NIT) {
            stage_load(smem0 + ((it + 1) & 1) * STAGE_B, Ah, Al, Wh, Wl,
                       mrow, ncol, OUT, K, (it + 1) * 32, tid);
            CP_COMMIT();
            CP_WAIT(1);
        } else {
            CP_WAIT(0);
        }
        __syncthreads();
        uint32_t sb = smem0 + (it & 1) * STAGE_B;
#pragma unroll
        for (int ks = 0; ks < 2; ks++) {
            uint32_t kb = (uint32_t)(ks * 32);
            uint32_t ah[4][4], al[4][4], bh[4][2], bl2[4][2];
#pragma unroll
            for (int mt = 0; mt < 4; mt++) {
                uint32_t ad = sb + a_lm + mt * (16 * TPITCH) + kb;
                LDSM4(ah[mt][0], ah[mt][1], ah[mt][2], ah[mt][3], ad);
                LDSM4(al[mt][0], al[mt][1], al[mt][2], al[mt][3], ad + TILE_B);
            }
#pragma unroll
            for (int np = 0; np < 2; np++) {
                uint32_t bd = sb + 2 * TILE_B + b_lm + np * (16 * TPITCH) + kb;
                LDSM4(bh[2 * np][0], bh[2 * np][1], bh[2 * np + 1][0], bh[2 * np + 1][1], bd);
                LDSM4(bl2[2 * np][0], bl2[2 * np][1], bl2[2 * np + 1][0], bl2[2 * np + 1][1], bd + TILE_B);
            }
#pragma unroll
            for (int mt = 0; mt < 4; mt++)
#pragma unroll
                for (int nt = 0; nt < 4; nt++) {
                    mma_bf16(acc[mt][nt], ah[mt], bh[nt]);
                    mma_bf16(acc[mt][nt], ah[mt], bl2[nt]);
                    mma_bf16(acc[mt][nt], al[mt], bh[nt]);
                }
        }
        __syncthreads();
    }

    const int r0 = lane >> 2, cp = (lane & 3) * 2;
#pragma unroll
    for (int mt = 0; mt < 4; mt++)
#pragma unroll
        for (int nt = 0; nt < 4; nt++) {
            int col = ncol + n_off + nt * 8 + cp;
            if (col >= OUT) continue;
            float bx = bias[col], by = bias[col + 1];
#pragma unroll
            for (int half = 0; half < 2; half++) {
                int row = mrow + m_off + mt * 16 + r0 + half * 8;
                float vx = acc[mt][nt][2 * half] + bx;
                float vy = acc[mt][nt][2 * half + 1] + by;
                size_t idx = (size_t)row * OUT + col;
                if (MODE == 0) {
                    *(float2*)(out32 + idx) = make_float2(vx, vy);
                } else if (MODE == 4) {
                    uint32_t hp; PACKBF(hp, vx, vy);
                    *(uint32_t*)(outh + idx) = hp;
                } else if (MODE == 1 || MODE == 3) {
                    if (MODE == 1) {
                        vx = 0.5f * vx * (1.0f + erff(vx * 0.70710678118654752f));
                        vy = 0.5f * vy * (1.0f + erff(vy * 0.70710678118654752f));
                    }
                    __nv_bfloat16 hx, lx, hy, ly;
                    hilo(vx, hx, lx); hilo(vy, hy, ly);
                    __nv_bfloat162 p;
                    p.x = hx; p.y = hy; *(__nv_bfloat162*)(outh + idx) = p;
                    p.x = lx; p.y = ly; *(__nv_bfloat162*)(outl + idx) = p;
                } else {
                    float2 o = *(float2*)(out32 + idx);
                    o.x += vx; o.y += vy;
                    *(float2*)(out32 + idx) = o;
                }
            }
        }
}

// ---------------- flash attention, pure bf16 (Qh Kh / Ph Vh) ----------------
// CTA = (head, 64-query block), 128 threads. All operands bf16-hi.
// Stage = Kh + Vh = 10 KB, double-buffered.
#define AP 80
#define KVT (64 * AP)
#define ASTG (2 * KVT)

__global__ void __launch_bounds__(128) attn_tc() {
    __shared__ __align__(16) char smem[2 * ASTG];
    const int tid = threadIdx.x, wid = tid >> 5, lane = tid & 31;
    const int h = blockIdx.x, qb = blockIdx.y * 64;
    const uint32_t s0 = smem_u32(smem);

    // ---- stage Q (64x32 hi) and load fragments
#pragma unroll
    for (int i = 0; i < 2; i++) {
        int idx = tid + i * 128;            // 0..255
        int r = idx >> 2, c = idx & 3;
        CP_ASYNC16(s0 + r * AP + c * 16,
                   g_qkv_h + (size_t)(qb + r) * 1536 + h * 32 + c * 8);
    }
    CP_COMMIT(); CP_WAIT(0); __syncthreads();
    uint32_t qh[2][4];
    {
        uint32_t alm = s0 + (wid * 16 + (lane & 15)) * AP + (lane & 16);
        LDSM4(qh[0][0], qh[0][1], qh[0][2], qh[0][3], alm);
        LDSM4(qh[1][0], qh[1][1], qh[1][2], qh[1][3], alm + 32);
    }
    __syncthreads();

    const int bl = lane & 7, bg = (lane >> 3) & 3;
    const uint32_t koff = (uint32_t)((((bg >> 1) * 8) + bl) * AP + ((bg & 1) * 16));
    const uint32_t voff = (uint32_t)(((((lane >> 3) & 1) * 8) + (lane & 7)) * AP + (((lane >> 4) & 1) * 16));

    float O[4][4];
#pragma unroll
    for (int a = 0; a < 4; a++)
#pragma unroll
        for (int b = 0; b < 4; b++) O[a][b] = 0.f;
    float m0 = -1e30f, m1 = -1e30f, lsum0 = 0.f, lsum1 = 0.f;
    const float sc2 = 0.25501649f;   // (1/sqrt(32)) * log2(e)

    // prologue: K/V tile 0 (tiles: 0=Kh, 1=Vh)
    {
#pragma unroll
        for (int i = 0; i < 4; i++) {
            int idx = tid + i * 128;
            int tile = idx >> 8, rem = idx & 255, r = rem >> 2, c = rem & 3;
            int col = (tile ? 1024 : 512) + h * 32;
            CP_ASYNC16(s0 + tile * KVT + r * AP + c * 16,
                       g_qkv_h + (size_t)r * 1536 + col + c * 8);
        }
        CP_COMMIT();
    }

    for (int t = 0; t < NT / 64; t++) {
        if (t + 1 < NT / 64) {
            int kb = (t + 1) * 64;
            uint32_t st = s0 + ((t + 1) & 1) * ASTG;
#pragma unroll
            for (int i = 0; i < 4; i++) {
                int idx = tid + i * 128;
                int tile = idx >> 8, rem = idx & 255, r = rem >> 2, c = rem & 3;
                int col = (tile ? 1024 : 512) + h * 32;
                CP_ASYNC16(st + tile * KVT + r * AP + c * 16,
                           g_qkv_h + (size_t)(kb + r) * 1536 + col + c * 8);
            }
            CP_COMMIT(); CP_WAIT(1);
        } else {
            CP_WAIT(0);
        }
        __syncthreads();
        uint32_t sb = s0 + (t & 1) * ASTG;

        // ---- S = Qh Kh^T
        float S[8][4];
#pragma unroll
        for (int a = 0; a < 8; a++)
#pragma unroll
            for (int b = 0; b < 4; b++) S[a][b] = 0.f;
#pragma unroll
        for (int ks = 0; ks < 2; ks++) {
            uint32_t kh[8][2];
#pragma unroll
            for (int np = 0; np < 4; np++) {
                uint32_t ad = sb + np * (16 * AP) + koff + ks * 32;
                LDSM4(kh[2 * np][0], kh[2 * np][1], kh[2 * np + 1][0], kh[2 * np + 1][1], ad);
            }
#pragma unroll
            for (int nt = 0; nt < 8; nt++)
                mma_bf16(S[nt], qh[ks], kh[nt]);
        }

        // ---- online softmax
        float t0 = -1e30f, t1 = -1e30f;
#pragma unroll
        for (int nt = 0; nt < 8; nt++) {
            t0 = fmaxf(t0, fmaxf(S[nt][0], S[nt][1]));
            t1 = fmaxf(t1, fmaxf(S[nt][2], S[nt][3]));
        }
        t0 *= sc2; t1 *= sc2;
        t0 = fmaxf(t0, __shfl_xor_sync(0xffffffffu, t0, 1));
        t0 = fmaxf(t0, __shfl_xor_sync(0xffffffffu, t0, 2));
        t1 = fmaxf(t1, __shfl_xor_sync(0xffffffffu, t1, 1));
        t1 = fmaxf(t1, __shfl_xor_sync(0xffffffffu, t1, 2));
        float mn0 = fmaxf(m0, t0), mn1 = fmaxf(m1, t1);
        float c0 = ex2f(m0 - mn0), c1 = ex2f(m1 - mn1);
        m0 = mn0; m1 = mn1;
        lsum0 *= c0; lsum1 *= c1;
#pragma unroll
        for (int nt = 0; nt < 4; nt++) {
            O[nt][0] *= c0; O[nt][1] *= c0; O[nt][2] *= c1; O[nt][3] *= c1;
        }
        uint32_t ph01[8], ph23[8];
#pragma unroll
        for (int nt = 0; nt < 8; nt++) {
            float p0 = ex2f(fmaf(S[nt][0], sc2, -m0));
            float p1 = ex2f(fmaf(S[nt][1], sc2, -m0));
            float p2 = ex2f(fmaf(S[nt][2], sc2, -m1));
            float p3 = ex2f(fmaf(S[nt][3], sc2, -m1));
            lsum0 += p0 + p1; lsum1 += p2 + p3;
            PACKBF(ph01[nt], p0, p1);
            PACKBF(ph23[nt], p2, p3);
        }

        // ---- O += Ph Vh
#pragma unroll
        for (int s = 0; s < 4; s++) {
            uint32_t aH[4] = { ph01[2 * s], ph23[2 * s], ph01[2 * s + 1], ph23[2 * s + 1] };
            uint32_t vh[4][2];
#pragma unroll
            for (int d2 = 0; d2 < 2; d2++) {
                uint32_t ad = sb + KVT + s * (16 * AP) + voff + d2 * 32;
                LDSM4T(vh[2 * d2][0], vh[2 * d2][1], vh[2 * d2 + 1][0], vh[2 * d2 + 1][1], ad);
            }
#pragma unroll
            for (int nt = 0; nt < 4; nt++)
                mma_bf16(O[nt], aH, vh[nt]);
        }
        __syncthreads();
    }

    // ---- epilogue (ao written as hi/lo for the 3-term wo GEMM)
    lsum0 += __shfl_xor_sync(0xffffffffu, lsum0, 1);
    lsum0 += __shfl_xor_sync(0xffffffffu, lsum0, 2);
    lsum1 += __shfl_xor_sync(0xffffffffu, lsum1, 1);
    lsum1 += __shfl_xor_sync(0xffffffffu, lsum1, 2);
    float i0 = 1.f / lsum0, i1 = 1.f / lsum1;
    int r0 = qb + wid * 16 + (lane >> 2), r1 = r0 + 8;
    int colb = h * 32 + (lane & 3) * 2;
#pragma unroll
    for (int nt = 0; nt < 4; nt++) {
        int col = colb + nt * 8;
        float v0 = O[nt][0] * i0, v1 = O[nt][1] * i0;
        float v2 = O[nt][2] * i1, v3 = O[nt][3] * i1;
        uint32_t hp, lp;
        PACKBF(hp, v0, v1);
        float h0f = __uint_as_float(hp << 16), h1f = __uint_as_float(hp & 0xffff0000u);
        PACKBF(lp, v0 - h0f, v1 - h1f);
        *(uint32_t*)(g_ao_h + (size_t)r0 * D + col) = hp;
        *(uint32_t*)(g_ao_l + (size_t)r0 * D + col) = lp;
        PACKBF(hp, v2, v3);
        h0f = __uint_as_float(hp << 16); h1f = __uint_as_float(hp & 0xffff0000u);
        PACKBF(lp, v2 - h0f, v3 - h1f);
        *(uint32_t*)(g_ao_h + (size_t)r1 * D + col) = hp;
        *(uint32_t*)(g_ao_l + (size_t)r1 * D + col) = lp;
    }
}

// ---------------- conv path (scatter, then fused conv+gather) --------------
__global__ void scatter_kernel(const int* __restrict__ coords) {
    int idx = blockIdx.x * blockDim.x + threadIdx.x;
    int n = idx >> 7, d4 = idx & 127;
    int rr = coords[2 * n], cc = coords[2 * n + 1];
    ((float4*)g_grid)[(size_t)(rr * GW + cc) * 128 + d4] =
        ((const float4*)g_x)[(size_t)n * 128 + d4];
}
__global__ void convgather_kernel(const int* __restrict__ coords,
                                  const float* __restrict__ ck,
                                  const float* __restrict__ cb) {
    int idx = blockIdx.x * blockDim.x + threadIdx.x;
    int n = idx >> 9, d = idx & (D - 1);
    int r = coords[2 * n], c = coords[2 * n + 1];
    float acc = cb[d];
#pragma unroll
    for (int kh = 0; kh < 3; kh++) {
        int rr = r + kh - 1;
        if ((unsigned)rr >= GH) continue;
#pragma unroll
        for (int kw = 0; kw < 3; kw++) {
            int cc = c + kw - 1;
            if ((unsigned)cc >= GW) continue;
            acc += ck[d * 9 + kh * 3 + kw] * g_grid[(size_t)(rr * GW + cc) * D + d];
        }
    }
    g_x[idx] += acc;
}

// ---------------- host ----------------
extern "C" void kernel_launch(void* const* d_in, const int* in_sizes, int n_in,
                              void* d_out, int out_size) {
    const float* gf     = (const float*)d_in[0];
    const int*   coords = (const int*)d_in[1];
    int wi = (n_in >= 22) ? 4 : 2;
    const float* ln1_g = (const float*)d_in[wi + 0];
    const float* ln1_b = (const float*)d_in[wi + 1];
    const float* wqkv  = (const float*)d_in[wi + 2];
    const float* bqkv  = (const float*)d_in[wi + 3];
    const float* wo    = (const float*)d_in[wi + 4];
    const float* bo    = (const float*)d_in[wi + 5];
    const float* ln2_g = (const float*)d_in[wi + 6];
    const float* ln2_b = (const float*)d_in[wi + 7];
    const float* w1    = (const float*)d_in[wi + 8];
    const float* b1    = (const float*)d_in[wi + 9];
    const float* w2    = (const float*)d_in[wi + 10];
    const float* b2    = (const float*)d_in[wi + 11];
    const float* ck    = (const float*)d_in[wi + 12];
    const float* cb    = (const float*)d_in[wi + 13];
    const float* lnf_g = (const float*)d_in[wi + 14];
    const float* lnf_b = (const float*)d_in[wi + 15];
    const float* wp    = (const float*)d_in[wi + 16];
    const float* bp    = (const float*)d_in[wi + 17];

    float* out_x    = (float*)d_out;
    float* out_pred = out_x + (size_t)NT * D;

    static float* px = nullptr;
    static __nv_bfloat16 *pqh, *pxnh, *pxnl, *paoh, *paol, *phh, *phl, *pxfh, *pxfl;
    static __nv_bfloat16 *pWqh, *pWql, *pWoh, *pWol, *pW1h, *pW1l, *pW2h, *pW2l, *pWph, *pWpl;
    if (!px) {
        cudaGetSymbolAddress((void**)&px, g_x);
        cudaGetSymbolAddress((void**)&pqh, g_qkv_h);
        cudaGetSymbolAddress((void**)&pxnh, g_xn_h);  cudaGetSymbolAddress((void**)&pxnl, g_xn_l);
        cudaGetSymbolAddress((void**)&paoh, g_ao_h);  cudaGetSymbolAddress((void**)&paol, g_ao_l);
        cudaGetSymbolAddress((void**)&phh, g_hh);     cudaGetSymbolAddress((void**)&phl, g_hl);
        cudaGetSymbolAddress((void**)&pxfh, g_xf_h);  cudaGetSymbolAddress((void**)&pxfl, g_xf_l);
        cudaGetSymbolAddress((void**)&pWqh, g_wqkv_h); cudaGetSymbolAddress((void**)&pWql, g_wqkv_l);
        cudaGetSymbolAddress((void**)&pWoh, g_wo_h);   cudaGetSymbolAddress((void**)&pWol, g_wo_l);
        cudaGetSymbolAddress((void**)&pW1h, g_w1_h);   cudaGetSymbolAddress((void**)&pW1l, g_w1_l);
        cudaGetSymbolAddress((void**)&pW2h, g_w2_h);   cudaGetSymbolAddress((void**)&pW2l, g_w2_l);
        cudaGetSymbolAddress((void**)&pWph, g_wp_h);   cudaGetSymbolAddress((void**)&pWpl, g_wp_l);
        cudaFuncSetAttribute(gemm_mma<0>, cudaFuncAttributeMaxDynamicSharedMemorySize, GEMM_DYN);
        cudaFuncSetAttribute(gemm_mma<1>, cudaFuncAttributeMaxDynamicSharedMemorySize, GEMM_DYN);
        cudaFuncSetAttribute(gemm_mma<2>, cudaFuncAttributeMaxDynamicSharedMemorySize, GEMM_DYN);
        cudaFuncSetAttribute(gemm_mma<4>, cudaFuncAttributeMaxDynamicSharedMemorySize, GEMM_DYN);
    }

    cudaMemcpyAsync(px, gf, (size_t)NT * D * sizeof(float), cudaMemcpyDeviceToDevice);

    cvt_all<<<(N_CVT + 255) / 256, 256>>>(wqkv, w1, w2, wo, wp);

    for (int i = 0; i < DEPTH; i++) {
        ln_kernel<0><<<NT, 128>>>(px, nullptr, pxnh, pxnl, ln1_g + i * D, ln1_b + i * D);
        gemm_mma<4><<<dim3(12, 32), 256, GEMM_DYN>>>(
            pxnh, pxnl, pWqh + (size_t)i * 3 * D * D, pWql + (size_t)i * 3 * D * D,
            bqkv + i * 3 * D, nullptr, pqh, nullptr, 3 * D, D);
        attn_tc<<<dim3(NHD, NT / 64), 128>>>();
        gemm_mma<2><<<dim3(4, 32), 256, GEMM_DYN>>>(
            paoh, paol, pWoh + (size_t)i * D * D, pWol + (size_t)i * D * D,
            bo + i * D, px, nullptr, nullptr, D, D);
        ln_kernel<0><<<NT, 128>>>(px, nullptr, pxnh, pxnl, ln2_g + i * D, ln2_b + i * D);
        gemm_mma<1><<<dim3(16, 32), 256, GEMM_DYN>>>(
            pxnh, pxnl, pW1h + (size_t)i * DMLP * D, pW1l + (size_t)i * DMLP * D,
            b1 + i * DMLP, nullptr, phh, phl, DMLP, D);
        gemm_mma<2><<<dim3(4, 32), 256, GEMM_DYN>>>(
            phh, phl, pW2h + (size_t)i * D * DMLP, pW2l + (size_t)i * D * DMLP,
            b2 + i * D, px, nullptr, nullptr, D, DMLP);
        scatter_kernel<<<NT * (D / 4) / 256, 256>>>(coords);
        convgather_kernel<<<NT * D / 256, 256>>>(coords, ck + (size_t)i * D * 9, cb + i * D);
    }
    ln_kernel<1><<<NT, 128>>>(px, out_x, pxfh, pxfl, lnf_g, lnf_b);
    gemm_mma<0><<<dim3(2, 32), 256, GEMM_DYN>>>(
        pxfh, pxfl, pWph, pWpl, bp, out_pred, nullptr, nullptr, GENES, D);
}

// round 10
// speedup vs baseline: 1.6983x; 1.2203x over previous
#include <cuda_runtime.h>
#include <cuda_bf16.h>
#include <math.h>
#include <stdint.h>

#define NT    4096
#define D     512
#define NHD   16
#define DH    32
#define DEPTH 3
#define DMLP  2048
#define GENES 250
#define GH    64
#define GW    64

// ---------------- PTX helpers ----------------
__device__ __forceinline__ uint32_t smem_u32(const void* p) {
    uint32_t a;
    asm("{ .reg .u64 t; cvta.to.shared.u64 t, %1; cvt.u32.u64 %0, t; }" : "=r"(a) : "l"(p));
    return a;
}
#define CP_ASYNC16(sa, ga) \
    asm volatile("cp.async.cg.shared.global [%0], [%1], 16;" :: "r"(sa), "l"(ga))
#define CP_COMMIT() asm volatile("cp.async.commit_group;")
#define CP_WAIT(n)  asm volatile("cp.async.wait_group %0;" :: "n"(n))

#define LDSM4(r0, r1, r2, r3, addr) \
    asm volatile("ldmatrix.sync.aligned.m8n8.x4.shared.b16 {%0,%1,%2,%3}, [%4];" \
        : "=r"(r0), "=r"(r1), "=r"(r2), "=r"(r3) : "r"(addr))
#define LDSM4T(r0, r1, r2, r3, addr) \
    asm volatile("ldmatrix.sync.aligned.m8n8.x4.trans.shared.b16 {%0,%1,%2,%3}, [%4];" \
        : "=r"(r0), "=r"(r1), "=r"(r2), "=r"(r3) : "r"(addr))

__device__ __forceinline__ void mma_bf16(float* d, const uint32_t* a, const uint32_t* b) {
    asm volatile("mma.sync.aligned.m16n8k16.row.col.f32.bf16.bf16.f32 "
        "{%0,%1,%2,%3}, {%4,%5,%6,%7}, {%8,%9}, {%0,%1,%2,%3};"
        : "+f"(d[0]), "+f"(d[1]), "+f"(d[2]), "+f"(d[3])
        : "r"(a[0]), "r"(a[1]), "r"(a[2]), "r"(a[3]), "r"(b[0]), "r"(b[1]));
}

#define PACKBF(d, lo, hi) \
    asm("cvt.rn.bf16x2.f32 %0, %1, %2;" : "=r"(d) : "f"(hi), "f"(lo))

__device__ __forceinline__ float ex2f(float x) {
    float y; asm("ex2.approx.f32 %0, %1;" : "=f"(y) : "f"(x)); return y;
}

__device__ __forceinline__ void hilo(float v, __nv_bfloat16& h, __nv_bfloat16& l) {
    h = __float2bfloat16(v);
    l = __float2bfloat16(v - __bfloat162float(h));
}

// ---------------- device scratch ----------------
__device__ float g_x[NT * D];
__device__ float g_grid[GH * GW * D];
__device__ __nv_bfloat16 g_qkv_h[NT * 3 * D];
__device__ __nv_bfloat16 g_xn_h[NT * D],  g_xn_l[NT * D];
__device__ __nv_bfloat16 g_ao_h[NT * D],  g_ao_l[NT * D];
__device__ __nv_bfloat16 g_hh[NT * DMLP];
__device__ __nv_bfloat16 g_xf_h[NT * D],  g_xf_l[NT * D];
__device__ __nv_bfloat16 g_wqkv_h[DEPTH * 3 * D * D], g_wqkv_l[DEPTH * 3 * D * D];
__device__ __nv_bfloat16 g_wo_h[DEPTH * D * D],       g_wo_l[DEPTH * D * D];
__device__ __nv_bfloat16 g_w1_h[DEPTH * DMLP * D],    g_w1_l[DEPTH * DMLP * D];
__device__ __nv_bfloat16 g_w2_h[DEPTH * D * DMLP],    g_w2_l[DEPTH * D * DMLP];
__device__ __nv_bfloat16 g_wp_h[GENES * D],           g_wp_l[GENES * D];

// ---- one merged weight-conversion kernel ----
#define N_WQKV (DEPTH * 3 * D * D)
#define N_W1   (DEPTH * DMLP * D)
#define N_W2   (DEPTH * D * DMLP)
#define N_WO   (DEPTH * D * D)
#define N_WP   (GENES * D)
#define N_CVT  (N_WQKV + N_W1 + N_W2 + N_WO + N_WP)

__global__ void cvt_all(const float* __restrict__ wqkv, const float* __restrict__ w1,
                        const float* __restrict__ w2, const float* __restrict__ wo,
                        const float* __restrict__ wp) {
    int i = blockIdx.x * blockDim.x + threadIdx.x;
    const float* s; __nv_bfloat16 *h, *l; int j = i;
    if (j < N_WQKV)              { s = wqkv; h = g_wqkv_h; l = g_wqkv_l; }
    else if ((j -= N_WQKV) < N_W1) { s = w1; h = g_w1_h; l = g_w1_l; }
    else if ((j -= N_W1) < N_W2)   { s = w2; h = g_w2_h; l = g_w2_l; }
    else if ((j -= N_W2) < N_WO)   { s = wo; h = g_wo_h; l = g_wo_l; }
    else if ((j -= N_WO) < N_WP)   { s = wp; h = g_wp_h; l = g_wp_l; }
    else return;
    __nv_bfloat16 a, b; hilo(s[j], a, b); h[j] = a; l[j] = b;
}

// ---------------- LayerNorm -> bf16 hi/lo (optionally fp32 copy) -----------
template <int WF32>
__global__ void ln_kernel(const float* __restrict__ in, float* __restrict__ out32,
                          __nv_bfloat16* __restrict__ oh, __nv_bfloat16* __restrict__ ol,
                          const float* __restrict__ gam, const float* __restrict__ bet) {
    int row = blockIdx.x, t = threadIdx.x;
    float4 v = ((const float4*)(in + (size_t)row * D))[t];
    float s = v.x + v.y + v.z + v.w;
    float ss = v.x * v.x + v.y * v.y + v.z * v.z + v.w * v.w;
#pragma unroll
    for (int off = 16; off; off >>= 1) {
        s  += __shfl_xor_sync(0xffffffffu, s, off);
        ss += __shfl_xor_sync(0xffffffffu, ss, off);
    }
    __shared__ float sb[4], ssb[4];
    int w = t >> 5, lane = t & 31;
    if (lane == 0) { sb[w] = s; ssb[w] = ss; }
    __syncthreads();
    s = sb[0] + sb[1] + sb[2] + sb[3];
    ss = ssb[0] + ssb[1] + ssb[2] + ssb[3];
    float mean = s * (1.0f / D);
    float inv = rsqrtf(ss * (1.0f / D) - mean * mean + 1e-5f);
    float4 g4 = ((const float4*)gam)[t];
    float4 b4 = ((const float4*)bet)[t];
    float o0 = (v.x - mean) * inv * g4.x + b4.x;
    float o1 = (v.y - mean) * inv * g4.y + b4.y;
    float o2 = (v.z - mean) * inv * g4.z + b4.z;
    float o3 = (v.w - mean) * inv * g4.w + b4.w;
    size_t base = (size_t)row * D + t * 4;
    __nv_bfloat16 h0, l0, h1, l1, h2, l2, h3, l3;
    hilo(o0, h0, l0); hilo(o1, h1, l1); hilo(o2, h2, l2); hilo(o3, h3, l3);
    __nv_bfloat162 p;
    p.x = h0; p.y = h1; *(__nv_bfloat162*)(oh + base) = p;
    p.x = h2; p.y = h3; *(__nv_bfloat162*)(oh + base + 2) = p;
    p.x = l0; p.y = l1; *(__nv_bfloat162*)(ol + base) = p;
    p.x = l2; p.y = l3; *(__nv_bfloat162*)(ol + base + 2) = p;
    if (WF32) {
        float4 o; o.x = o0; o.y = o1; o.z = o2; o.w = o3;
        ((float4*)(out32 + (size_t)row * D))[t] = o;
    }
}

// ---------------- bf16 hi/lo GEMM via mma.sync (HMMA) ----------------------
// TERMS=3: Ah*Wh + Ah*Wl + Al*Wh   TERMS=2: Ah*Wh + Ah*Wl (A truncated)
#define TPITCH 80
#define TILE_B (128 * TPITCH)
#define STAGE_B (4 * TILE_B)
#define GEMM_DYN (2 * STAGE_B)

template <int TERMS>
__device__ __forceinline__ void stage_load(
    uint32_t sbase, const __nv_bfloat16* Ah, const __nv_bfloat16* Al,
    const __nv_bfloat16* Wh, const __nv_bfloat16* Wl,
    int mrow, int ncol, int OUT, int K, int kt, int tid) {
#pragma unroll
    for (int i = 0; i < 2; i++) {
        int chunk = tid + i * 256;
        int r = chunk >> 2, c16 = chunk & 3;
        uint32_t so = (uint32_t)(r * TPITCH + c16 * 16);
        size_t aoff = (size_t)(mrow + r) * K + kt + c16 * 8;
        int wr = ncol + r; if (wr >= OUT) wr = OUT - 1;
        size_t woff = (size_t)wr * K + kt + c16 * 8;
        CP_ASYNC16(sbase + so,              (const char*)(Ah + aoff));
        if (TERMS == 3)
            CP_ASYNC16(sbase + TILE_B + so, (const char*)(Al + aoff));
        CP_ASYNC16(sbase + 2 * TILE_B + so, (const char*)(Wh + woff));
        CP_ASYNC16(sbase + 3 * TILE_B + so, (const char*)(Wl + woff));
    }
}

// MODE 0: out32=v+bias ; 1: outh/l=hilo(gelu(v+bias)) ; 2: out32+=v+bias ;
// 4: outh=bf16(v+bias) ; 5: outh=bf16(gelu(v+bias))
template <int MODE, int TERMS>
__global__ void __launch_bounds__(256) gemm_mma(
    const __nv_bfloat16* __restrict__ Ah, const __nv_bfloat16* __restrict__ Al,
    const __nv_bfloat16* __restrict__ Wh, const __nv_bfloat16* __restrict__ Wl,
    const float* __restrict__ bias, float* __restrict__ out32,
    __nv_bfloat16* __restrict__ outh, __nv_bfloat16* __restrict__ outl,
    int OUT, int K) {
    extern __shared__ char dyn_raw[];
    const int tid = threadIdx.x, wid = tid >> 5, lane = tid & 31;
    const int mrow = blockIdx.y * 128, ncol = blockIdx.x * 128;
    const int warp_m = wid & 1, warp_n = wid >> 1;
    const int m_off = warp_m * 64, n_off = warp_n * 32;
    const int NIT = K >> 5;
    uint32_t smem0 = smem_u32(dyn_raw);

    float acc[4][4][4];
#pragma unroll
    for (int a = 0; a < 4; a++)
#pragma unroll
        for (int b = 0; b < 4; b++)
#pragma unroll
            for (int c = 0; c < 4; c++) acc[a][b][c] = 0.f;

    const uint32_t a_lm = (uint32_t)((m_off + (lane & 15)) * TPITCH + (lane & 16));
    const int bl = lane & 7, bg = (lane >> 3) & 3;
    const uint32_t b_lm = (uint32_t)((n_off + ((bg >> 1) << 3) + bl) * TPITCH + ((bg & 1) << 4));

    stage_load<TERMS>(smem0, Ah, Al, Wh, Wl, mrow, ncol, OUT, K, 0, tid);
    CP_COMMIT();

    for (int it = 0; it < NIT; it++) {
        if (it + 1 < NIT) {
            stage_load<TERMS>(smem0 + ((it + 1) & 1) * STAGE_B, Ah, Al, Wh, Wl,
                              mrow, ncol, OUT, K, (it + 1) * 32, tid);
            CP_COMMIT();
            CP_WAIT(1);
        } else {
            CP_WAIT(0);
        }
        __syncthreads();
        uint32_t sb = smem0 + (it & 1) * STAGE_B;
#pragma unroll
        for (int ks = 0; ks < 2; ks++) {
            uint32_t kb = (uint32_t)(ks * 32);
            uint32_t ah[4][4], al[4][4], bh[4][2], bl2[4][2];
#pragma unroll
            for (int mt = 0; mt < 4; mt++) {
                uint32_t ad = sb + a_lm + mt * (16 * TPITCH) + kb;
                LDSM4(ah[mt][0], ah[mt][1], ah[mt][2], ah[mt][3], ad);
                if (TERMS == 3)
                    LDSM4(al[mt][0], al[mt][1], al[mt][2], al[mt][3], ad + TILE_B);
            }
#pragma unroll
            for (int np = 0; np < 2; np++) {
                uint32_t bd = sb + 2 * TILE_B + b_lm + np * (16 * TPITCH) + kb;
                LDSM4(bh[2 * np][0], bh[2 * np][1], bh[2 * np + 1][0], bh[2 * np + 1][1], bd);
                LDSM4(bl2[2 * np][0], bl2[2 * np][1], bl2[2 * np + 1][0], bl2[2 * np + 1][1], bd + TILE_B);
            }
#pragma unroll
            for (int mt = 0; mt < 4; mt++)
#pragma unroll
                for (int nt = 0; nt < 4; nt++) {
                    mma_bf16(acc[mt][nt], ah[mt], bh[nt]);
                    mma_bf16(acc[mt][nt], ah[mt], bl2[nt]);
                    if (TERMS == 3)
                        mma_bf16(acc[mt][nt], al[mt], bh[nt]);
                }
        }
        __syncthreads();
    }

    const int r0 = lane >> 2, cp = (lane & 3) * 2;
#pragma unroll
    for (int mt = 0; mt < 4; mt++)
#pragma unroll
        for (int nt = 0; nt < 4; nt++) {
            int col = ncol + n_off + nt * 8 + cp;
            if (col >= OUT) continue;
            float bx = bias[col], by = bias[col + 1];
#pragma unroll
            for (int half = 0; half < 2; half++) {
                int row = mrow + m_off + mt * 16 + r0 + half * 8;
                float vx = acc[mt][nt][2 * half] + bx;
                float vy = acc[mt][nt][2 * half + 1] + by;
                size_t idx = (size_t)row * OUT + col;
                if (MODE == 0) {
                    *(float2*)(out32 + idx) = make_float2(vx, vy);
                } else if (MODE == 4 || MODE == 5) {
                    if (MODE == 5) {
                        vx = 0.5f * vx * (1.0f + erff(vx * 0.70710678118654752f));
                        vy = 0.5f * vy * (1.0f + erff(vy * 0.70710678118654752f));
                    }
                    uint32_t hp; PACKBF(hp, vx, vy);
                    *(uint32_t*)(outh + idx) = hp;
                } else if (MODE == 1) {
                    vx = 0.5f * vx * (1.0f + erff(vx * 0.70710678118654752f));
                    vy = 0.5f * vy * (1.0f + erff(vy * 0.70710678118654752f));
                    __nv_bfloat16 hx, lx, hy, ly;
                    hilo(vx, hx, lx); hilo(vy, hy, ly);
                    __nv_bfloat162 p;
                    p.x = hx; p.y = hy; *(__nv_bfloat162*)(outh + idx) = p;
                    p.x = lx; p.y = ly; *(__nv_bfloat162*)(outl + idx) = p;
                } else {
                    float2 o = *(float2*)(out32 + idx);
                    o.x += vx; o.y += vy;
                    *(float2*)(out32 + idx) = o;
                }
            }
        }
}

// ---------------- flash attention, pure bf16, max-free softmax --------------
// CTA = (head, 64-query block), 128 threads. Scores bounded -> exp without
// running max (softmax is shift-invariant; fp32 range is ample).
#define AP 80
#define KVT (64 * AP)
#define ASTG (2 * KVT)

__global__ void __launch_bounds__(128) attn_tc() {
    __shared__ __align__(16) char smem[2 * ASTG];
    const int tid = threadIdx.x, wid = tid >> 5, lane = tid & 31;
    const int h = blockIdx.x, qb = blockIdx.y * 64;
    const uint32_t s0 = smem_u32(smem);

    // ---- stage Q (64x32 hi) and load fragments
#pragma unroll
    for (int i = 0; i < 2; i++) {
        int idx = tid + i * 128;
        int r = idx >> 2, c = idx & 3;
        CP_ASYNC16(s0 + r * AP + c * 16,
                   g_qkv_h + (size_t)(qb + r) * 1536 + h * 32 + c * 8);
    }
    CP_COMMIT(); CP_WAIT(0); __syncthreads();
    uint32_t qh[2][4];
    {
        uint32_t alm = s0 + (wid * 16 + (lane & 15)) * AP + (lane & 16);
        LDSM4(qh[0][0], qh[0][1], qh[0][2], qh[0][3], alm);
        LDSM4(qh[1][0], qh[1][1], qh[1][2], qh[1][3], alm + 32);
    }
    __syncthreads();

    const int bl = lane & 7, bg = (lane >> 3) & 3;
    const uint32_t koff = (uint32_t)((((bg >> 1) * 8) + bl) * AP + ((bg & 1) * 16));
    const uint32_t voff = (uint32_t)(((((lane >> 3) & 1) * 8) + (lane & 7)) * AP + (((lane >> 4) & 1) * 16));

    float O[4][4];
#pragma unroll
    for (int a = 0; a < 4; a++)
#pragma unroll
        for (int b = 0; b < 4; b++) O[a][b] = 0.f;
    float lsum0 = 0.f, lsum1 = 0.f;
    const float sc2 = 0.25501649f;   // (1/sqrt(32)) * log2(e)

    // prologue: K/V tile 0 (tiles: 0=Kh, 1=Vh)
    {
#pragma unroll
        for (int i = 0; i < 4; i++) {
            int idx = tid + i * 128;
            int tile = idx >> 8, rem = idx & 255, r = rem >> 2, c = rem & 3;
            int col = (tile ? 1024 : 512) + h * 32;
            CP_ASYNC16(s0 + tile * KVT + r * AP + c * 16,
                       g_qkv_h + (size_t)r * 1536 + col + c * 8);
        }
        CP_COMMIT();
    }

    for (int t = 0; t < NT / 64; t++) {
        if (t + 1 < NT / 64) {
            int kb = (t + 1) * 64;
            uint32_t st = s0 + ((t + 1) & 1) * ASTG;
#pragma unroll
            for (int i = 0; i < 4; i++) {
                int idx = tid + i * 128;
                int tile = idx >> 8, rem = idx & 255, r = rem >> 2, c = rem & 3;
                int col = (tile ? 1024 : 512) + h * 32;
                CP_ASYNC16(st + tile * KVT + r * AP + c * 16,
                           g_qkv_h + (size_t)(kb + r) * 1536 + col + c * 8);
            }
            CP_COMMIT(); CP_WAIT(1);
        } else {
            CP_WAIT(0);
        }
        __syncthreads();
        uint32_t sb = s0 + (t & 1) * ASTG;

        // ---- S = Qh Kh^T
        float S[8][4];
#pragma unroll
        for (int a = 0; a < 8; a++)
#pragma unroll
            for (int b = 0; b < 4; b++) S[a][b] = 0.f;
#pragma unroll
        for (int ks = 0; ks < 2; ks++) {
            uint32_t kh[8][2];
#pragma unroll
            for (int np = 0; np < 4; np++) {
                uint32_t ad = sb + np * (16 * AP) + koff + ks * 32;
                LDSM4(kh[2 * np][0], kh[2 * np][1], kh[2 * np + 1][0], kh[2 * np + 1][1], ad);
            }
#pragma unroll
            for (int nt = 0; nt < 8; nt++)
                mma_bf16(S[nt], qh[ks], kh[nt]);
        }

        // ---- unnormalized exp (no max subtraction)
        uint32_t ph01[8], ph23[8];
#pragma unroll
        for (int nt = 0; nt < 8; nt++) {
            float p0 = ex2f(S[nt][0] * sc2);
            float p1 = ex2f(S[nt][1] * sc2);
            float p2 = ex2f(S[nt][2] * sc2);
            float p3 = ex2f(S[nt][3] * sc2);
            lsum0 += p0 + p1; lsum1 += p2 + p3;
            PACKBF(ph01[nt], p0, p1);
            PACKBF(ph23[nt], p2, p3);
        }

        // ---- O += Ph Vh
#pragma unroll
        for (int s = 0; s < 4; s++) {
            uint32_t aH[4] = { ph01[2 * s], ph23[2 * s], ph01[2 * s + 1], ph23[2 * s + 1] };
            uint32_t vh[4][2];
#pragma unroll
            for (int d2 = 0; d2 < 2; d2++) {
                uint32_t ad = sb + KVT + s * (16 * AP) + voff + d2 * 32;
                LDSM4T(vh[2 * d2][0], vh[2 * d2][1], vh[2 * d2 + 1][0], vh[2 * d2 + 1][1], ad);
            }
#pragma unroll
            for (int nt = 0; nt < 4; nt++)
                mma_bf16(O[nt], aH, vh[nt]);
        }
        __syncthreads();
    }

    // ---- epilogue (ao written as hi/lo for the 3-term wo GEMM)
    lsum0 += __shfl_xor_sync(0xffffffffu, lsum0, 1);
    lsum0 += __shfl_xor_sync(0xffffffffu, lsum0, 2);
    lsum1 += __shfl_xor_sync(0xffffffffu, lsum1, 1);
    lsum1 += __shfl_xor_sync(0xffffffffu, lsum1, 2);
    float i0 = 1.f / lsum0, i1 = 1.f / lsum1;
    int r0 = qb + wid * 16 + (lane >> 2), r1 = r0 + 8;
    int colb = h * 32 + (lane & 3) * 2;
#pragma unroll
    for (int nt = 0; nt < 4; nt++) {
        int col = colb + nt * 8;
        float v0 = O[nt][0] * i0, v1 = O[nt][1] * i0;
        float v2 = O[nt][2] * i1, v3 = O[nt][3] * i1;
        uint32_t hp, lp;
        PACKBF(hp, v0, v1);
        float h0f = __uint_as_float(hp << 16), h1f = __uint_as_float(hp & 0xffff0000u);
        PACKBF(lp, v0 - h0f, v1 - h1f);
        *(uint32_t*)(g_ao_h + (size_t)r0 * D + col) = hp;
        *(uint32_t*)(g_ao_l + (size_t)r0 * D + col) = lp;
        PACKBF(hp, v2, v3);
        h0f = __uint_as_float(hp << 16); h1f = __uint_as_float(hp & 0xffff0000u);
        PACKBF(lp, v2 - h0f, v3 - h1f);
        *(uint32_t*)(g_ao_h + (size_t)r1 * D + col) = hp;
        *(uint32_t*)(g_ao_l + (size_t)r1 * D + col) = lp;
    }
}

// ---------------- conv path (scatter, then fused conv+gather) --------------
__global__ void scatter_kernel(const int* __restrict__ coords) {
    int idx = blockIdx.x * blockDim.x + threadIdx.x;
    int n = idx >> 7, d4 = idx & 127;
    int rr = coords[2 * n], cc = coords[2 * n + 1];
    ((float4*)g_grid)[(size_t)(rr * GW + cc) * 128 + d4] =
        ((const float4*)g_x)[(size_t)n * 128 + d4];
}
__global__ void convgather_kernel(const int* __restrict__ coords,
                                  const float* __restrict__ ck,
                                  const float* __restrict__ cb) {
    int idx = blockIdx.x * blockDim.x + threadIdx.x;
    int n = idx >> 9, d = idx & (D - 1);
    int r = coords[2 * n], c = coords[2 * n + 1];
    float acc = cb[d];
#pragma unroll
    for (int kh = 0; kh < 3; kh++) {
        int rr = r + kh - 1;
        if ((unsigned)rr >= GH) continue;
#pragma unroll
        for (int kw = 0; kw < 3; kw++) {
            int cc = c + kw - 1;
            if ((unsigned)cc >= GW) continue;
            acc += ck[d * 9 + kh * 3 + kw] * g_grid[(size_t)(rr * GW + cc) * D + d];
        }
    }
    g_x[idx] += acc;
}

// ---------------- host ----------------
extern "C" void kernel_launch(void* const* d_in, const int* in_sizes, int n_in,
                              void* d_out, int out_size) {
    const float* gf     = (const float*)d_in[0];
    const int*   coords = (const int*)d_in[1];
    int wi = (n_in >= 22) ? 4 : 2;
    const float* ln1_g = (const float*)d_in[wi + 0];
    const float* ln1_b = (const float*)d_in[wi + 1];
    const float* wqkv  = (const float*)d_in[wi + 2];
    const float* bqkv  = (const float*)d_in[wi + 3];
    const float* wo    = (const float*)d_in[wi + 4];
    const float* bo    = (const float*)d_in[wi + 5];
    const float* ln2_g = (const float*)d_in[wi + 6];
    const float* ln2_b = (const float*)d_in[wi + 7];
    const float* w1    = (const float*)d_in[wi + 8];
    const float* b1    = (const float*)d_in[wi + 9];
    const float* w2    = (const float*)d_in[wi + 10];
    const float* b2    = (const float*)d_in[wi + 11];
    const float* ck    = (const float*)d_in[wi + 12];
    const float* cb    = (const float*)d_in[wi + 13];
    const float* lnf_g = (const float*)d_in[wi + 14];
    const float* lnf_b = (const float*)d_in[wi + 15];
    const float* wp    = (const float*)d_in[wi + 16];
    const float* bp    = (const float*)d_in[wi + 17];

    float* out_x    = (float*)d_out;
    float* out_pred = out_x + (size_t)NT * D;

    static float* px = nullptr;
    static __nv_bfloat16 *pqh, *pxnh, *pxnl, *paoh, *paol, *phh, *pxfh, *pxfl;
    static __nv_bfloat16 *pWqh, *pWql, *pWoh, *pWol, *pW1h, *pW1l, *pW2h, *pW2l, *pWph, *pWpl;
    if (!px) {
        cudaGetSymbolAddress((void**)&px, g_x);
        cudaGetSymbolAddress((void**)&pqh, g_qkv_h);
        cudaGetSymbolAddress((void**)&pxnh, g_xn_h);  cudaGetSymbolAddress((void**)&pxnl, g_xn_l);
        cudaGetSymbolAddress((void**)&paoh, g_ao_h);  cudaGetSymbolAddress((void**)&paol, g_ao_l);
        cudaGetSymbolAddress((void**)&phh, g_hh);
        cudaGetSymbolAddress((void**)&pxfh, g_xf_h);  cudaGetSymbolAddress((void**)&pxfl, g_xf_l);
        cudaGetSymbolAddress((void**)&pWqh, g_wqkv_h); cudaGetSymbolAddress((void**)&pWql, g_wqkv_l);
        cudaGetSymbolAddress((void**)&pWoh, g_wo_h);   cudaGetSymbolAddress((void**)&pWol, g_wo_l);
        cudaGetSymbolAddress((void**)&pW1h, g_w1_h);   cudaGetSymbolAddress((void**)&pW1l, g_w1_l);
        cudaGetSymbolAddress((void**)&pW2h, g_w2_h);   cudaGetSymbolAddress((void**)&pW2l, g_w2_l);
        cudaGetSymbolAddress((void**)&pWph, g_wp_h);   cudaGetSymbolAddress((void**)&pWpl, g_wp_l);
        cudaFuncSetAttribute((const void*)gemm_mma<0, 3>, cudaFuncAttributeMaxDynamicSharedMemorySize, GEMM_DYN);
        cudaFuncSetAttribute((const void*)gemm_mma<2, 3>, cudaFuncAttributeMaxDynamicSharedMemorySize, GEMM_DYN);
        cudaFuncSetAttribute((const void*)gemm_mma<4, 3>, cudaFuncAttributeMaxDynamicSharedMemorySize, GEMM_DYN);
        cudaFuncSetAttribute((const void*)gemm_mma<5, 2>, cudaFuncAttributeMaxDynamicSharedMemorySize, GEMM_DYN);
        cudaFuncSetAttribute((const void*)gemm_mma<2, 2>, cudaFuncAttributeMaxDynamicSharedMemorySize, GEMM_DYN);
    }

    cudaMemcpyAsync(px, gf, (size_t)NT * D * sizeof(float), cudaMemcpyDeviceToDevice);

    cvt_all<<<(N_CVT + 255) / 256, 256>>>(wqkv, w1, w2, wo, wp);

    for (int i = 0; i < DEPTH; i++) {
        ln_kernel<0><<<NT, 128>>>(px, nullptr, pxnh, pxnl, ln1_g + i * D, ln1_b + i * D);
        gemm_mma<4, 3><<<dim3(12, 32), 256, GEMM_DYN>>>(
            pxnh, pxnl, pWqh + (size_t)i * 3 * D * D, pWql + (size_t)i * 3 * D * D,
            bqkv + i * 3 * D, nullptr, pqh, nullptr, 3 * D, D);
        attn_tc<<<dim3(NHD, NT / 64), 128>>>();
        gemm_mma<2, 3><<<dim3(4, 32), 256, GEMM_DYN>>>(
            paoh, paol, pWoh + (size_t)i * D * D, pWol + (size_t)i * D * D,
            bo + i * D, px, nullptr, nullptr, D, D);
        ln_kernel<0><<<NT, 128>>>(px, nullptr, pxnh, pxnl, ln2_g + i * D, ln2_b + i * D);
        gemm_mma<5, 2><<<dim3(16, 32), 256, GEMM_DYN>>>(
            pxnh, nullptr, pW1h + (size_t)i * DMLP * D, pW1l + (size_t)i * DMLP * D,
            b1 + i * DMLP, nullptr, phh, nullptr, DMLP, D);
        gemm_mma<2, 2><<<dim3(4, 32), 256, GEMM_DYN>>>(
            phh, nullptr, pW2h + (size_t)i * D * DMLP, pW2l + (size_t)i * D * DMLP,
            b2 + i * D, px, nullptr, nullptr, D, DMLP);
        scatter_kernel<<<NT * (D / 4) / 256, 256>>>(coords);
        convgather_kernel<<<NT * D / 256, 256>>>(coords, ck + (size_t)i * D * 9, cb + i * D);
    }
    ln_kernel<1><<<NT, 128>>>(px, out_x, pxfh, pxfl, lnf_g, lnf_b);
    gemm_mma<0, 3><<<dim3(2, 32), 256, GEMM_DYN>>>(
        pxfh, pxfl, pWph, pWpl, bp, out_pred, nullptr, nullptr, GENES, D);
}

// round 11
// speedup vs baseline: 1.8231x; 1.0735x over previous
#include <cuda_runtime.h>
#include <cuda_bf16.h>
#include <cuda_fp16.h>
#include <math.h>
#include <stdint.h>

#define NT    4096
#define D     512
#define NHD   16
#define DH    32
#define DEPTH 3
#define DMLP  2048
#define GENES 250
#define GH    64
#define GW    64

// ---------------- PTX helpers ----------------
__device__ __forceinline__ uint32_t smem_u32(const void* p) {
    uint32_t a;
    asm("{ .reg .u64 t; cvta.to.shared.u64 t, %1; cvt.u32.u64 %0, t; }" : "=r"(a) : "l"(p));
    return a;
}
#define CP_ASYNC16(sa, ga) \
    asm volatile("cp.async.cg.shared.global [%0], [%1], 16;" :: "r"(sa), "l"(ga))
#define CP_COMMIT() asm volatile("cp.async.commit_group;")
#define CP_WAIT(n)  asm volatile("cp.async.wait_group %0;" :: "n"(n))

#define LDSM4(r0, r1, r2, r3, addr) \
    asm volatile("ldmatrix.sync.aligned.m8n8.x4.shared.b16 {%0,%1,%2,%3}, [%4];" \
        : "=r"(r0), "=r"(r1), "=r"(r2), "=r"(r3) : "r"(addr))
#define LDSM4T(r0, r1, r2, r3, addr) \
    asm volatile("ldmatrix.sync.aligned.m8n8.x4.trans.shared.b16 {%0,%1,%2,%3}, [%4];" \
        : "=r"(r0), "=r"(r1), "=r"(r2), "=r"(r3) : "r"(addr))

template <int F16>
__device__ __forceinline__ void mma_any(float* d, const uint32_t* a, const uint32_t* b) {
    if (F16)
        asm volatile("mma.sync.aligned.m16n8k16.row.col.f32.f16.f16.f32 "
            "{%0,%1,%2,%3}, {%4,%5,%6,%7}, {%8,%9}, {%0,%1,%2,%3};"
            : "+f"(d[0]), "+f"(d[1]), "+f"(d[2]), "+f"(d[3])
            : "r"(a[0]), "r"(a[1]), "r"(a[2]), "r"(a[3]), "r"(b[0]), "r"(b[1]));
    else
        asm volatile("mma.sync.aligned.m16n8k16.row.col.f32.bf16.bf16.f32 "
            "{%0,%1,%2,%3}, {%4,%5,%6,%7}, {%8,%9}, {%0,%1,%2,%3};"
            : "+f"(d[0]), "+f"(d[1]), "+f"(d[2]), "+f"(d[3])
            : "r"(a[0]), "r"(a[1]), "r"(a[2]), "r"(a[3]), "r"(b[0]), "r"(b[1]));
}
__device__ __forceinline__ void mma_bf16(float* d, const uint32_t* a, const uint32_t* b) {
    mma_any<0>(d, a, b);
}

#define PACKBF(d, lo, hi) \
    asm("cvt.rn.bf16x2.f32 %0, %1, %2;" : "=r"(d) : "f"(hi), "f"(lo))
#define PACKF16(d, lo, hi) \
    asm("cvt.rn.f16x2.f32 %0, %1, %2;" : "=r"(d) : "f"(hi), "f"(lo))

__device__ __forceinline__ float ex2f(float x) {
    float y; asm("ex2.approx.f32 %0, %1;" : "=f"(y) : "f"(x)); return y;
}

__device__ __forceinline__ void hilo(float v, __nv_bfloat16& h, __nv_bfloat16& l) {
    h = __float2bfloat16(v);
    l = __float2bfloat16(v - __bfloat162float(h));
}
__device__ __forceinline__ void hilo16(float v, __half& h, __half& l) {
    h = __float2half_rn(v);
    l = __float2half_rn(v - __half2float(h));
}

// ---------------- device scratch ----------------
__device__ float g_x[NT * D];
__device__ float g_grid[GH * GW * D];
__device__ __nv_bfloat16 g_qkv_h[NT * 3 * D];
__device__ __half        g_xn16[NT * D];
__device__ __nv_bfloat16 g_ao_h[NT * D],  g_ao_l[NT * D];
__device__ __half        g_h16[NT * DMLP];
__device__ __nv_bfloat16 g_xf_h[NT * D],  g_xf_l[NT * D];
__device__ __half        g_wq16h[DEPTH * 3 * D * D], g_wq16l[DEPTH * 3 * D * D];
__device__ __half        g_w1_16h[DEPTH * DMLP * D], g_w1_16l[DEPTH * DMLP * D];
__device__ __half        g_w2_16h[DEPTH * D * DMLP], g_w2_16l[DEPTH * D * DMLP];
__device__ __nv_bfloat16 g_wo_h[DEPTH * D * D],      g_wo_l[DEPTH * D * D];
__device__ __nv_bfloat16 g_wp_h[GENES * D],          g_wp_l[GENES * D];

// ---- one merged weight-conversion kernel ----
#define N_WQKV (DEPTH * 3 * D * D)
#define N_W1   (DEPTH * DMLP * D)
#define N_W2   (DEPTH * D * DMLP)
#define N_WO   (DEPTH * D * D)
#define N_WP   (GENES * D)
#define N_CVT  (N_WQKV + N_W1 + N_W2 + N_WO + N_WP)

__global__ void cvt_all(const float* __restrict__ wqkv, const float* __restrict__ w1,
                        const float* __restrict__ w2, const float* __restrict__ wo,
                        const float* __restrict__ wp) {
    int j = blockIdx.x * blockDim.x + threadIdx.x;
    if (j < N_WQKV) {
        __half h, l; hilo16(wqkv[j], h, l); g_wq16h[j] = h; g_wq16l[j] = l; return;
    }
    j -= N_WQKV;
    if (j < N_W1) {
        __half h, l; hilo16(w1[j], h, l); g_w1_16h[j] = h; g_w1_16l[j] = l; return;
    }
    j -= N_W1;
    if (j < N_W2) {
        __half h, l; hilo16(w2[j], h, l); g_w2_16h[j] = h; g_w2_16l[j] = l; return;
    }
    j -= N_W2;
    if (j < N_WO) {
        __nv_bfloat16 h, l; hilo(wo[j], h, l); g_wo_h[j] = h; g_wo_l[j] = l; return;
    }
    j -= N_WO;
    if (j < N_WP) {
        __nv_bfloat16 h, l; hilo(wp[j], h, l); g_wp_h[j] = h; g_wp_l[j] = l;
    }
}

// ---------------- LayerNorm -> fp16 single (for fp16 GEMM A operand) -------
__global__ void ln_f16(const float* __restrict__ in, __half* __restrict__ oh,
                       const float* __restrict__ gam, const float* __restrict__ bet) {
    int row = blockIdx.x, t = threadIdx.x;
    float4 v = ((const float4*)(in + (size_t)row * D))[t];
    float s = v.x + v.y + v.z + v.w;
    float ss = v.x * v.x + v.y * v.y + v.z * v.z + v.w * v.w;
#pragma unroll
    for (int off = 16; off; off >>= 1) {
        s  += __shfl_xor_sync(0xffffffffu, s, off);
        ss += __shfl_xor_sync(0xffffffffu, ss, off);
    }
    __shared__ float sb[4], ssb[4];
    int w = t >> 5, lane = t & 31;
    if (lane == 0) { sb[w] = s; ssb[w] = ss; }
    __syncthreads();
    s = sb[0] + sb[1] + sb[2] + sb[3];
    ss = ssb[0] + ssb[1] + ssb[2] + ssb[3];
    float mean = s * (1.0f / D);
    float inv = rsqrtf(ss * (1.0f / D) - mean * mean + 1e-5f);
    float4 g4 = ((const float4*)gam)[t];
    float4 b4 = ((const float4*)bet)[t];
    float o0 = (v.x - mean) * inv * g4.x + b4.x;
    float o1 = (v.y - mean) * inv * g4.y + b4.y;
    float o2 = (v.z - mean) * inv * g4.z + b4.z;
    float o3 = (v.w - mean) * inv * g4.w + b4.w;
    uint2 pk;
    PACKF16(pk.x, o0, o1);
    PACKF16(pk.y, o2, o3);
    *(uint2*)(oh + (size_t)row * D + t * 4) = pk;
}

// ---------------- LayerNorm -> bf16 hi/lo + fp32 (final LN) ----------------
__global__ void ln_bf(const float* __restrict__ in, float* __restrict__ out32,
                      __nv_bfloat16* __restrict__ oh, __nv_bfloat16* __restrict__ ol,
                      const float* __restrict__ gam, const float* __restrict__ bet) {
    int row = blockIdx.x, t = threadIdx.x;
    float4 v = ((const float4*)(in + (size_t)row * D))[t];
    float s = v.x + v.y + v.z + v.w;
    float ss = v.x * v.x + v.y * v.y + v.z * v.z + v.w * v.w;
#pragma unroll
    for (int off = 16; off; off >>= 1) {
        s  += __shfl_xor_sync(0xffffffffu, s, off);
        ss += __shfl_xor_sync(0xffffffffu, ss, off);
    }
    __shared__ float sb[4], ssb[4];
    int w = t >> 5, lane = t & 31;
    if (lane == 0) { sb[w] = s; ssb[w] = ss; }
    __syncthreads();
    s = sb[0] + sb[1] + sb[2] + sb[3];
    ss = ssb[0] + ssb[1] + ssb[2] + ssb[3];
    float mean = s * (1.0f / D);
    float inv = rsqrtf(ss * (1.0f / D) - mean * mean + 1e-5f);
    float4 g4 = ((const float4*)gam)[t];
    float4 b4 = ((const float4*)bet)[t];
    float o0 = (v.x - mean) * inv * g4.x + b4.x;
    float o1 = (v.y - mean) * inv * g4.y + b4.y;
    float o2 = (v.z - mean) * inv * g4.z + b4.z;
    float o3 = (v.w - mean) * inv * g4.w + b4.w;
    size_t base = (size_t)row * D + t * 4;
    __nv_bfloat16 h0, l0, h1, l1, h2, l2, h3, l3;
    hilo(o0, h0, l0); hilo(o1, h1, l1); hilo(o2, h2, l2); hilo(o3, h3, l3);
    __nv_bfloat162 p;
    p.x = h0; p.y = h1; *(__nv_bfloat162*)(oh + base) = p;
    p.x = h2; p.y = h3; *(__nv_bfloat162*)(oh + base + 2) = p;
    p.x = l0; p.y = l1; *(__nv_bfloat162*)(ol + base) = p;
    p.x = l2; p.y = l3; *(__nv_bfloat162*)(ol + base + 2) = p;
    float4 o; o.x = o0; o.y = o1; o.z = o2; o.w = o3;
    ((float4*)(out32 + (size_t)row * D))[t] = o;
}

// ---------------- 16-bit hi/lo GEMM via mma.sync ----------------------------
// TERMS=3: Ah*Wh + Ah*Wl + Al*Wh   TERMS=2: Ah*Wh + Ah*Wl (A single precision)
// F16 selects fp16 vs bf16 operands.
#define TPITCH 80
#define TILE_B (128 * TPITCH)
#define STAGE_B (4 * TILE_B)
#define GEMM_DYN (2 * STAGE_B)

template <int TERMS>
__device__ __forceinline__ void stage_load(
    uint32_t sbase, const uint16_t* Ah, const uint16_t* Al,
    const uint16_t* Wh, const uint16_t* Wl,
    int mrow, int ncol, int OUT, int K, int kt, int tid) {
#pragma unroll
    for (int i = 0; i < 2; i++) {
        int chunk = tid + i * 256;
        int r = chunk >> 2, c16 = chunk & 3;
        uint32_t so = (uint32_t)(r * TPITCH + c16 * 16);
        size_t aoff = (size_t)(mrow + r) * K + kt + c16 * 8;
        int wr = ncol + r; if (wr >= OUT) wr = OUT - 1;
        size_t woff = (size_t)wr * K + kt + c16 * 8;
        CP_ASYNC16(sbase + so,              (const char*)(Ah + aoff));
        if (TERMS == 3)
            CP_ASYNC16(sbase + TILE_B + so, (const char*)(Al + aoff));
        CP_ASYNC16(sbase + 2 * TILE_B + so, (const char*)(Wh + woff));
        CP_ASYNC16(sbase + 3 * TILE_B + so, (const char*)(Wl + woff));
    }
}

// MODE 0: out32=v+bias ; 2: out32+=v+bias ; 4: out16=pack(v+bias) ;
// 5: out16=pack(gelu(v+bias))  (pack = bf16 if !OUTF16 else fp16)
template <int MODE, int TERMS, int F16, int OUTF16>
__global__ void __launch_bounds__(256) gemm_mma(
    const uint16_t* __restrict__ Ah, const uint16_t* __restrict__ Al,
    const uint16_t* __restrict__ Wh, const uint16_t* __restrict__ Wl,
    const float* __restrict__ bias, float* __restrict__ out32,
    uint16_t* __restrict__ out16, int OUT, int K) {
    extern __shared__ char dyn_raw[];
    const int tid = threadIdx.x, wid = tid >> 5, lane = tid & 31;
    const int mrow = blockIdx.y * 128, ncol = blockIdx.x * 128;
    const int warp_m = wid & 1, warp_n = wid >> 1;
    const int m_off = warp_m * 64, n_off = warp_n * 32;
    const int NIT = K >> 5;
    uint32_t smem0 = smem_u32(dyn_raw);

    float acc[4][4][4];
#pragma unroll
    for (int a = 0; a < 4; a++)
#pragma unroll
        for (int b = 0; b < 4; b++)
#pragma unroll
            for (int c = 0; c < 4; c++) acc[a][b][c] = 0.f;

    const uint32_t a_lm = (uint32_t)((m_off + (lane & 15)) * TPITCH + (lane & 16));
    const int bl = lane & 7, bg = (lane >> 3) & 3;
    const uint32_t b_lm = (uint32_t)((n_off + ((bg >> 1) << 3) + bl) * TPITCH + ((bg & 1) << 4));

    stage_load<TERMS>(smem0, Ah, Al, Wh, Wl, mrow, ncol, OUT, K, 0, tid);
    CP_COMMIT();

    for (int it = 0; it < NIT; it++) {
        if (it + 1 < NIT) {
            stage_load<TERMS>(smem0 + ((it + 1) & 1) * STAGE_B, Ah, Al, Wh, Wl,
                              mrow, ncol, OUT, K, (it + 1) * 32, tid);
            CP_COMMIT();
            CP_WAIT(1);
        } else {
            CP_WAIT(0);
        }
        __syncthreads();
        uint32_t sb = smem0 + (it & 1) * STAGE_B;
#pragma unroll
        for (int ks = 0; ks < 2; ks++) {
            uint32_t kb = (uint32_t)(ks * 32);
            uint32_t ah[4][4], al[4][4], bh[4][2], bl2[4][2];
#pragma unroll
            for (int mt = 0; mt < 4; mt++) {
                uint32_t ad = sb + a_lm + mt * (16 * TPITCH) + kb;
                LDSM4(ah[mt][0], ah[mt][1], ah[mt][2], ah[mt][3], ad);
                if (TERMS == 3)
                    LDSM4(al[mt][0], al[mt][1], al[mt][2], al[mt][3], ad + TILE_B);
            }
#pragma unroll
            for (int np = 0; np < 2; np++) {
                uint32_t bd = sb + 2 * TILE_B + b_lm + np * (16 * TPITCH) + kb;
                LDSM4(bh[2 * np][0], bh[2 * np][1], bh[2 * np + 1][0], bh[2 * np + 1][1], bd);
                LDSM4(bl2[2 * np][0], bl2[2 * np][1], bl2[2 * np + 1][0], bl2[2 * np + 1][1], bd + TILE_B);
            }
#pragma unroll
            for (int mt = 0; mt < 4; mt++)
#pragma unroll
                for (int nt = 0; nt < 4; nt++) {
                    mma_any<F16>(acc[mt][nt], ah[mt], bh[nt]);
                    mma_any<F16>(acc[mt][nt], ah[mt], bl2[nt]);
                    if (TERMS == 3)
                        mma_any<F16>(acc[mt][nt], al[mt], bh[nt]);
                }
        }
        __syncthreads();
    }

    const int r0 = lane >> 2, cp = (lane & 3) * 2;
#pragma unroll
    for (int mt = 0; mt < 4; mt++)
#pragma unroll
        for (int nt = 0; nt < 4; nt++) {
            int col = ncol + n_off + nt * 8 + cp;
            if (col >= OUT) continue;
            float bx = bias[col], by = bias[col + 1];
#pragma unroll
            for (int half = 0; half < 2; half++) {
                int row = mrow + m_off + mt * 16 + r0 + half * 8;
                float vx = acc[mt][nt][2 * half] + bx;
                float vy = acc[mt][nt][2 * half + 1] + by;
                size_t idx = (size_t)row * OUT + col;
                if (MODE == 0) {
                    *(float2*)(out32 + idx) = make_float2(vx, vy);
                } else if (MODE == 4 || MODE == 5) {
                    if (MODE == 5) {
                        vx = 0.5f * vx * (1.0f + erff(vx * 0.70710678118654752f));
                        vy = 0.5f * vy * (1.0f + erff(vy * 0.70710678118654752f));
                    }
                    uint32_t hp;
                    if (OUTF16) PACKF16(hp, vx, vy);
                    else        PACKBF(hp, vx, vy);
                    *(uint32_t*)(out16 + idx) = hp;
                } else {
                    float2 o = *(float2*)(out32 + idx);
                    o.x += vx; o.y += vy;
                    *(float2*)(out32 + idx) = o;
                }
            }
        }
}

// ---------------- flash attention, pure bf16, max-free softmax --------------
#define AP 80
#define KVT (64 * AP)
#define ASTG (2 * KVT)

__global__ void __launch_bounds__(128) attn_tc() {
    __shared__ __align__(16) char smem[2 * ASTG];
    const int tid = threadIdx.x, wid = tid >> 5, lane = tid & 31;
    const int h = blockIdx.x, qb = blockIdx.y * 64;
    const uint32_t s0 = smem_u32(smem);

#pragma unroll
    for (int i = 0; i < 2; i++) {
        int idx = tid + i * 128;
        int r = idx >> 2, c = idx & 3;
        CP_ASYNC16(s0 + r * AP + c * 16,
                   g_qkv_h + (size_t)(qb + r) * 1536 + h * 32 + c * 8);
    }
    CP_COMMIT(); CP_WAIT(0); __syncthreads();
    uint32_t qh[2][4];
    {
        uint32_t alm = s0 + (wid * 16 + (lane & 15)) * AP + (lane & 16);
        LDSM4(qh[0][0], qh[0][1], qh[0][2], qh[0][3], alm);
        LDSM4(qh[1][0], qh[1][1], qh[1][2], qh[1][3], alm + 32);
    }
    __syncthreads();

    const int bl = lane & 7, bg = (lane >> 3) & 3;
    const uint32_t koff = (uint32_t)((((bg >> 1) * 8) + bl) * AP + ((bg & 1) * 16));
    const uint32_t voff = (uint32_t)(((((lane >> 3) & 1) * 8) + (lane & 7)) * AP + (((lane >> 4) & 1) * 16));

    float O[4][4];
#pragma unroll
    for (int a = 0; a < 4; a++)
#pragma unroll
        for (int b = 0; b < 4; b++) O[a][b] = 0.f;
    float lsum0 = 0.f, lsum1 = 0.f;
    const float sc2 = 0.25501649f;   // (1/sqrt(32)) * log2(e)

    {
#pragma unroll
        for (int i = 0; i < 4; i++) {
            int idx = tid + i * 128;
            int tile = idx >> 8, rem = idx & 255, r = rem >> 2, c = rem & 3;
            int col = (tile ? 1024 : 512) + h * 32;
            CP_ASYNC16(s0 + tile * KVT + r * AP + c * 16,
                       g_qkv_h + (size_t)r * 1536 + col + c * 8);
        }
        CP_COMMIT();
    }

    for (int t = 0; t < NT / 64; t++) {
        if (t + 1 < NT / 64) {
            int kb = (t + 1) * 64;
            uint32_t st = s0 + ((t + 1) & 1) * ASTG;
#pragma unroll
            for (int i = 0; i < 4; i++) {
                int idx = tid + i * 128;
                int tile = idx >> 8, rem = idx & 255, r = rem >> 2, c = rem & 3;
                int col = (tile ? 1024 : 512) + h * 32;
                CP_ASYNC16(st + tile * KVT + r * AP + c * 16,
                           g_qkv_h + (size_t)(kb + r) * 1536 + col + c * 8);
            }
            CP_COMMIT(); CP_WAIT(1);
        } else {
            CP_WAIT(0);
        }
        __syncthreads();
        uint32_t sb = s0 + (t & 1) * ASTG;

        float S[8][4];
#pragma unroll
        for (int a = 0; a < 8; a++)
#pragma unroll
            for (int b = 0; b < 4; b++) S[a][b] = 0.f;
#pragma unroll
        for (int ks = 0; ks < 2; ks++) {
            uint32_t kh[8][2];
#pragma unroll
            for (int np = 0; np < 4; np++) {
                uint32_t ad = sb + np * (16 * AP) + koff + ks * 32;
                LDSM4(kh[2 * np][0], kh[2 * np][1], kh[2 * np + 1][0], kh[2 * np + 1][1], ad);
            }
#pragma unroll
            for (int nt = 0; nt < 8; nt++)
                mma_bf16(S[nt], qh[ks], kh[nt]);
        }

        uint32_t ph01[8], ph23[8];
#pragma unroll
        for (int nt = 0; nt < 8; nt++) {
            float p0 = ex2f(S[nt][0] * sc2);
            float p1 = ex2f(S[nt][1] * sc2);
            float p2 = ex2f(S[nt][2] * sc2);
            float p3 = ex2f(S[nt][3] * sc2);
            lsum0 += p0 + p1; lsum1 += p2 + p3;
            PACKBF(ph01[nt], p0, p1);
            PACKBF(ph23[nt], p2, p3);
        }

#pragma unroll
        for (int s = 0; s < 4; s++) {
            uint32_t aH[4] = { ph01[2 * s], ph23[2 * s], ph01[2 * s + 1], ph23[2 * s + 1] };
            uint32_t vh[4][2];
#pragma unroll
            for (int d2 = 0; d2 < 2; d2++) {
                uint32_t ad = sb + KVT + s * (16 * AP) + voff + d2 * 32;
                LDSM4T(vh[2 * d2][0], vh[2 * d2][1], vh[2 * d2 + 1][0], vh[2 * d2 + 1][1], ad);
            }
#pragma unroll
            for (int nt = 0; nt < 4; nt++)
                mma_bf16(O[nt], aH, vh[nt]);
        }
        __syncthreads();
    }

    lsum0 += __shfl_xor_sync(0xffffffffu, lsum0, 1);
    lsum0 += __shfl_xor_sync(0xffffffffu, lsum0, 2);
    lsum1 += __shfl_xor_sync(0xffffffffu, lsum1, 1);
    lsum1 += __shfl_xor_sync(0xffffffffu, lsum1, 2);
    float i0 = 1.f / lsum0, i1 = 1.f / lsum1;
    int r0 = qb + wid * 16 + (lane >> 2), r1 = r0 + 8;
    int colb = h * 32 + (lane & 3) * 2;
#pragma unroll
    for (int nt = 0; nt < 4; nt++) {
        int col = colb + nt * 8;
        float v0 = O[nt][0] * i0, v1 = O[nt][1] * i0;
        float v2 = O[nt][2] * i1, v3 = O[nt][3] * i1;
        uint32_t hp, lp;
        PACKBF(hp, v0, v1);
        float h0f = __uint_as_float(hp << 16), h1f = __uint_as_float(hp & 0xffff0000u);
        PACKBF(lp, v0 - h0f, v1 - h1f);
        *(uint32_t*)(g_ao_h + (size_t)r0 * D + col) = hp;
        *(uint32_t*)(g_ao_l + (size_t)r0 * D + col) = lp;
        PACKBF(hp, v2, v3);
        h0f = __uint_as_float(hp << 16); h1f = __uint_as_float(hp & 0xffff0000u);
        PACKBF(lp, v2 - h0f, v3 - h1f);
        *(uint32_t*)(g_ao_h + (size_t)r1 * D + col) = hp;
        *(uint32_t*)(g_ao_l + (size_t)r1 * D + col) = lp;
    }
}

// ---------------- conv path ----------------
__global__ void scatter_kernel(const int* __restrict__ coords) {
    int idx = blockIdx.x * blockDim.x + threadIdx.x;
    int n = idx >> 7, d4 = idx & 127;
    int rr = coords[2 * n], cc = coords[2 * n + 1];
    ((float4*)g_grid)[(size_t)(rr * GW + cc) * 128 + d4] =
        ((const float4*)g_x)[(size_t)n * 128 + d4];
}
__global__ void convgather_kernel(const int* __restrict__ coords,
                                  const float* __restrict__ ck,
                                  const float* __restrict__ cb) {
    int idx = blockIdx.x * blockDim.x + threadIdx.x;
    int n = idx >> 9, d = idx & (D - 1);
    int r = coords[2 * n], c = coords[2 * n + 1];
    float acc = cb[d];
#pragma unroll
    for (int kh = 0; kh < 3; kh++) {
        int rr = r + kh - 1;
        if ((unsigned)rr >= GH) continue;
#pragma unroll
        for (int kw = 0; kw < 3; kw++) {
            int cc = c + kw - 1;
            if ((unsigned)cc >= GW) continue;
            acc += ck[d * 9 + kh * 3 + kw] * g_grid[(size_t)(rr * GW + cc) * D + d];
        }
    }
    g_x[idx] += acc;
}

// ---------------- host ----------------
extern "C" void kernel_launch(void* const* d_in, const int* in_sizes, int n_in,
                              void* d_out, int out_size) {
    const float* gf     = (const float*)d_in[0];
    const int*   coords = (const int*)d_in[1];
    int wi = (n_in >= 22) ? 4 : 2;
    const float* ln1_g = (const float*)d_in[wi + 0];
    const float* ln1_b = (const float*)d_in[wi + 1];
    const float* wqkv  = (const float*)d_in[wi + 2];
    const float* bqkv  = (const float*)d_in[wi + 3];
    const float* wo    = (const float*)d_in[wi + 4];
    const float* bo    = (const float*)d_in[wi + 5];
    const float* ln2_g = (const float*)d_in[wi + 6];
    const float* ln2_b = (const float*)d_in[wi + 7];
    const float* w1    = (const float*)d_in[wi + 8];
    const float* b1    = (const float*)d_in[wi + 9];
    const float* w2    = (const float*)d_in[wi + 10];
    const float* b2    = (const float*)d_in[wi + 11];
    const float* ck    = (const float*)d_in[wi + 12];
    const float* cb    = (const float*)d_in[wi + 13];
    const float* lnf_g = (const float*)d_in[wi + 14];
    const float* lnf_b = (const float*)d_in[wi + 15];
    const float* wp    = (const float*)d_in[wi + 16];
    const float* bp    = (const float*)d_in[wi + 17];

    float* out_x    = (float*)d_out;
    float* out_pred = out_x + (size_t)NT * D;

    static float* px = nullptr;
    static uint16_t *pqh, *pxn16, *paoh, *paol, *ph16, *pxfh, *pxfl;
    static uint16_t *pWq16h, *pWq16l, *pW1h, *pW1l, *pW2h, *pW2l, *pWoh, *pWol, *pWph, *pWpl;
    if (!px) {
        cudaGetSymbolAddress((void**)&px, g_x);
        cudaGetSymbolAddress((void**)&pqh, g_qkv_h);
        cudaGetSymbolAddress((void**)&pxn16, g_xn16);
        cudaGetSymbolAddress((void**)&paoh, g_ao_h);  cudaGetSymbolAddress((void**)&paol, g_ao_l);
        cudaGetSymbolAddress((void**)&ph16, g_h16);
        cudaGetSymbolAddress((void**)&pxfh, g_xf_h);  cudaGetSymbolAddress((void**)&pxfl, g_xf_l);
        cudaGetSymbolAddress((void**)&pWq16h, g_wq16h); cudaGetSymbolAddress((void**)&pWq16l, g_wq16l);
        cudaGetSymbolAddress((void**)&pW1h, g_w1_16h);  cudaGetSymbolAddress((void**)&pW1l, g_w1_16l);
        cudaGetSymbolAddress((void**)&pW2h, g_w2_16h);  cudaGetSymbolAddress((void**)&pW2l, g_w2_16l);
        cudaGetSymbolAddress((void**)&pWoh, g_wo_h);    cudaGetSymbolAddress((void**)&pWol, g_wo_l);
        cudaGetSymbolAddress((void**)&pWph, g_wp_h);    cudaGetSymbolAddress((void**)&pWpl, g_wp_l);
        cudaFuncSetAttribute((const void*)gemm_mma<0, 3, 0, 0>, cudaFuncAttributeMaxDynamicSharedMemorySize, GEMM_DYN);
        cudaFuncSetAttribute((const void*)gemm_mma<2, 3, 0, 0>, cudaFuncAttributeMaxDynamicSharedMemorySize, GEMM_DYN);
        cudaFuncSetAttribute((const void*)gemm_mma<4, 2, 1, 0>, cudaFuncAttributeMaxDynamicSharedMemorySize, GEMM_DYN);
        cudaFuncSetAttribute((const void*)gemm_mma<5, 2, 1, 1>, cudaFuncAttributeMaxDynamicSharedMemorySize, GEMM_DYN);
        cudaFuncSetAttribute((const void*)gemm_mma<2, 2, 1, 0>, cudaFuncAttributeMaxDynamicSharedMemorySize, GEMM_DYN);
        // attention: raise smem carveout so smem (20KB/CTA) stops limiting occupancy
        cudaFuncSetAttribute((const void*)attn_tc, cudaFuncAttributePreferredSharedMemoryCarveout, 100);
    }

    cudaMemcpyAsync(px, gf, (size_t)NT * D * sizeof(float), cudaMemcpyDeviceToDevice);

    cvt_all<<<(N_CVT + 255) / 256, 256>>>(wqkv, w1, w2, wo, wp);

    for (int i = 0; i < DEPTH; i++) {
        ln_f16<<<NT, 128>>>(px, (__half*)pxn16, ln1_g + i * D, ln1_b + i * D);
        gemm_mma<4, 2, 1, 0><<<dim3(12, 32), 256, GEMM_DYN>>>(
            pxn16, nullptr, pWq16h + (size_t)i * 3 * D * D, pWq16l + (size_t)i * 3 * D * D,
            bqkv + i * 3 * D, nullptr, pqh, 3 * D, D);
        attn_tc<<<dim3(NHD, NT / 64), 128>>>();
        gemm_mma<2, 3, 0, 0><<<dim3(4, 32), 256, GEMM_DYN>>>(
            paoh, paol, pWoh + (size_t)i * D * D, pWol + (size_t)i * D * D,
            bo + i * D, px, nullptr, D, D);
        ln_f16<<<NT, 128>>>(px, (__half*)pxn16, ln2_g + i * D, ln2_b + i * D);
        gemm_mma<5, 2, 1, 1><<<dim3(16, 32), 256, GEMM_DYN>>>(
            pxn16, nullptr, pW1h + (size_t)i * DMLP * D, pW1l + (size_t)i * DMLP * D,
            b1 + i * DMLP, nullptr, ph16, DMLP, D);
        gemm_mma<2, 2, 1, 0><<<dim3(4, 32), 256, GEMM_DYN>>>(
            ph16, nullptr, pW2h + (size_t)i * D * DMLP, pW2l + (size_t)i * D * DMLP,
            b2 + i * D, px, nullptr, D, DMLP);
        scatter_kernel<<<NT * (D / 4) / 256, 256>>>(coords);
        convgather_kernel<<<NT * D / 256, 256>>>(coords, ck + (size_t)i * D * 9, cb + i * D);
    }
    ln_bf<<<NT, 128>>>(px, out_x, (__nv_bfloat16*)pxfh, (__nv_bfloat16*)pxfl, lnf_g, lnf_b);
    gemm_mma<0, 3, 0, 0><<<dim3(2, 32), 256, GEMM_DYN>>>(
        pxfh, pxfl, pWph, pWpl, bp, out_pred, nullptr, GENES, D);
}

// round 12
// speedup vs baseline: 1.9401x; 1.0641x over previous
#include <cuda_runtime.h>
#include <cuda_bf16.h>
#include <cuda_fp16.h>
#include <math.h>
#include <stdint.h>

#define NT    4096
#define D     512
#define NHD   16
#define DH    32
#define DEPTH 3
#define DMLP  2048
#define GENES 250
#define GH    64
#define GW    64

// ---------------- PTX helpers ----------------
__device__ __forceinline__ uint32_t smem_u32(const void* p) {
    uint32_t a;
    asm("{ .reg .u64 t; cvta.to.shared.u64 t, %1; cvt.u32.u64 %0, t; }" : "=r"(a) : "l"(p));
    return a;
}
#define CP_ASYNC16(sa, ga) \
    asm volatile("cp.async.cg.shared.global [%0], [%1], 16;" :: "r"(sa), "l"(ga))
#define CP_COMMIT() asm volatile("cp.async.commit_group;")
#define CP_WAIT(n)  asm volatile("cp.async.wait_group %0;" :: "n"(n))

#define LDSM4(r0, r1, r2, r3, addr) \
    asm volatile("ldmatrix.sync.aligned.m8n8.x4.shared.b16 {%0,%1,%2,%3}, [%4];" \
        : "=r"(r0), "=r"(r1), "=r"(r2), "=r"(r3) : "r"(addr))
#define LDSM4T(r0, r1, r2, r3, addr) \
    asm volatile("ldmatrix.sync.aligned.m8n8.x4.trans.shared.b16 {%0,%1,%2,%3}, [%4];" \
        : "=r"(r0), "=r"(r1), "=r"(r2), "=r"(r3) : "r"(addr))

template <int F16>
__device__ __forceinline__ void mma_any(float* d, const uint32_t* a, const uint32_t* b) {
    if (F16)
        asm volatile("mma.sync.aligned.m16n8k16.row.col.f32.f16.f16.f32 "
            "{%0,%1,%2,%3}, {%4,%5,%6,%7}, {%8,%9}, {%0,%1,%2,%3};"
            : "+f"(d[0]), "+f"(d[1]), "+f"(d[2]), "+f"(d[3])
            : "r"(a[0]), "r"(a[1]), "r"(a[2]), "r"(a[3]), "r"(b[0]), "r"(b[1]));
    else
        asm volatile("mma.sync.aligned.m16n8k16.row.col.f32.bf16.bf16.f32 "
            "{%0,%1,%2,%3}, {%4,%5,%6,%7}, {%8,%9}, {%0,%1,%2,%3};"
            : "+f"(d[0]), "+f"(d[1]), "+f"(d[2]), "+f"(d[3])
            : "r"(a[0]), "r"(a[1]), "r"(a[2]), "r"(a[3]), "r"(b[0]), "r"(b[1]));
}
__device__ __forceinline__ void mma_bf16(float* d, const uint32_t* a, const uint32_t* b) {
    mma_any<0>(d, a, b);
}

#define PACKBF(d, lo, hi) \
    asm("cvt.rn.bf16x2.f32 %0, %1, %2;" : "=r"(d) : "f"(hi), "f"(lo))
#define PACKF16(d, lo, hi) \
    asm("cvt.rn.f16x2.f32 %0, %1, %2;" : "=r"(d) : "f"(hi), "f"(lo))

__device__ __forceinline__ float ex2f(float x) {
    float y; asm("ex2.approx.f32 %0, %1;" : "=f"(y) : "f"(x)); return y;
}

__device__ __forceinline__ void hilo(float v, __nv_bfloat16& h, __nv_bfloat16& l) {
    h = __float2bfloat16(v);
    l = __float2bfloat16(v - __bfloat162float(h));
}
__device__ __forceinline__ void hilo16(float v, __half& h, __half& l) {
    h = __float2half_rn(v);
    l = __float2half_rn(v - __half2float(h));
}

// ---------------- device scratch ----------------
__device__ float g_x[NT * D];
__device__ float g_grid[GH * GW * D];
__device__ __nv_bfloat16 g_qkv_h[NT * 3 * D];
__device__ __half        g_xn16[NT * D];
__device__ __half        g_ao16[NT * D];
__device__ __half        g_h16[NT * DMLP];
__device__ __nv_bfloat16 g_xf_h[NT * D],  g_xf_l[NT * D];
__device__ __half        g_wq16h[DEPTH * 3 * D * D];
__device__ __half        g_w1_16h[DEPTH * DMLP * D], g_w1_16l[DEPTH * DMLP * D];
__device__ __half        g_w2_16h[DEPTH * D * DMLP], g_w2_16l[DEPTH * D * DMLP];
__device__ __half        g_wo16h[DEPTH * D * D],     g_wo16l[DEPTH * D * D];
__device__ __nv_bfloat16 g_wp_h[GENES * D],          g_wp_l[GENES * D];

// ---- one merged weight-conversion kernel ----
#define N_WQKV (DEPTH * 3 * D * D)
#define N_W1   (DEPTH * DMLP * D)
#define N_W2   (DEPTH * D * DMLP)
#define N_WO   (DEPTH * D * D)
#define N_WP   (GENES * D)
#define N_CVT  (N_WQKV + N_W1 + N_W2 + N_WO + N_WP)

__global__ void cvt_all(const float* __restrict__ wqkv, const float* __restrict__ w1,
                        const float* __restrict__ w2, const float* __restrict__ wo,
                        const float* __restrict__ wp) {
    int j = blockIdx.x * blockDim.x + threadIdx.x;
    if (j < N_WQKV) { g_wq16h[j] = __float2half_rn(wqkv[j]); return; }
    j -= N_WQKV;
    if (j < N_W1) {
        __half h, l; hilo16(w1[j], h, l); g_w1_16h[j] = h; g_w1_16l[j] = l; return;
    }
    j -= N_W1;
    if (j < N_W2) {
        __half h, l; hilo16(w2[j], h, l); g_w2_16h[j] = h; g_w2_16l[j] = l; return;
    }
    j -= N_W2;
    if (j < N_WO) {
        __half h, l; hilo16(wo[j], h, l); g_wo16h[j] = h; g_wo16l[j] = l; return;
    }
    j -= N_WO;
    if (j < N_WP) {
        __nv_bfloat16 h, l; hilo(wp[j], h, l); g_wp_h[j] = h; g_wp_l[j] = l;
    }
}

// ---------------- LayerNorm -> fp16 single ---------------------------------
__global__ void ln_f16(const float* __restrict__ in, __half* __restrict__ oh,
                       const float* __restrict__ gam, const float* __restrict__ bet) {
    int row = blockIdx.x, t = threadIdx.x;
    float4 v = ((const float4*)(in + (size_t)row * D))[t];
    float s = v.x + v.y + v.z + v.w;
    float ss = v.x * v.x + v.y * v.y + v.z * v.z + v.w * v.w;
#pragma unroll
    for (int off = 16; off; off >>= 1) {
        s  += __shfl_xor_sync(0xffffffffu, s, off);
        ss += __shfl_xor_sync(0xffffffffu, ss, off);
    }
    __shared__ float sb[4], ssb[4];
    int w = t >> 5, lane = t & 31;
    if (lane == 0) { sb[w] = s; ssb[w] = ss; }
    __syncthreads();
    s = sb[0] + sb[1] + sb[2] + sb[3];
    ss = ssb[0] + ssb[1] + ssb[2] + ssb[3];
    float mean = s * (1.0f / D);
    float inv = rsqrtf(ss * (1.0f / D) - mean * mean + 1e-5f);
    float4 g4 = ((const float4*)gam)[t];
    float4 b4 = ((const float4*)bet)[t];
    float o0 = (v.x - mean) * inv * g4.x + b4.x;
    float o1 = (v.y - mean) * inv * g4.y + b4.y;
    float o2 = (v.z - mean) * inv * g4.z + b4.z;
    float o3 = (v.w - mean) * inv * g4.w + b4.w;
    uint2 pk;
    PACKF16(pk.x, o0, o1);
    PACKF16(pk.y, o2, o3);
    *(uint2*)(oh + (size_t)row * D + t * 4) = pk;
}

// ---------------- LayerNorm -> bf16 hi/lo + fp32 (final LN) ----------------
__global__ void ln_bf(const float* __restrict__ in, float* __restrict__ out32,
                      __nv_bfloat16* __restrict__ oh, __nv_bfloat16* __restrict__ ol,
                      const float* __restrict__ gam, const float* __restrict__ bet) {
    int row = blockIdx.x, t = threadIdx.x;
    float4 v = ((const float4*)(in + (size_t)row * D))[t];
    float s = v.x + v.y + v.z + v.w;
    float ss = v.x * v.x + v.y * v.y + v.z * v.z + v.w * v.w;
#pragma unroll
    for (int off = 16; off; off >>= 1) {
        s  += __shfl_xor_sync(0xffffffffu, s, off);
        ss += __shfl_xor_sync(0xffffffffu, ss, off);
    }
    __shared__ float sb[4], ssb[4];
    int w = t >> 5, lane = t & 31;
    if (lane == 0) { sb[w] = s; ssb[w] = ss; }
    __syncthreads();
    s = sb[0] + sb[1] + sb[2] + sb[3];
    ss = ssb[0] + ssb[1] + ssb[2] + ssb[3];
    float mean = s * (1.0f / D);
    float inv = rsqrtf(ss * (1.0f / D) - mean * mean + 1e-5f);
    float4 g4 = ((const float4*)gam)[t];
    float4 b4 = ((const float4*)bet)[t];
    float o0 = (v.x - mean) * inv * g4.x + b4.x;
    float o1 = (v.y - mean) * inv * g4.y + b4.y;
    float o2 = (v.z - mean) * inv * g4.z + b4.z;
    float o3 = (v.w - mean) * inv * g4.w + b4.w;
    size_t base = (size_t)row * D + t * 4;
    __nv_bfloat16 h0, l0, h1, l1, h2, l2, h3, l3;
    hilo(o0, h0, l0); hilo(o1, h1, l1); hilo(o2, h2, l2); hilo(o3, h3, l3);
    __nv_bfloat162 p;
    p.x = h0; p.y = h1; *(__nv_bfloat162*)(oh + base) = p;
    p.x = h2; p.y = h3; *(__nv_bfloat162*)(oh + base + 2) = p;
    p.x = l0; p.y = l1; *(__nv_bfloat162*)(ol + base) = p;
    p.x = l2; p.y = l3; *(__nv_bfloat162*)(ol + base + 2) = p;
    float4 o; o.x = o0; o.y = o1; o.z = o2; o.w = o3;
    ((float4*)(out32 + (size_t)row * D))[t] = o;
}

// ---------------- 16-bit hi/lo GEMM via mma.sync ----------------------------
// TERMS=3: Ah*Wh + Ah*Wl + Al*Wh ; TERMS=2: Ah*Wh + Ah*Wl ; TERMS=1: Ah*Wh
#define TPITCH 80
#define TILE_B (128 * TPITCH)
#define STAGE_B (4 * TILE_B)
#define GEMM_DYN (2 * STAGE_B)

template <int TERMS>
__device__ __forceinline__ void stage_load(
    uint32_t sbase, const uint16_t* Ah, const uint16_t* Al,
    const uint16_t* Wh, const uint16_t* Wl,
    int mrow, int ncol, int OUT, int K, int kt, int tid) {
#pragma unroll
    for (int i = 0; i < 2; i++) {
        int chunk = tid + i * 256;
        int r = chunk >> 2, c16 = chunk & 3;
        uint32_t so = (uint32_t)(r * TPITCH + c16 * 16);
        size_t aoff = (size_t)(mrow + r) * K + kt + c16 * 8;
        int wr = ncol + r; if (wr >= OUT) wr = OUT - 1;
        size_t woff = (size_t)wr * K + kt + c16 * 8;
        CP_ASYNC16(sbase + so,              (const char*)(Ah + aoff));
        if (TERMS == 3)
            CP_ASYNC16(sbase + TILE_B + so, (const char*)(Al + aoff));
        CP_ASYNC16(sbase + 2 * TILE_B + so, (const char*)(Wh + woff));
        if (TERMS >= 2)
            CP_ASYNC16(sbase + 3 * TILE_B + so, (const char*)(Wl + woff));
    }
}

// MODE 0: out32=v+bias ; 2: out32+=v+bias ; 4: out16=pack(v+bias) ;
// 5: out16=pack(gelu(v+bias))  (pack = bf16 if !OUTF16 else fp16)
template <int MODE, int TERMS, int F16, int OUTF16>
__global__ void __launch_bounds__(256) gemm_mma(
    const uint16_t* __restrict__ Ah, const uint16_t* __restrict__ Al,
    const uint16_t* __restrict__ Wh, const uint16_t* __restrict__ Wl,
    const float* __restrict__ bias, float* __restrict__ out32,
    uint16_t* __restrict__ out16, int OUT, int K) {
    extern __shared__ char dyn_raw[];
    const int tid = threadIdx.x, wid = tid >> 5, lane = tid & 31;
    const int mrow = blockIdx.y * 128, ncol = blockIdx.x * 128;
    const int warp_m = wid & 1, warp_n = wid >> 1;
    const int m_off = warp_m * 64, n_off = warp_n * 32;
    const int NIT = K >> 5;
    uint32_t smem0 = smem_u32(dyn_raw);

    float acc[4][4][4];
#pragma unroll
    for (int a = 0; a < 4; a++)
#pragma unroll
        for (int b = 0; b < 4; b++)
#pragma unroll
            for (int c = 0; c < 4; c++) acc[a][b][c] = 0.f;

    const uint32_t a_lm = (uint32_t)((m_off + (lane & 15)) * TPITCH + (lane & 16));
    const int bl = lane & 7, bg = (lane >> 3) & 3;
    const uint32_t b_lm = (uint32_t)((n_off + ((bg >> 1) << 3) + bl) * TPITCH + ((bg & 1) << 4));

    stage_load<TERMS>(smem0, Ah, Al, Wh, Wl, mrow, ncol, OUT, K, 0, tid);
    CP_COMMIT();

    for (int it = 0; it < NIT; it++) {
        if (it + 1 < NIT) {
            stage_load<TERMS>(smem0 + ((it + 1) & 1) * STAGE_B, Ah, Al, Wh, Wl,
                              mrow, ncol, OUT, K, (it + 1) * 32, tid);
            CP_COMMIT();
            CP_WAIT(1);
        } else {
            CP_WAIT(0);
        }
        __syncthreads();
        uint32_t sb = smem0 + (it & 1) * STAGE_B;
#pragma unroll
        for (int ks = 0; ks < 2; ks++) {
            uint32_t kb = (uint32_t)(ks * 32);
            uint32_t ah[4][4], al[4][4], bh[4][2], bl2[4][2];
#pragma unroll
            for (int mt = 0; mt < 4; mt++) {
                uint32_t ad = sb + a_lm + mt * (16 * TPITCH) + kb;
                LDSM4(ah[mt][0], ah[mt][1], ah[mt][2], ah[mt][3], ad);
                if (TERMS == 3)
                    LDSM4(al[mt][0], al[mt][1], al[mt][2], al[mt][3], ad + TILE_B);
            }
#pragma unroll
            for (int np = 0; np < 2; np++) {
                uint32_t bd = sb + 2 * TILE_B + b_lm + np * (16 * TPITCH) + kb;
                LDSM4(bh[2 * np][0], bh[2 * np][1], bh[2 * np + 1][0], bh[2 * np + 1][1], bd);
                if (TERMS >= 2)
                    LDSM4(bl2[2 * np][0], bl2[2 * np][1], bl2[2 * np + 1][0], bl2[2 * np + 1][1], bd + TILE_B);
            }
#pragma unroll
            for (int mt = 0; mt < 4; mt++)
#pragma unroll
                for (int nt = 0; nt < 4; nt++) {
                    mma_any<F16>(acc[mt][nt], ah[mt], bh[nt]);
                    if (TERMS >= 2)
                        mma_any<F16>(acc[mt][nt], ah[mt], bl2[nt]);
                    if (TERMS == 3)
                        mma_any<F16>(acc[mt][nt], al[mt], bh[nt]);
                }
        }
        __syncthreads();
    }

    const int r0 = lane >> 2, cp = (lane & 3) * 2;
#pragma unroll
    for (int mt = 0; mt < 4; mt++)
#pragma unroll
        for (int nt = 0; nt < 4; nt++) {
            int col = ncol + n_off + nt * 8 + cp;
            if (col >= OUT) continue;
            float bx = bias[col], by = bias[col + 1];
#pragma unroll
            for (int half = 0; half < 2; half++) {
                int row = mrow + m_off + mt * 16 + r0 + half * 8;
                float vx = acc[mt][nt][2 * half] + bx;
                float vy = acc[mt][nt][2 * half + 1] + by;
                size_t idx = (size_t)row * OUT + col;
                if (MODE == 0) {
                    *(float2*)(out32 + idx) = make_float2(vx, vy);
                } else if (MODE == 4 || MODE == 5) {
                    if (MODE == 5) {
                        vx = 0.5f * vx * (1.0f + erff(vx * 0.70710678118654752f));
                        vy = 0.5f * vy * (1.0f + erff(vy * 0.70710678118654752f));
                    }
                    uint32_t hp;
                    if (OUTF16) PACKF16(hp, vx, vy);
                    else        PACKBF(hp, vx, vy);
                    *(uint32_t*)(out16 + idx) = hp;
                } else {
                    float2 o = *(float2*)(out32 + idx);
                    o.x += vx; o.y += vy;
                    *(float2*)(out32 + idx) = o;
                }
            }
        }
}

// ---------------- flash attention, pure bf16, max-free softmax --------------
// Dynamic smem (20 KB) with MaxDynamicSharedMemorySize so occupancy is
// reg-limited (~10 CTA) instead of carveout-limited (5 CTA).
#define AP 80
#define KVT (64 * AP)
#define ASTG (2 * KVT)
#define ATTN_DYN (2 * ASTG)

__global__ void __launch_bounds__(128) attn_tc() {
    extern __shared__ __align__(16) char smem[];
    const int tid = threadIdx.x, wid = tid >> 5, lane = tid & 31;
    const int h = blockIdx.x, qb = blockIdx.y * 64;
    const uint32_t s0 = smem_u32(smem);

#pragma unroll
    for (int i = 0; i < 2; i++) {
        int idx = tid + i * 128;
        int r = idx >> 2, c = idx & 3;
        CP_ASYNC16(s0 + r * AP + c * 16,
                   g_qkv_h + (size_t)(qb + r) * 1536 + h * 32 + c * 8);
    }
    CP_COMMIT(); CP_WAIT(0); __syncthreads();
    uint32_t qh[2][4];
    {
        uint32_t alm = s0 + (wid * 16 + (lane & 15)) * AP + (lane & 16);
        LDSM4(qh[0][0], qh[0][1], qh[0][2], qh[0][3], alm);
        LDSM4(qh[1][0], qh[1][1], qh[1][2], qh[1][3], alm + 32);
    }
    __syncthreads();

    const int bl = lane & 7, bg = (lane >> 3) & 3;
    const uint32_t koff = (uint32_t)((((bg >> 1) * 8) + bl) * AP + ((bg & 1) * 16));
    const uint32_t voff = (uint32_t)(((((lane >> 3) & 1) * 8) + (lane & 7)) * AP + (((lane >> 4) & 1) * 16));

    float O[4][4];
#pragma unroll
    for (int a = 0; a < 4; a++)
#pragma unroll
        for (int b = 0; b < 4; b++) O[a][b] = 0.f;
    float lsum0 = 0.f, lsum1 = 0.f;
    const float sc2 = 0.25501649f;   // (1/sqrt(32)) * log2(e)

    {
#pragma unroll
        for (int i = 0; i < 4; i++) {
            int idx = tid + i * 128;
            int tile = idx >> 8, rem = idx & 255, r = rem >> 2, c = rem & 3;
            int col = (tile ? 1024 : 512) + h * 32;
            CP_ASYNC16(s0 + tile * KVT + r * AP + c * 16,
                       g_qkv_h + (size_t)r * 1536 + col + c * 8);
        }
        CP_COMMIT();
    }

    for (int t = 0; t < NT / 64; t++) {
        if (t + 1 < NT / 64) {
            int kb = (t + 1) * 64;
            uint32_t st = s0 + ((t + 1) & 1) * ASTG;
#pragma unroll
            for (int i = 0; i < 4; i++) {
                int idx = tid + i * 128;
                int tile = idx >> 8, rem = idx & 255, r = rem >> 2, c = rem & 3;
                int col = (tile ? 1024 : 512) + h * 32;
                CP_ASYNC16(st + tile * KVT + r * AP + c * 16,
                           g_qkv_h + (size_t)(kb + r) * 1536 + col + c * 8);
            }
            CP_COMMIT(); CP_WAIT(1);
        } else {
            CP_WAIT(0);
        }
        __syncthreads();
        uint32_t sb = s0 + (t & 1) * ASTG;

        float S[8][4];
#pragma unroll
        for (int a = 0; a < 8; a++)
#pragma unroll
            for (int b = 0; b < 4; b++) S[a][b] = 0.f;
#pragma unroll
        for (int ks = 0; ks < 2; ks++) {
            uint32_t kh[8][2];
#pragma unroll
            for (int np = 0; np < 4; np++) {
                uint32_t ad = sb + np * (16 * AP) + koff + ks * 32;
                LDSM4(kh[2 * np][0], kh[2 * np][1], kh[2 * np + 1][0], kh[2 * np + 1][1], ad);
            }
#pragma unroll
            for (int nt = 0; nt < 8; nt++)
                mma_bf16(S[nt], qh[ks], kh[nt]);
        }

        uint32_t ph01[8], ph23[8];
#pragma unroll
        for (int nt = 0; nt < 8; nt++) {
            float p0 = ex2f(S[nt][0] * sc2);
            float p1 = ex2f(S[nt][1] * sc2);
            float p2 = ex2f(S[nt][2] * sc2);
            float p3 = ex2f(S[nt][3] * sc2);
            lsum0 += p0 + p1; lsum1 += p2 + p3;
            PACKBF(ph01[nt], p0, p1);
            PACKBF(ph23[nt], p2, p3);
        }

#pragma unroll
        for (int s = 0; s < 4; s++) {
            uint32_t aH[4] = { ph01[2 * s], ph23[2 * s], ph01[2 * s + 1], ph23[2 * s + 1] };
            uint32_t vh[4][2];
#pragma unroll
            for (int d2 = 0; d2 < 2; d2++) {
                uint32_t ad = sb + KVT + s * (16 * AP) + voff + d2 * 32;
                LDSM4T(vh[2 * d2][0], vh[2 * d2][1], vh[2 * d2 + 1][0], vh[2 * d2 + 1][1], ad);
            }
#pragma unroll
            for (int nt = 0; nt < 4; nt++)
                mma_bf16(O[nt], aH, vh[nt]);
        }
        __syncthreads();
    }

    lsum0 += __shfl_xor_sync(0xffffffffu, lsum0, 1);
    lsum0 += __shfl_xor_sync(0xffffffffu, lsum0, 2);
    lsum1 += __shfl_xor_sync(0xffffffffu, lsum1, 1);
    lsum1 += __shfl_xor_sync(0xffffffffu, lsum1, 2);
    float i0 = 1.f / lsum0, i1 = 1.f / lsum1;
    int r0 = qb + wid * 16 + (lane >> 2), r1 = r0 + 8;
    int colb = h * 32 + (lane & 3) * 2;
#pragma unroll
    for (int nt = 0; nt < 4; nt++) {
        int col = colb + nt * 8;
        uint32_t hp;
        PACKF16(hp, O[nt][0] * i0, O[nt][1] * i0);
        *(uint32_t*)(g_ao16 + (size_t)r0 * D + col) = hp;
        PACKF16(hp, O[nt][2] * i1, O[nt][3] * i1);
        *(uint32_t*)(g_ao16 + (size_t)r1 * D + col) = hp;
    }
}

// ---------------- conv path ----------------
__global__ void scatter_kernel(const int* __restrict__ coords) {
    int idx = blockIdx.x * blockDim.x + threadIdx.x;
    int n = idx >> 7, d4 = idx & 127;
    int rr = coords[2 * n], cc = coords[2 * n + 1];
    ((float4*)g_grid)[(size_t)(rr * GW + cc) * 128 + d4] =
        ((const float4*)g_x)[(size_t)n * 128 + d4];
}
__global__ void convgather_kernel(const int* __restrict__ coords,
                                  const float* __restrict__ ck,
                                  const float* __restrict__ cb) {
    int idx = blockIdx.x * blockDim.x + threadIdx.x;
    int n = idx >> 9, d = idx & (D - 1);
    int r = coords[2 * n], c = coords[2 * n + 1];
    float acc = cb[d];
#pragma unroll
    for (int kh = 0; kh < 3; kh++) {
        int rr = r + kh - 1;
        if ((unsigned)rr >= GH) continue;
#pragma unroll
        for (int kw = 0; kw < 3; kw++) {
            int cc = c + kw - 1;
            if ((unsigned)cc >= GW) continue;
            acc += ck[d * 9 + kh * 3 + kw] * g_grid[(size_t)(rr * GW + cc) * D + d];
        }
    }
    g_x[idx] += acc;
}

// ---------------- host ----------------
extern "C" void kernel_launch(void* const* d_in, const int* in_sizes, int n_in,
                              void* d_out, int out_size) {
    const float* gf     = (const float*)d_in[0];
    const int*   coords = (const int*)d_in[1];
    int wi = (n_in >= 22) ? 4 : 2;
    const float* ln1_g = (const float*)d_in[wi + 0];
    const float* ln1_b = (const float*)d_in[wi + 1];
    const float* wqkv  = (const float*)d_in[wi + 2];
    const float* bqkv  = (const float*)d_in[wi + 3];
    const float* wo    = (const float*)d_in[wi + 4];
    const float* bo    = (const float*)d_in[wi + 5];
    const float* ln2_g = (const float*)d_in[wi + 6];
    const float* ln2_b = (const float*)d_in[wi + 7];
    const float* w1    = (const float*)d_in[wi + 8];
    const float* b1    = (const float*)d_in[wi + 9];
    const float* w2    = (const float*)d_in[wi + 10];
    const float* b2    = (const float*)d_in[wi + 11];
    const float* ck    = (const float*)d_in[wi + 12];
    const float* cb    = (const float*)d_in[wi + 13];
    const float* lnf_g = (const float*)d_in[wi + 14];
    const float* lnf_b = (const float*)d_in[wi + 15];
    const float* wp    = (const float*)d_in[wi + 16];
    const float* bp    = (const float*)d_in[wi + 17];

    float* out_x    = (float*)d_out;
    float* out_pred = out_x + (size_t)NT * D;

    static float* px = nullptr;
    static uint16_t *pqh, *pxn16, *pao16, *ph16, *pxfh, *pxfl;
    static uint16_t *pWq16h, *pW1h, *pW1l, *pW2h, *pW2l, *pWoh, *pWol, *pWph, *pWpl;
    if (!px) {
        cudaGetSymbolAddress((void**)&px, g_x);
        cudaGetSymbolAddress((void**)&pqh, g_qkv_h);
        cudaGetSymbolAddress((void**)&pxn16, g_xn16);
        cudaGetSymbolAddress((void**)&pao16, g_ao16);
        cudaGetSymbolAddress((void**)&ph16, g_h16);
        cudaGetSymbolAddress((void**)&pxfh, g_xf_h);  cudaGetSymbolAddress((void**)&pxfl, g_xf_l);
        cudaGetSymbolAddress((void**)&pWq16h, g_wq16h);
        cudaGetSymbolAddress((void**)&pW1h, g_w1_16h);  cudaGetSymbolAddress((void**)&pW1l, g_w1_16l);
        cudaGetSymbolAddress((void**)&pW2h, g_w2_16h);  cudaGetSymbolAddress((void**)&pW2l, g_w2_16l);
        cudaGetSymbolAddress((void**)&pWoh, g_wo16h);   cudaGetSymbolAddress((void**)&pWol, g_wo16l);
        cudaGetSymbolAddress((void**)&pWph, g_wp_h);    cudaGetSymbolAddress((void**)&pWpl, g_wp_l);
        cudaFuncSetAttribute((const void*)gemm_mma<0, 3, 0, 0>, cudaFuncAttributeMaxDynamicSharedMemorySize, GEMM_DYN);
        cudaFuncSetAttribute((const void*)gemm_mma<4, 1, 1, 0>, cudaFuncAttributeMaxDynamicSharedMemorySize, GEMM_DYN);
        cudaFuncSetAttribute((const void*)gemm_mma<5, 2, 1, 1>, cudaFuncAttributeMaxDynamicSharedMemorySize, GEMM_DYN);
        cudaFuncSetAttribute((const void*)gemm_mma<2, 2, 1, 0>, cudaFuncAttributeMaxDynamicSharedMemorySize, GEMM_DYN);
        cudaFuncSetAttribute((const void*)attn_tc, cudaFuncAttributeMaxDynamicSharedMemorySize, ATTN_DYN);
    }

    cudaMemcpyAsync(px, gf, (size_t)NT * D * sizeof(float), cudaMemcpyDeviceToDevice);

    cvt_all<<<(N_CVT + 255) / 256, 256>>>(wqkv, w1, w2, wo, wp);

    for (int i = 0; i < DEPTH; i++) {
        ln_f16<<<NT, 128>>>(px, (__half*)pxn16, ln1_g + i * D, ln1_b + i * D);
        gemm_mma<4, 1, 1, 0><<<dim3(12, 32), 256, GEMM_DYN>>>(
            pxn16, nullptr, pWq16h + (size_t)i * 3 * D * D, nullptr,
            bqkv + i * 3 * D, nullptr, pqh, 3 * D, D);
        attn_tc<<<dim3(NHD, NT / 64), 128, ATTN_DYN>>>();
        gemm_mma<2, 2, 1, 0><<<dim3(4, 32), 256, GEMM_DYN>>>(
            pao16, nullptr, pWoh + (size_t)i * D * D, pWol + (size_t)i * D * D,
            bo + i * D, px, nullptr, D, D);
        ln_f16<<<NT, 128>>>(px, (__half*)pxn16, ln2_g + i * D, ln2_b + i * D);
        gemm_mma<5, 2, 1, 1><<<dim3(16, 32), 256, GEMM_DYN>>>(
            pxn16, nullptr, pW1h + (size_t)i * DMLP * D, pW1l + (size_t)i * DMLP * D,
            b1 + i * DMLP, nullptr, ph16, DMLP, D);
        gemm_mma<2, 2, 1, 0><<<dim3(4, 32), 256, GEMM_DYN>>>(
            ph16, nullptr, pW2h + (size_t)i * D * DMLP, pW2l + (size_t)i * D * DMLP,
            b2 + i * D, px, nullptr, D, DMLP);
        scatter_kernel<<<NT * (D / 4) / 256, 256>>>(coords);
        convgather_kernel<<<NT * D / 256, 256>>>(coords, ck + (size_t)i * D * 9, cb + i * D);
    }
    ln_bf<<<NT, 128>>>(px, out_x, (__nv_bfloat16*)pxfh, (__nv_bfloat16*)pxfl, lnf_g, lnf_b);
    gemm_mma<0, 3, 0, 0><<<dim3(2, 32), 256, GEMM_DYN>>>(
        pxfh, pxfl, pWph, pWpl, bp, out_pred, nullptr, GENES, D);
}

// round 13
// speedup vs baseline: 2.0175x; 1.0399x over previous
#include <cuda_runtime.h>
#include <cuda_bf16.h>
#include <cuda_fp16.h>
#include <math.h>
#include <stdint.h>

#define NT    4096
#define D     512
#define NHD   16
#define DH    32
#define DEPTH 3
#define DMLP  2048
#define GENES 250
#define GH    64
#define GW    64

// ---------------- PTX helpers ----------------
__device__ __forceinline__ uint32_t smem_u32(const void* p) {
    uint32_t a;
    asm("{ .reg .u64 t; cvta.to.shared.u64 t, %1; cvt.u32.u64 %0, t; }" : "=r"(a) : "l"(p));
    return a;
}
#define CP_ASYNC16(sa, ga) \
    asm volatile("cp.async.cg.shared.global [%0], [%1], 16;" :: "r"(sa), "l"(ga))
#define CP_COMMIT() asm volatile("cp.async.commit_group;")
#define CP_WAIT(n)  asm volatile("cp.async.wait_group %0;" :: "n"(n))

#define LDSM4(r0, r1, r2, r3, addr) \
    asm volatile("ldmatrix.sync.aligned.m8n8.x4.shared.b16 {%0,%1,%2,%3}, [%4];" \
        : "=r"(r0), "=r"(r1), "=r"(r2), "=r"(r3) : "r"(addr))
#define LDSM4T(r0, r1, r2, r3, addr) \
    asm volatile("ldmatrix.sync.aligned.m8n8.x4.trans.shared.b16 {%0,%1,%2,%3}, [%4];" \
        : "=r"(r0), "=r"(r1), "=r"(r2), "=r"(r3) : "r"(addr))

template <int F16>
__device__ __forceinline__ void mma_any(float* d, const uint32_t* a, const uint32_t* b) {
    if (F16)
        asm volatile("mma.sync.aligned.m16n8k16.row.col.f32.f16.f16.f32 "
            "{%0,%1,%2,%3}, {%4,%5,%6,%7}, {%8,%9}, {%0,%1,%2,%3};"
            : "+f"(d[0]), "+f"(d[1]), "+f"(d[2]), "+f"(d[3])
            : "r"(a[0]), "r"(a[1]), "r"(a[2]), "r"(a[3]), "r"(b[0]), "r"(b[1]));
    else
        asm volatile("mma.sync.aligned.m16n8k16.row.col.f32.bf16.bf16.f32 "
            "{%0,%1,%2,%3}, {%4,%5,%6,%7}, {%8,%9}, {%0,%1,%2,%3};"
            : "+f"(d[0]), "+f"(d[1]), "+f"(d[2]), "+f"(d[3])
            : "r"(a[0]), "r"(a[1]), "r"(a[2]), "r"(a[3]), "r"(b[0]), "r"(b[1]));
}
__device__ __forceinline__ void mma_bf16(float* d, const uint32_t* a, const uint32_t* b) {
    mma_any<0>(d, a, b);
}

#define PACKBF(d, lo, hi) \
    asm("cvt.rn.bf16x2.f32 %0, %1, %2;" : "=r"(d) : "f"(hi), "f"(lo))
#define PACKF16(d, lo, hi) \
    asm("cvt.rn.f16x2.f32 %0, %1, %2;" : "=r"(d) : "f"(hi), "f"(lo))
#define PRMT(d, a, b, s) \
    asm("prmt.b32 %0, %1, %2, %3;" : "=r"(d) : "r"(a), "r"(b), "n"(s))

__device__ __forceinline__ void hilo(float v, __nv_bfloat16& h, __nv_bfloat16& l) {
    h = __float2bfloat16(v);
    l = __float2bfloat16(v - __bfloat162float(h));
}
__device__ __forceinline__ void hilo16(float v, __half& h, __half& l) {
    h = __float2half_rn(v);
    l = __float2half_rn(v - __half2float(h));
}

// ---------------- device scratch ----------------
__device__ float g_x[NT * D];
__device__ float g_xb[NT * D];
__device__ int   g_idxg[GH * GW];
__device__ __nv_bfloat16 g_qkv_h[NT * 3 * D];
__device__ __half        g_xn16[NT * D];
__device__ __half        g_ao16[NT * D];
__device__ __half        g_h16[NT * DMLP];
__device__ __nv_bfloat16 g_xf_h[NT * D],  g_xf_l[NT * D];
__device__ __half        g_wq16h[DEPTH * 3 * D * D];
__device__ __half        g_w1_16h[DEPTH * DMLP * D], g_w1_16l[DEPTH * DMLP * D];
__device__ __half        g_w2_16h[DEPTH * D * DMLP], g_w2_16l[DEPTH * D * DMLP];
__device__ __half        g_wo16h[DEPTH * D * D],     g_wo16l[DEPTH * D * D];
__device__ __nv_bfloat16 g_wp_h[GENES * D],          g_wp_l[GENES * D];

// ---- one merged weight-conversion kernel ----
#define N_WQKV (DEPTH * 3 * D * D)
#define N_W1   (DEPTH * DMLP * D)
#define N_W2   (DEPTH * D * DMLP)
#define N_WO   (DEPTH * D * D)
#define N_WP   (GENES * D)
#define N_CVT  (N_WQKV + N_W1 + N_W2 + N_WO + N_WP)

__global__ void cvt_all(const float* __restrict__ wqkv, const float* __restrict__ w1,
                        const float* __restrict__ w2, const float* __restrict__ wo,
                        const float* __restrict__ wp) {
    int j = blockIdx.x * blockDim.x + threadIdx.x;
    if (j < N_WQKV) { g_wq16h[j] = __float2half_rn(wqkv[j]); return; }
    j -= N_WQKV;
    if (j < N_W1) {
        __half h, l; hilo16(w1[j], h, l); g_w1_16h[j] = h; g_w1_16l[j] = l; return;
    }
    j -= N_W1;
    if (j < N_W2) {
        __half h, l; hilo16(w2[j], h, l); g_w2_16h[j] = h; g_w2_16l[j] = l; return;
    }
    j -= N_W2;
    if (j < N_WO) {
        __half h, l; hilo16(wo[j], h, l); g_wo16h[j] = h; g_wo16l[j] = l; return;
    }
    j -= N_WO;
    if (j < N_WP) {
        __nv_bfloat16 h, l; hilo(wp[j], h, l); g_wp_h[j] = h; g_wp_l[j] = l;
    }
}

// ---- inverse coords map (coords is a permutation of all GH*GW cells) ----
__global__ void build_idx(const int* __restrict__ coords) {
    int n = blockIdx.x * blockDim.x + threadIdx.x;
    if (n < NT) g_idxg[coords[2 * n] * GW + coords[2 * n + 1]] = n;
}

// ---------------- LayerNorm -> fp16 single ---------------------------------
__global__ void ln_f16(const float* __restrict__ in, __half* __restrict__ oh,
                       const float* __restrict__ gam, const float* __restrict__ bet) {
    int row = blockIdx.x, t = threadIdx.x;
    float4 v = ((const float4*)(in + (size_t)row * D))[t];
    float s = v.x + v.y + v.z + v.w;
    float ss = v.x * v.x + v.y * v.y + v.z * v.z + v.w * v.w;
#pragma unroll
    for (int off = 16; off; off >>= 1) {
        s  += __shfl_xor_sync(0xffffffffu, s, off);
        ss += __shfl_xor_sync(0xffffffffu, ss, off);
    }
    __shared__ float sb[4], ssb[4];
    int w = t >> 5, lane = t & 31;
    if (lane == 0) { sb[w] = s; ssb[w] = ss; }
    __syncthreads();
    s = sb[0] + sb[1] + sb[2] + sb[3];
    ss = ssb[0] + ssb[1] + ssb[2] + ssb[3];
    float mean = s * (1.0f / D);
    float inv = rsqrtf(ss * (1.0f / D) - mean * mean + 1e-5f);
    float4 g4 = ((const float4*)gam)[t];
    float4 b4 = ((const float4*)bet)[t];
    float o0 = (v.x - mean) * inv * g4.x + b4.x;
    float o1 = (v.y - mean) * inv * g4.y + b4.y;
    float o2 = (v.z - mean) * inv * g4.z + b4.z;
    float o3 = (v.w - mean) * inv * g4.w + b4.w;
    uint2 pk;
    PACKF16(pk.x, o0, o1);
    PACKF16(pk.y, o2, o3);
    *(uint2*)(oh + (size_t)row * D + t * 4) = pk;
}

// ---------------- LayerNorm -> bf16 hi/lo + fp32 (final LN) ----------------
__global__ void ln_bf(const float* __restrict__ in, float* __restrict__ out32,
                      __nv_bfloat16* __restrict__ oh, __nv_bfloat16* __restrict__ ol,
                      const float* __restrict__ gam, const float* __restrict__ bet) {
    int row = blockIdx.x, t = threadIdx.x;
    float4 v = ((const float4*)(in + (size_t)row * D))[t];
    float s = v.x + v.y + v.z + v.w;
    float ss = v.x * v.x + v.y * v.y + v.z * v.z + v.w * v.w;
#pragma unroll
    for (int off = 16; off; off >>= 1) {
        s  += __shfl_xor_sync(0xffffffffu, s, off);
        ss += __shfl_xor_sync(0xffffffffu, ss, off);
    }
    __shared__ float sb[4], ssb[4];
    int w = t >> 5, lane = t & 31;
    if (lane == 0) { sb[w] = s; ssb[w] = ss; }
    __syncthreads();
    s = sb[0] + sb[1] + sb[2] + sb[3];
    ss = ssb[0] + ssb[1] + ssb[2] + ssb[3];
    float mean = s * (1.0f / D);
    float inv = rsqrtf(ss * (1.0f / D) - mean * mean + 1e-5f);
    float4 g4 = ((const float4*)gam)[t];
    float4 b4 = ((const float4*)bet)[t];
    float o0 = (v.x - mean) * inv * g4.x + b4.x;
    float o1 = (v.y - mean) * inv * g4.y + b4.y;
    float o2 = (v.z - mean) * inv * g4.z + b4.z;
    float o3 = (v.w - mean) * inv * g4.w + b4.w;
    size_t base = (size_t)row * D + t * 4;
    __nv_bfloat16 h0, l0, h1, l1, h2, l2, h3, l3;
    hilo(o0, h0, l0); hilo(o1, h1, l1); hilo(o2, h2, l2); hilo(o3, h3, l3);
    __nv_bfloat162 p;
    p.x = h0; p.y = h1; *(__nv_bfloat162*)(oh + base) = p;
    p.x = h2; p.y = h3; *(__nv_bfloat162*)(oh + base + 2) = p;
    p.x = l0; p.y = l1; *(__nv_bfloat162*)(ol + base) = p;
    p.x = l2; p.y = l3; *(__nv_bfloat162*)(ol + base + 2) = p;
    float4 o; o.x = o0; o.y = o1; o.z = o2; o.w = o3;
    ((float4*)(out32 + (size_t)row * D))[t] = o;
}

// ---------------- 16-bit hi/lo GEMM via mma.sync ----------------------------
#define TPITCH 80
#define TILE_B (128 * TPITCH)
#define STAGE_B (4 * TILE_B)
#define GEMM_DYN (2 * STAGE_B)

template <int TERMS>
__device__ __forceinline__ void stage_load(
    uint32_t sbase, const uint16_t* Ah, const uint16_t* Al,
    const uint16_t* Wh, const uint16_t* Wl,
    int mrow, int ncol, int OUT, int K, int kt, int tid) {
#pragma unroll
    for (int i = 0; i < 2; i++) {
        int chunk = tid + i * 256;
        int r = chunk >> 2, c16 = chunk & 3;
        uint32_t so = (uint32_t)(r * TPITCH + c16 * 16);
        size_t aoff = (size_t)(mrow + r) * K + kt + c16 * 8;
        int wr = ncol + r; if (wr >= OUT) wr = OUT - 1;
        size_t woff = (size_t)wr * K + kt + c16 * 8;
        CP_ASYNC16(sbase + so,              (const char*)(Ah + aoff));
        if (TERMS == 3)
            CP_ASYNC16(sbase + TILE_B + so, (const char*)(Al + aoff));
        CP_ASYNC16(sbase + 2 * TILE_B + so, (const char*)(Wh + woff));
        if (TERMS >= 2)
            CP_ASYNC16(sbase + 3 * TILE_B + so, (const char*)(Wl + woff));
    }
}

// MODE 0: out32=v+bias ; 2: out32+=v+bias ; 4: out16=pack(v+bias) ;
// 5: out16=pack(gelu(v+bias))
template <int MODE, int TERMS, int F16, int OUTF16>
__global__ void __launch_bounds__(256) gemm_mma(
    const uint16_t* __restrict__ Ah, const uint16_t* __restrict__ Al,
    const uint16_t* __restrict__ Wh, const uint16_t* __restrict__ Wl,
    const float* __restrict__ bias, const float* __restrict__ res32,
    float* __restrict__ out32, uint16_t* __restrict__ out16, int OUT, int K) {
    extern __shared__ char dyn_raw[];
    const int tid = threadIdx.x, wid = tid >> 5, lane = tid & 31;
    const int mrow = blockIdx.y * 128, ncol = blockIdx.x * 128;
    const int warp_m = wid & 1, warp_n = wid >> 1;
    const int m_off = warp_m * 64, n_off = warp_n * 32;
    const int NIT = K >> 5;
    uint32_t smem0 = smem_u32(dyn_raw);

    float acc[4][4][4];
#pragma unroll
    for (int a = 0; a < 4; a++)
#pragma unroll
        for (int b = 0; b < 4; b++)
#pragma unroll
            for (int c = 0; c < 4; c++) acc[a][b][c] = 0.f;

    const uint32_t a_lm = (uint32_t)((m_off + (lane & 15)) * TPITCH + (lane & 16));
    const int bl = lane & 7, bg = (lane >> 3) & 3;
    const uint32_t b_lm = (uint32_t)((n_off + ((bg >> 1) << 3) + bl) * TPITCH + ((bg & 1) << 4));

    stage_load<TERMS>(smem0, Ah, Al, Wh, Wl, mrow, ncol, OUT, K, 0, tid);
    CP_COMMIT();

    for (int it = 0; it < NIT; it++) {
        if (it + 1 < NIT) {
            stage_load<TERMS>(smem0 + ((it + 1) & 1) * STAGE_B, Ah, Al, Wh, Wl,
                              mrow, ncol, OUT, K, (it + 1) * 32, tid);
            CP_COMMIT();
            CP_WAIT(1);
        } else {
            CP_WAIT(0);
        }
        __syncthreads();
        uint32_t sb = smem0 + (it & 1) * STAGE_B;
#pragma unroll
        for (int ks = 0; ks < 2; ks++) {
            uint32_t kb = (uint32_t)(ks * 32);
            uint32_t ah[4][4], al[4][4], bh[4][2], bl2[4][2];
#pragma unroll
            for (int mt = 0; mt < 4; mt++) {
                uint32_t ad = sb + a_lm + mt * (16 * TPITCH) + kb;
                LDSM4(ah[mt][0], ah[mt][1], ah[mt][2], ah[mt][3], ad);
                if (TERMS == 3)
                    LDSM4(al[mt][0], al[mt][1], al[mt][2], al[mt][3], ad + TILE_B);
            }
#pragma unroll
            for (int np = 0; np < 2; np++) {
                uint32_t bd = sb + 2 * TILE_B + b_lm + np * (16 * TPITCH) + kb;
                LDSM4(bh[2 * np][0], bh[2 * np][1], bh[2 * np + 1][0], bh[2 * np + 1][1], bd);
                if (TERMS >= 2)
                    LDSM4(bl2[2 * np][0], bl2[2 * np][1], bl2[2 * np + 1][0], bl2[2 * np + 1][1], bd + TILE_B);
            }
#pragma unroll
            for (int mt = 0; mt < 4; mt++)
#pragma unroll
                for (int nt = 0; nt < 4; nt++) {
                    mma_any<F16>(acc[mt][nt], ah[mt], bh[nt]);
                    if (TERMS >= 2)
                        mma_any<F16>(acc[mt][nt], ah[mt], bl2[nt]);
                    if (TERMS == 3)
                        mma_any<F16>(acc[mt][nt], al[mt], bh[nt]);
                }
        }
        __syncthreads();
    }

    const int r0 = lane >> 2, cp = (lane & 3) * 2;
#pragma unroll
    for (int mt = 0; mt < 4; mt++)
#pragma unroll
        for (int nt = 0; nt < 4; nt++) {
            int col = ncol + n_off + nt * 8 + cp;
            if (col >= OUT) continue;
            float bx = bias[col], by = bias[col + 1];
#pragma unroll
            for (int half = 0; half < 2; half++) {
                int row = mrow + m_off + mt * 16 + r0 + half * 8;
                float vx = acc[mt][nt][2 * half] + bx;
                float vy = acc[mt][nt][2 * half + 1] + by;
                size_t idx = (size_t)row * OUT + col;
                if (MODE == 0) {
                    *(float2*)(out32 + idx) = make_float2(vx, vy);
                } else if (MODE == 4 || MODE == 5) {
                    if (MODE == 5) {
                        vx = 0.5f * vx * (1.0f + erff(vx * 0.70710678118654752f));
                        vy = 0.5f * vy * (1.0f + erff(vy * 0.70710678118654752f));
                    }
                    uint32_t hp;
                    if (OUTF16) PACKF16(hp, vx, vy);
                    else        PACKBF(hp, vx, vy);
                    *(uint32_t*)(out16 + idx) = hp;
                } else {
                    float2 o = *(const float2*)(res32 + idx);
                    o.x += vx; o.y += vy;
                    *(float2*)(out32 + idx) = o;
                }
            }
        }
}

// ---------------- flash attention, bf16, max-free + Schraudolph exp ---------
// exp2(x) via bit trick: y = fma(S, sc2*1024, 12582912) puts round(x*2^10)
// in y's mantissa; p_bits = bits(y)*8192 + C reconstructs 2^x with linear
// mantissa (~2% RMS). All fixed-lat fma/alu work, zero MUFU.
#define AP 80
#define KVT (64 * AP)
#define ASTG (2 * KVT)
#define ATTN_DYN (2 * ASTG)
#define SC_A 261.13688f          // (1/sqrt(32))*log2(e) * 1024
#define MAGICF 12582912.0f
#define EXPC 1064987000u         // (127<<23) - nudge(~0.0437*2^23)

__global__ void __launch_bounds__(128) attn_tc() {
    extern __shared__ __align__(16) char smem[];
    const int tid = threadIdx.x, wid = tid >> 5, lane = tid & 31;
    const int h = blockIdx.x, qb = blockIdx.y * 64;
    const uint32_t s0 = smem_u32(smem);

#pragma unroll
    for (int i = 0; i < 2; i++) {
        int idx = tid + i * 128;
        int r = idx >> 2, c = idx & 3;
        CP_ASYNC16(s0 + r * AP + c * 16,
                   g_qkv_h + (size_t)(qb + r) * 1536 + h * 32 + c * 8);
    }
    CP_COMMIT(); CP_WAIT(0); __syncthreads();
    uint32_t qh[2][4];
    {
        uint32_t alm = s0 + (wid * 16 + (lane & 15)) * AP + (lane & 16);
        LDSM4(qh[0][0], qh[0][1], qh[0][2], qh[0][3], alm);
        LDSM4(qh[1][0], qh[1][1], qh[1][2], qh[1][3], alm + 32);
    }
    __syncthreads();

    const int bl = lane & 7, bg = (lane >> 3) & 3;
    const uint32_t koff = (uint32_t)((((bg >> 1) * 8) + bl) * AP + ((bg & 1) * 16));
    const uint32_t voff = (uint32_t)(((((lane >> 3) & 1) * 8) + (lane & 7)) * AP + (((lane >> 4) & 1) * 16));

    float O[4][4];
#pragma unroll
    for (int a = 0; a < 4; a++)
#pragma unroll
        for (int b = 0; b < 4; b++) O[a][b] = 0.f;
    float lsum0 = 0.f, lsum1 = 0.f;

    {
#pragma unroll
        for (int i = 0; i < 4; i++) {
            int idx = tid + i * 128;
            int tile = idx >> 8, rem = idx & 255, r = rem >> 2, c = rem & 3;
            int col = (tile ? 1024 : 512) + h * 32;
            CP_ASYNC16(s0 + tile * KVT + r * AP + c * 16,
                       g_qkv_h + (size_t)r * 1536 + col + c * 8);
        }
        CP_COMMIT();
    }

    for (int t = 0; t < NT / 64; t++) {
        if (t + 1 < NT / 64) {
            int kb = (t + 1) * 64;
            uint32_t st = s0 + ((t + 1) & 1) * ASTG;
#pragma unroll
            for (int i = 0; i < 4; i++) {
                int idx = tid + i * 128;
                int tile = idx >> 8, rem = idx & 255, r = rem >> 2, c = rem & 3;
                int col = (tile ? 1024 : 512) + h * 32;
                CP_ASYNC16(st + tile * KVT + r * AP + c * 16,
                           g_qkv_h + (size_t)(kb + r) * 1536 + col + c * 8);
            }
            CP_COMMIT(); CP_WAIT(1);
        } else {
            CP_WAIT(0);
        }
        __syncthreads();
        uint32_t sb = s0 + (t & 1) * ASTG;

        float S[8][4];
#pragma unroll
        for (int a = 0; a < 8; a++)
#pragma unroll
            for (int b = 0; b < 4; b++) S[a][b] = 0.f;
#pragma unroll
        for (int ks = 0; ks < 2; ks++) {
            uint32_t kh[8][2];
#pragma unroll
            for (int np = 0; np < 4; np++) {
                uint32_t ad = sb + np * (16 * AP) + koff + ks * 32;
                LDSM4(kh[2 * np][0], kh[2 * np][1], kh[2 * np + 1][0], kh[2 * np + 1][1], ad);
            }
#pragma unroll
            for (int nt = 0; nt < 8; nt++)
                mma_bf16(S[nt], qh[ks], kh[nt]);
        }

        // ---- Schraudolph exp + bf16 pack (no MUFU)
        uint32_t ph01[8], ph23[8];
#pragma unroll
        for (int nt = 0; nt < 8; nt++) {
            uint32_t i0 = __float_as_uint(fmaf(S[nt][0], SC_A, MAGICF)) * 8192u + EXPC;
            uint32_t i1 = __float_as_uint(fmaf(S[nt][1], SC_A, MAGICF)) * 8192u + EXPC;
            uint32_t i2 = __float_as_uint(fmaf(S[nt][2], SC_A, MAGICF)) * 8192u + EXPC;
            uint32_t i3 = __float_as_uint(fmaf(S[nt][3], SC_A, MAGICF)) * 8192u + EXPC;
            lsum0 += __uint_as_float(i0) + __uint_as_float(i1);
            lsum1 += __uint_as_float(i2) + __uint_as_float(i3);
            PRMT(ph01[nt], i0, i1, 0x7632);
            PRMT(ph23[nt], i2, i3, 0x7632);
        }

#pragma unroll
        for (int s = 0; s < 4; s++) {
            uint32_t aH[4] = { ph01[2 * s], ph23[2 * s], ph01[2 * s + 1], ph23[2 * s + 1] };
            uint32_t vh[4][2];
#pragma unroll
            for (int d2 = 0; d2 < 2; d2++) {
                uint32_t ad = sb + KVT + s * (16 * AP) + voff + d2 * 32;
                LDSM4T(vh[2 * d2][0], vh[2 * d2][1], vh[2 * d2 + 1][0], vh[2 * d2 + 1][1], ad);
            }
#pragma unroll
            for (int nt = 0; nt < 4; nt++)
                mma_bf16(O[nt], aH, vh[nt]);
        }
        __syncthreads();
    }

    lsum0 += __shfl_xor_sync(0xffffffffu, lsum0, 1);
    lsum0 += __shfl_xor_sync(0xffffffffu, lsum0, 2);
    lsum1 += __shfl_xor_sync(0xffffffffu, lsum1, 1);
    lsum1 += __shfl_xor_sync(0xffffffffu, lsum1, 2);
    float i0 = 1.f / lsum0, i1 = 1.f / lsum1;
    int r0 = qb + wid * 16 + (lane >> 2), r1 = r0 + 8;
    int colb = h * 32 + (lane & 3) * 2;
#pragma unroll
    for (int nt = 0; nt < 4; nt++) {
        int col = colb + nt * 8;
        uint32_t hp;
        PACKF16(hp, O[nt][0] * i0, O[nt][1] * i0);
        *(uint32_t*)(g_ao16 + (size_t)r0 * D + col) = hp;
        PACKF16(hp, O[nt][2] * i1, O[nt][3] * i1);
        *(uint32_t*)(g_ao16 + (size_t)r1 * D + col) = hp;
    }
}

// ---------------- fused conv+gather via inverse index grid ------------------
// Reads xin (prev buffer) through g_idxg; writes xout = xin + conv + cb.
__global__ void convgather_kernel(const float* __restrict__ xin,
                                  float* __restrict__ xout,
                                  const int* __restrict__ coords,
                                  const float* __restrict__ ck,
                                  const float* __restrict__ cb) {
    int idx = blockIdx.x * blockDim.x + threadIdx.x;
    int n = idx >> 9, d = idx & (D - 1);
    int r = coords[2 * n], c = coords[2 * n + 1];
    float acc = cb[d];
#pragma unroll
    for (int kh = 0; kh < 3; kh++) {
        int rr = r + kh - 1;
        if ((unsigned)rr >= GH) continue;
#pragma unroll
        for (int kw = 0; kw < 3; kw++) {
            int cc = c + kw - 1;
            if ((unsigned)cc >= GW) continue;
            int nn = g_idxg[rr * GW + cc];
            acc += ck[d * 9 + kh * 3 + kw] * xin[(size_t)nn * D + d];
        }
    }
    xout[idx] = xin[idx] + acc;
}

// ---------------- host ----------------
extern "C" void kernel_launch(void* const* d_in, const int* in_sizes, int n_in,
                              void* d_out, int out_size) {
    const float* gf     = (const float*)d_in[0];
    const int*   coords = (const int*)d_in[1];
    int wi = (n_in >= 22) ? 4 : 2;
    const float* ln1_g = (const float*)d_in[wi + 0];
    const float* ln1_b = (const float*)d_in[wi + 1];
    const float* wqkv  = (const float*)d_in[wi + 2];
    const float* bqkv  = (const float*)d_in[wi + 3];
    const float* wo    = (const float*)d_in[wi + 4];
    const float* bo    = (const float*)d_in[wi + 5];
    const float* ln2_g = (const float*)d_in[wi + 6];
    const float* ln2_b = (const float*)d_in[wi + 7];
    const float* w1    = (const float*)d_in[wi + 8];
    const float* b1    = (const float*)d_in[wi + 9];
    const float* w2    = (const float*)d_in[wi + 10];
    const float* b2    = (const float*)d_in[wi + 11];
    const float* ck    = (const float*)d_in[wi + 12];
    const float* cb    = (const float*)d_in[wi + 13];
    const float* lnf_g = (const float*)d_in[wi + 14];
    const float* lnf_b = (const float*)d_in[wi + 15];
    const float* wp    = (const float*)d_in[wi + 16];
    const float* bp    = (const float*)d_in[wi + 17];

    float* out_x    = (float*)d_out;
    float* out_pred = out_x + (size_t)NT * D;

    static float *pxa = nullptr, *pxb;
    static uint16_t *pqh, *pxn16, *pao16, *ph16, *pxfh, *pxfl;
    static uint16_t *pWq16h, *pW1h, *pW1l, *pW2h, *pW2l, *pWoh, *pWol, *pWph, *pWpl;
    if (!pxa) {
        cudaGetSymbolAddress((void**)&pxa, g_x);
        cudaGetSymbolAddress((void**)&pxb, g_xb);
        cudaGetSymbolAddress((void**)&pqh, g_qkv_h);
        cudaGetSymbolAddress((void**)&pxn16, g_xn16);
        cudaGetSymbolAddress((void**)&pao16, g_ao16);
        cudaGetSymbolAddress((void**)&ph16, g_h16);
        cudaGetSymbolAddress((void**)&pxfh, g_xf_h);  cudaGetSymbolAddress((void**)&pxfl, g_xf_l);
        cudaGetSymbolAddress((void**)&pWq16h, g_wq16h);
        cudaGetSymbolAddress((void**)&pW1h, g_w1_16h);  cudaGetSymbolAddress((void**)&pW1l, g_w1_16l);
        cudaGetSymbolAddress((void**)&pW2h, g_w2_16h);  cudaGetSymbolAddress((void**)&pW2l, g_w2_16l);
        cudaGetSymbolAddress((void**)&pWoh, g_wo16h);   cudaGetSymbolAddress((void**)&pWol, g_wo16l);
        cudaGetSymbolAddress((void**)&pWph, g_wp_h);    cudaGetSymbolAddress((void**)&pWpl, g_wp_l);
        cudaFuncSetAttribute((const void*)gemm_mma<0, 3, 0, 0>, cudaFuncAttributeMaxDynamicSharedMemorySize, GEMM_DYN);
        cudaFuncSetAttribute((const void*)gemm_mma<4, 1, 1, 0>, cudaFuncAttributeMaxDynamicSharedMemorySize, GEMM_DYN);
        cudaFuncSetAttribute((const void*)gemm_mma<5, 2, 1, 1>, cudaFuncAttributeMaxDynamicSharedMemorySize, GEMM_DYN);
        cudaFuncSetAttribute((const void*)gemm_mma<2, 2, 1, 0>, cudaFuncAttributeMaxDynamicSharedMemorySize, GEMM_DYN);
        cudaFuncSetAttribute((const void*)attn_tc, cudaFuncAttributeMaxDynamicSharedMemorySize, ATTN_DYN);
    }

    cudaMemcpyAsync(pxa, gf, (size_t)NT * D * sizeof(float), cudaMemcpyDeviceToDevice);

    cvt_all<<<(N_CVT + 255) / 256, 256>>>(wqkv, w1, w2, wo, wp);
    build_idx<<<NT / 256, 256>>>(coords);

    float* cur = pxa;
    float* nxt = pxb;
    for (int i = 0; i < DEPTH; i++) {
        ln_f16<<<NT, 128>>>(cur, (__half*)pxn16, ln1_g + i * D, ln1_b + i * D);
        gemm_mma<4, 1, 1, 0><<<dim3(12, 32), 256, GEMM_DYN>>>(
            pxn16, nullptr, pWq16h + (size_t)i * 3 * D * D, nullptr,
            bqkv + i * 3 * D, nullptr, nullptr, pqh, 3 * D, D);
        attn_tc<<<dim3(NHD, NT / 64), 128, ATTN_DYN>>>();
        gemm_mma<2, 2, 1, 0><<<dim3(4, 32), 256, GEMM_DYN>>>(
            pao16, nullptr, pWoh + (size_t)i * D * D, pWol + (size_t)i * D * D,
            bo + i * D, cur, cur, nullptr, D, D);
        ln_f16<<<NT, 128>>>(cur, (__half*)pxn16, ln2_g + i * D, ln2_b + i * D);
        gemm_mma<5, 2, 1, 1><<<dim3(16, 32), 256, GEMM_DYN>>>(
            pxn16, nullptr, pW1h + (size_t)i * DMLP * D, pW1l + (size_t)i * DMLP * D,
            b1 + i * DMLP, nullptr, nullptr, ph16, DMLP, D);
        gemm_mma<2, 2, 1, 0><<<dim3(4, 32), 256, GEMM_DYN>>>(
            ph16, nullptr, pW2h + (size_t)i * D * DMLP, pW2l + (size_t)i * D * DMLP,
            b2 + i * D, cur, cur, nullptr, D, DMLP);
        convgather_kernel<<<NT * D / 256, 256>>>(cur, nxt, coords,
                                                 ck + (size_t)i * D * 9, cb + i * D);
        float* tmp = cur; cur = nxt; nxt = tmp;
    }
    ln_bf<<<NT, 128>>>(cur, out_x, (__nv_bfloat16*)pxfh, (__nv_bfloat16*)pxfl, lnf_g, lnf_b);
    gemm_mma<0, 3, 0, 0><<<dim3(2, 32), 256, GEMM_DYN>>>(
        pxfh, pxfl, pWph, pWpl, bp, nullptr, out_pred, nullptr, GENES, D);
}